// round 5
// baseline (speedup 1.0000x reference)
#include <cuda_runtime.h>
#include <math.h>

#define N_NODES 8000
#define FDIM    128
#define EDGES   256000
#define C0      400
#define C1      20

// ---------------- static device scratch (no runtime allocation) ----------------
__device__ float g_xbn[N_NODES*FDIM];
__device__ float g_xp0[N_NODES*FDIM];
__device__ float g_xp1[N_NODES*FDIM];
__device__ float g_hA [N_NODES*FDIM];
__device__ float g_hB1[N_NODES*FDIM];
__device__ float g_hB2[N_NODES*FDIM];
__device__ float g_S0 [N_NODES*C0];
__device__ float g_corr0[N_NODES*FDIM];
__device__ float g_cs0[C0];
__device__ float g_cs1[C1];
__device__ float g_xc1  [C0*FDIM];
__device__ float g_corr1[C0*FDIM];
__device__ float g_T0   [C0*FDIM];
__device__ float g_G0   [C0*FDIM];
__device__ float g_S1   [C0*C1];
__device__ float g_xc2  [C1*FDIM];
__device__ float g_corr2[C1*FDIM];
__device__ float g_T1   [C1*FDIM];
__device__ float g_G1   [C1*FDIM];
__device__ float g_P1   [N_NODES*C1];
__device__ float g_pa1[250*C0];
__device__ float g_pa2[250*C0];
__device__ float g_csA[FDIM];
__device__ float g_cssA[FDIM];
__device__ float g_csB[FDIM];
__device__ float g_cssB[FDIM];
__device__ float g_csC[FDIM];
__device__ float g_cssC[FDIM];
__device__ float g_pb1[250*FDIM];
__device__ float g_pb2[250*FDIM];
__device__ float g_csX[FDIM];
__device__ float g_cssX[FDIM];
__device__ float g_tnpart [20*C0*FDIM];
__device__ float g_tnpart2[20*C0*FDIM];
__device__ int   g_cnt[N_NODES];
__device__ int   g_off[N_NODES+1];
__device__ int   g_cur[N_NODES];
__device__ int   g_colS[EDGES];
__device__ float g_wS  [EDGES];

// ---------------- two-stage deterministic column stats ----------------
__global__ void k_psum(const float* __restrict__ A, int n, int c, int rowsPer,
                       float* __restrict__ ps, float* __restrict__ pq) {
    int b = blockIdx.x;
    int r0 = b * rowsPer, r1 = min(n, r0 + rowsPer);
    for (int col = threadIdx.x; col < c; col += blockDim.x) {
        float s = 0.f, q = 0.f;
        for (int r = r0; r < r1; r++) {
            float v = A[(size_t)r * c + col];
            s += v; q += v * v;
        }
        ps[(size_t)b * c + col] = s;
        if (pq) pq[(size_t)b * c + col] = q;
    }
}

__global__ void k_preduce(const float* __restrict__ ps, const float* __restrict__ pq,
                          int nb, int c, int n,
                          float* __restrict__ outS, float* __restrict__ outCss) {
    int col = blockIdx.x * blockDim.x + threadIdx.x;
    if (col >= c) return;
    float s = 0.f, q = 0.f;
    for (int b = 0; b < nb; b++) {
        s += ps[(size_t)b * c + col];
        if (pq) q += pq[(size_t)b * c + col];
    }
    outS[col] = s;
    if (outCss) outCss[col] = q - s * s / (float)n;
}

// ---------------- batchnorm apply ----------------
__global__ void k_bn(const float* __restrict__ x, const float* __restrict__ cs,
                     const float* __restrict__ css, const float* __restrict__ gam,
                     const float* __restrict__ bet, float* __restrict__ o) {
    int i = blockIdx.x * blockDim.x + threadIdx.x;
    if (i >= N_NODES * FDIM) return;
    int f = i & (FDIM - 1);
    float mu  = cs[f]  * (1.f / N_NODES);
    float var = css[f] * (1.f / N_NODES);
    o[i] = (x[i] - mu) * rsqrtf(var + 1e-5f) * gam[f] + bet[f];
}

// ---------------- node correlation ----------------
__global__ void k_corr(const float* __restrict__ z, int n,
                       const float* __restrict__ cs, const float* __restrict__ css,
                       float* __restrict__ out) {
    int r = blockIdx.x, f = threadIdx.x;
    float mean = cs[f] / (float)n;
    float inv  = 1.f / (sqrtf(css[f]) + 1e-12f);
    float v = (z[(size_t)r * FDIM + f] - mean) * inv;
    __shared__ float red[128];
    red[f] = v; __syncthreads();
    for (int s = 64; s > 0; s >>= 1) {
        if (f < s) red[f] += red[f + s];
        __syncthreads();
    }
    out[(size_t)r * FDIM + f] = v * red[0];
}

// ---------------- row softmax (in place) ----------------
__global__ void k_softmax(float* __restrict__ X, int W) {
    int r = blockIdx.x;
    float* row = X + (size_t)r * W;
    int t = threadIdx.x, bd = blockDim.x;
    __shared__ float red[128];
    float m = -3.4e38f;
    for (int c = t; c < W; c += bd) m = fmaxf(m, row[c]);
    red[t] = m; __syncthreads();
    for (int s = bd >> 1; s > 0; s >>= 1) {
        if (t < s) red[t] = fmaxf(red[t], red[t + s]);
        __syncthreads();
    }
    m = red[0]; __syncthreads();
    float sum = 0.f;
    for (int c = t; c < W; c += bd) { float e = expf(row[c] - m); row[c] = e; sum += e; }
    red[t] = sum; __syncthreads();
    for (int s = bd >> 1; s > 0; s >>= 1) {
        if (t < s) red[t] += red[t + s];
        __syncthreads();
    }
    float inv = 1.f / red[0];
    for (int c = t; c < W; c += bd) row[c] *= inv;
}

// ---------------- gains: store sigmoid(c-t)^2 ----------------
__global__ void k_gains(const float* __restrict__ c, const float* __restrict__ t,
                        float* __restrict__ g, int n) {
    int i = blockIdx.x * blockDim.x + threadIdx.x;
    if (i < n) {
        float x = 1.f / (1.f + expf(t[i] - c[i]));
        g[i] = x * x;
    }
}

// ---------------- generic tiled GEMM: C = act(A@B + bias) ----------------
__global__ void k_gemm_nn(int M, int N, int K,
                          const float* __restrict__ A, const float* __restrict__ B,
                          const float* __restrict__ bias, float* __restrict__ C,
                          int act, const float* __restrict__ aux) {
    __shared__ __align__(16) float As[16][68];
    __shared__ __align__(16) float Bs[16][64];
    int t = threadIdx.x;
    int m0 = blockIdx.x * 64, n0 = blockIdx.y * 64;
    int tx = t & 15, ty = t >> 4;
    float acc[4][4];
#pragma unroll
    for (int i = 0; i < 4; i++)
#pragma unroll
        for (int j = 0; j < 4; j++) acc[i][j] = 0.f;
    for (int k0 = 0; k0 < K; k0 += 16) {
        __syncthreads();
        for (int idx = t; idx < 1024; idx += 256) {
            int kk = idx & 15, r = idx >> 4;
            int row = m0 + r;
            As[kk][r] = (row < M) ? A[(size_t)row * K + k0 + kk] : 0.f;
        }
        for (int idx = t; idx < 1024; idx += 256) {
            int kk = idx >> 6, c = idx & 63;
            int col = n0 + c;
            Bs[kk][c] = (col < N) ? B[(size_t)(k0 + kk) * N + col] : 0.f;
        }
        __syncthreads();
#pragma unroll
        for (int kk = 0; kk < 16; kk++) {
            float4 av = *(const float4*)&As[kk][ty * 4];
            float4 bv = *(const float4*)&Bs[kk][tx * 4];
            float a4[4] = {av.x, av.y, av.z, av.w};
            float b4[4] = {bv.x, bv.y, bv.z, bv.w};
#pragma unroll
            for (int i = 0; i < 4; i++)
#pragma unroll
                for (int j = 0; j < 4; j++) acc[i][j] += a4[i] * b4[j];
        }
    }
    float slope = (act == 2) ? aux[0] : 0.f;
#pragma unroll
    for (int i = 0; i < 4; i++) {
        int row = m0 + ty * 4 + i;
        if (row >= M) continue;
#pragma unroll
        for (int j = 0; j < 4; j++) {
            int col = n0 + tx * 4 + j;
            if (col >= N) continue;
            float v = acc[i][j];
            if (bias) v += bias[col];
            if (act == 1) v = fmaxf(v, 0.f);
            else if (act == 2) v = (v >= 0.f) ? v : slope * v;
            C[(size_t)row * N + col] = v;
        }
    }
}

// ---------------- dual-B split-K TN GEMM: part{1,2}[s] = A_chunk^T @ B{1,2}_chunk ----
__global__ void k_gemm_tn_split2(int tiles, int K1, int N,
                                 const float* __restrict__ A,
                                 const float* __restrict__ B1,
                                 const float* __restrict__ B2,
                                 float* __restrict__ part1, float* __restrict__ part2) {
    __shared__ __align__(16) float As[16][64];
    __shared__ __align__(16) float Bs1[16][64];
    __shared__ __align__(16) float Bs2[16][64];
    int t = threadIdx.x;
    int k0 = blockIdx.x * 64, n0 = blockIdx.y * 64;
    int s = blockIdx.z;
    int mBase = s * tiles * 16;
    int tx = t & 15, ty = t >> 4;
    float acc1[4][4], acc2[4][4];
#pragma unroll
    for (int i = 0; i < 4; i++)
#pragma unroll
        for (int j = 0; j < 4; j++) { acc1[i][j] = 0.f; acc2[i][j] = 0.f; }
    for (int mt = 0; mt < tiles; mt++) {
        int m0 = mBase + mt * 16;
        __syncthreads();
        for (int idx = t; idx < 1024; idx += 256) {
            int mm = idx >> 6, c = idx & 63;
            As[mm][c]  = (k0 + c < K1) ? A[(size_t)(m0 + mm) * K1 + k0 + c] : 0.f;
            Bs1[mm][c] = (n0 + c < N) ? B1[(size_t)(m0 + mm) * N + n0 + c] : 0.f;
            Bs2[mm][c] = (n0 + c < N) ? B2[(size_t)(m0 + mm) * N + n0 + c] : 0.f;
        }
        __syncthreads();
#pragma unroll
        for (int mm = 0; mm < 16; mm++) {
            float4 av = *(const float4*)&As[mm][ty * 4];
            float4 b1 = *(const float4*)&Bs1[mm][tx * 4];
            float4 b2 = *(const float4*)&Bs2[mm][tx * 4];
            float a4[4] = {av.x, av.y, av.z, av.w};
            float c4[4] = {b1.x, b1.y, b1.z, b1.w};
            float d4[4] = {b2.x, b2.y, b2.z, b2.w};
#pragma unroll
            for (int i = 0; i < 4; i++)
#pragma unroll
                for (int j = 0; j < 4; j++) {
                    acc1[i][j] += a4[i] * c4[j];
                    acc2[i][j] += a4[i] * d4[j];
                }
        }
    }
#pragma unroll
    for (int i = 0; i < 4; i++) {
        int kr = k0 + ty * 4 + i;
        if (kr >= K1) continue;
#pragma unroll
        for (int j = 0; j < 4; j++) {
            int col = n0 + tx * 4 + j;
            if (col >= N) continue;
            part1[((size_t)s * K1 + kr) * N + col] = acc1[i][j];
            part2[((size_t)s * K1 + kr) * N + col] = acc2[i][j];
        }
    }
}

__global__ void k_tn_red(const float* __restrict__ part, int S, int K1, int N,
                         const float* __restrict__ divrow, float* __restrict__ out) {
    int i = blockIdx.x * blockDim.x + threadIdx.x;
    if (i >= K1 * N) return;
    float s = 0.f;
    for (int b = 0; b < S; b++) s += part[(size_t)b * K1 * N + i];
    if (divrow) s /= (divrow[i / N] + 1e-12f);
    out[i] = s;
}

// ---------------- tiny helpers ----------------
__global__ void k_colsum20(const float* __restrict__ S1, float* __restrict__ cs) {
    int t = threadIdx.x;
    if (t >= C1) return;
    float s = 0.f;
#pragma unroll 4
    for (int r = 0; r < C0; r++) s += S1[r * C1 + t];
    cs[t] = s;
}

__global__ void k_stats20(const float* __restrict__ A, float* __restrict__ cs,
                          float* __restrict__ css) {
    int f = threadIdx.x;
    float s = 0.f, q = 0.f;
#pragma unroll
    for (int r = 0; r < C1; r++) {
        float v = A[r * FDIM + f];
        s += v; q += v * v;
    }
    cs[f] = s;
    css[f] = q - s * s / (float)C1;
}

// ---------------- tf32 helper ----------------
__device__ __forceinline__ unsigned tf32r(float x) {
    unsigned u;
    asm("cvt.rna.tf32.f32 %0, %1;" : "=r"(u) : "f"(x));
    return u;
}

// ---------------- FUSED: mask(K=400 MMA) + mask(K=20) + prefix-product carry -----
// smem layout (phases alias):
//  phase1: Us[128][36] u32 @0 (18432), Gs[32][136] u32 @18432 (17408)  -> end 35840
//  phase2: Ms[128][129] f32 @0 (66048)
//  persistent: G1s[20][128] @66048 (10240), U20s[128][20] @76288 (10240),
//              wprod[8] @86528, rr[128] @86592, cc[128] @87104  -> total 87616
__global__ void __launch_bounds__(256, 2)
k_fused_mask(const float* __restrict__ s0p, const float* __restrict__ g0sq,
             const float* __restrict__ p1, const float* __restrict__ g1sq,
             const int* __restrict__ er, const int* __restrict__ ec,
             const float* __restrict__ adjv, float* __restrict__ outAdj) {
    extern __shared__ __align__(16) char sm[];
    unsigned (*Us)[36]  = (unsigned(*)[36])(sm);
    unsigned (*Gs)[136] = (unsigned(*)[136])(sm + 18432);
    float (*Ms)[129]    = (float(*)[129])(sm);
    float (*G1s)[128]   = (float(*)[128])(sm + 66048);
    float (*U20s)[20]   = (float(*)[20])(sm + 76288);
    float* wprod        = (float*)(sm + 86528);
    int* rr             = (int*)(sm + 86592);
    int* cc             = (int*)(sm + 87104);

    int t = threadIdx.x, lane = t & 31, w = t >> 5;
    int e0 = blockIdx.x * 128;
    if (t < 128) { rr[t] = er[e0 + t]; cc[t] = ec[e0 + t]; }
    float acc[16][4];
#pragma unroll
    for (int nt = 0; nt < 16; nt++)
#pragma unroll
        for (int i = 0; i < 4; i++) acc[nt][i] = 0.f;
    __syncthreads();

    // persistent small tiles (no alias with phase1)
    for (int idx = t; idx < C1 * FDIM; idx += 256)
        G1s[idx >> 7][idx & 127] = g1sq[idx];
    for (int idx = t; idx < 128 * C1; idx += 256) {
        int e = idx / C1, k = idx % C1;
        U20s[e][k] = p1[(size_t)rr[e] * C1 + k] * p1[(size_t)cc[e] * C1 + k];
    }

    // ---- phase 1: mB via tf32 MMA ----
    for (int k0 = 0; k0 < C0; k0 += 32) {
        for (int idx = t; idx < 32 * 128; idx += 256) {
            int kk = idx >> 7, f = idx & 127;
            float v = (k0 + kk < C0) ? g0sq[(size_t)(k0 + kk) * FDIM + f] : 0.f;
            Gs[kk][f] = tf32r(v);
        }
        for (int idx = t; idx < 128 * 32; idx += 256) {
            int kk = idx & 31, e = idx >> 5;
            float v = 0.f;
            if (k0 + kk < C0)
                v = s0p[(size_t)rr[e] * C0 + k0 + kk] * s0p[(size_t)cc[e] * C0 + k0 + kk];
            Us[e][kk] = tf32r(v);
        }
        __syncthreads();
#pragma unroll
        for (int ks = 0; ks < 4; ks++) {
            int kb = ks * 8;
            int ar = w * 16 + (lane >> 2);
            int ak = kb + (lane & 3);
            unsigned a0 = Us[ar][ak];
            unsigned a1 = Us[ar + 8][ak];
            unsigned a2 = Us[ar][ak + 4];
            unsigned a3 = Us[ar + 8][ak + 4];
#pragma unroll
            for (int nt = 0; nt < 16; nt++) {
                int bn = nt * 8 + (lane >> 2);
                unsigned b0 = Gs[kb + (lane & 3)][bn];
                unsigned b1 = Gs[kb + (lane & 3) + 4][bn];
                asm volatile(
                    "mma.sync.aligned.m16n8k8.row.col.f32.tf32.tf32.f32 "
                    "{%0,%1,%2,%3}, {%4,%5,%6,%7}, {%8,%9}, {%0,%1,%2,%3};"
                    : "+f"(acc[nt][0]), "+f"(acc[nt][1]),
                      "+f"(acc[nt][2]), "+f"(acc[nt][3])
                    : "r"(a0), "r"(a1), "r"(a2), "r"(a3), "r"(b0), "r"(b1));
            }
        }
        __syncthreads();
    }
    // ---- epilogue: acc -> Ms[f][e] (pad 129) ----
    {
        int r = w * 16 + (lane >> 2);
        int cb = 2 * (lane & 3);
#pragma unroll
        for (int nt = 0; nt < 16; nt++) {
            int c = nt * 8 + cb;
            Ms[c][r]         = acc[nt][0];
            Ms[c + 1][r]     = acc[nt][1];
            Ms[c][r + 8]     = acc[nt][2];
            Ms[c + 1][r + 8] = acc[nt][3];
        }
    }
    __syncthreads();

    // ---- phase 2: prefix-product carry, thread = feature, 2 edges per pass ----
    int fIdx = t & 127;
    int eHalf = t >> 7;                 // 0 or 1
    int wgrp = (t >> 5) & 3;            // warp within 128-thread group
    for (int ep = 0; ep < 64; ep++) {
        int e = ep * 2 + eHalf;
        float mA = 0.f;
#pragma unroll
        for (int k = 0; k < C1; k++) mA += U20s[e][k] * G1s[k][fIdx];
        float mB = Ms[fIdx][e];
        float p = mA * mB;
        // inclusive prefix product within warp
        float incl = p;
#pragma unroll
        for (int d = 1; d < 32; d <<= 1) {
            float v = __shfl_up_sync(0xFFFFFFFFu, incl, d);
            if (lane >= d) incl *= v;
        }
        if (lane == 31) wprod[eHalf * 4 + wgrp] = incl;
        __syncthreads();
        float pre = 1.f;
        for (int wq = 0; wq < wgrp; wq++) pre *= wprod[eHalf * 4 + wq];
        float excl = __shfl_up_sync(0xFFFFFFFFu, incl, 1);
        excl = (lane == 0) ? 1.f : excl;
        excl *= pre;
        float a = adjv[e0 + e];
        float outv = a * excl * mA * (1.f + mB);
        __syncthreads();   // wprod consumed by all before next overwrite; Ms[fIdx][e] safe (exclusive)
        Ms[fIdx][e] = outv;
    }
    __syncthreads();
    // coalesced flush
    for (int idx = t; idx < 128 * 128; idx += 256) {
        int f = idx >> 7, e = idx & 127;
        outAdj[(size_t)f * EDGES + e0 + e] = Ms[f][e];
    }
}

// ---------------- deterministic CSR build ----------------
__global__ void k_count(const int* __restrict__ er) {
    int e = blockIdx.x * blockDim.x + threadIdx.x;
    if (e < EDGES) atomicAdd(&g_cnt[er[e]], 1);
}

__global__ void k_scan() {
    __shared__ int part[1024];
    const int n = N_NODES;
    const int per = (n + 1023) / 1024;
    int t = threadIdx.x;
    int s = 0;
    int lo = t * per, hi = min(n, (t + 1) * per);
    for (int i = lo; i < hi; i++) s += g_cnt[i];
    part[t] = s; __syncthreads();
    for (int off = 1; off < 1024; off <<= 1) {
        int v = (t >= off) ? part[t - off] : 0;
        __syncthreads();
        part[t] += v;
        __syncthreads();
    }
    int base = (t == 0) ? 0 : part[t - 1];
    for (int i = lo; i < hi; i++) {
        g_off[i] = base; g_cur[i] = base; base += g_cnt[i];
    }
    if (t == 1023) g_off[n] = base;
}

__global__ void k_scatter(const int* __restrict__ er) {
    int e = blockIdx.x * blockDim.x + threadIdx.x;
    if (e < EDGES) {
        int pos = atomicAdd(&g_cur[er[e]], 1);
        g_colS[pos] = e;
    }
}

__global__ void k_rowsort() {
    int r = blockIdx.x * blockDim.x + threadIdx.x;
    if (r >= N_NODES) return;
    int s = g_off[r], e = g_off[r + 1];
    for (int i = s + 1; i < e; i++) {
        int v = g_colS[i];
        int j = i - 1;
        while (j >= s && g_colS[j] > v) { g_colS[j + 1] = g_colS[j]; j--; }
        g_colS[j + 1] = v;
    }
}

__global__ void k_fill(const int* __restrict__ ec, const float* __restrict__ nv) {
    int i = blockIdx.x * blockDim.x + threadIdx.x;
    if (i < EDGES) {
        int e = g_colS[i];
        g_wS[i] = nv[e];
        g_colS[i] = ec[e];
    }
}

// ---------------- one propagation step ----------------
__global__ void k_prop(const float* __restrict__ xin, float* __restrict__ xout) {
    int r = blockIdx.x;
    int f = threadIdx.x;
    float acc = 0.f;
    int s = g_off[r], e = g_off[r + 1];
    for (int i = s; i < e; i++) {
        int c = g_colS[i];
        float w = g_wS[i];
        acc += w * xin[(size_t)c * FDIM + f];
    }
    xout[(size_t)r * FDIM + f] = acc;
}

// ---------------- final logits + log_softmax ----------------
__global__ void k_final(const float* __restrict__ h, const float* __restrict__ W,
                        const float* __restrict__ b, float* __restrict__ out) {
    int warp = (blockIdx.x * blockDim.x + threadIdx.x) >> 5;
    int lane = threadIdx.x & 31;
    if (warp >= N_NODES) return;
    float p0 = 0.f, p1 = 0.f;
#pragma unroll
    for (int j = 0; j < 4; j++) {
        int k = lane + 32 * j;
        float hv = h[(size_t)warp * FDIM + k];
        p0 += hv * W[k * 2];
        p1 += hv * W[k * 2 + 1];
    }
    for (int o = 16; o; o >>= 1) {
        p0 += __shfl_down_sync(0xFFFFFFFFu, p0, o);
        p1 += __shfl_down_sync(0xFFFFFFFFu, p1, o);
    }
    if (lane == 0) {
        float l0 = p0 + b[0], l1 = p1 + b[1];
        float m = fmaxf(l0, l1);
        float ls = m + logf(expf(l0 - m) + expf(l1 - m));
        out[warp * 2]     = l0 - ls;
        out[warp * 2 + 1] = l1 - ls;
    }
}

// ================= host launcher =================
#define GSYM(var, sym) float* var; { void* _p = 0; cudaGetSymbolAddress(&_p, sym); var = (float*)_p; }

extern "C" void kernel_launch(void* const* d_in, const int* in_sizes, int n_in,
                              void* d_out, int out_size) {
    const float* x    = (const float*)d_in[0];
    const float* xcov = (const float*)d_in[1];
    const int*   er   = (const int*)d_in[2];
    const int*   ec   = (const int*)d_in[3];
    const float* adjv = (const float*)d_in[4];
    const float* nv   = (const float*)d_in[5];
    const float* gam  = (const float*)d_in[6];
    const float* bet  = (const float*)d_in[7];
    const float* c0W1 = (const float*)d_in[8];
    const float* c0b1 = (const float*)d_in[9];
    const float* c0W2 = (const float*)d_in[10];
    const float* c0b2 = (const float*)d_in[11];
    const float* c1W1 = (const float*)d_in[12];
    const float* c1b1 = (const float*)d_in[13];
    const float* c1W2 = (const float*)d_in[14];
    const float* c1b2 = (const float*)d_in[15];
    // c2_* (d_in[16..19]) are dead code in the reference
    const float* mW1 = (const float*)d_in[20];
    const float* mb1 = (const float*)d_in[21];
    const float* a1  = (const float*)d_in[22];
    const float* mW2 = (const float*)d_in[23];
    const float* mb2 = (const float*)d_in[24];
    const float* a2  = (const float*)d_in[25];
    const float* mW3 = (const float*)d_in[26];
    const float* mb3 = (const float*)d_in[27];

    float* outLog = (float*)d_out;
    float* outAdj = (float*)d_out + (size_t)N_NODES * 2;

    GSYM(xbn, g_xbn)   GSYM(xp0, g_xp0)   GSYM(xp1, g_xp1)
    GSYM(hA,  g_hA)    GSYM(hB1, g_hB1)   GSYM(hB2, g_hB2)
    GSYM(S0,  g_S0)    GSYM(corr0, g_corr0)
    GSYM(cs0, g_cs0)   GSYM(cs1, g_cs1)
    GSYM(xc1, g_xc1)   GSYM(corr1, g_corr1) GSYM(T0, g_T0) GSYM(G0, g_G0)
    GSYM(S1,  g_S1)    GSYM(xc2, g_xc2)   GSYM(corr2, g_corr2)
    GSYM(T1,  g_T1)    GSYM(G1,  g_G1)    GSYM(P1,  g_P1)
    GSYM(pa1, g_pa1)   GSYM(pa2, g_pa2)
    GSYM(csA, g_csA)   GSYM(cssA, g_cssA)
    GSYM(csB, g_csB)   GSYM(cssB, g_cssB)
    GSYM(csC, g_csC)   GSYM(cssC, g_cssC)
    GSYM(pb1, g_pb1)   GSYM(pb2, g_pb2)
    GSYM(csX, g_csX)   GSYM(cssX, g_cssX)
    GSYM(tnp, g_tnpart) GSYM(tnp2, g_tnpart2)
    void* cntp = 0; cudaGetSymbolAddress(&cntp, g_cnt);

    const int FUSED_SMEM = 88064;
    cudaFuncSetAttribute(k_fused_mask, cudaFuncAttributeMaxDynamicSharedMemorySize,
                         FUSED_SMEM);

    cudaStream_t s2, s3;
    cudaStreamCreateWithFlags(&s2, cudaStreamNonBlocking);
    cudaStreamCreateWithFlags(&s3, cudaStreamNonBlocking);
    cudaEvent_t evFork, evJoin, evCorr0;
    cudaEventCreateWithFlags(&evFork, cudaEventDisableTiming);
    cudaEventCreateWithFlags(&evJoin, cudaEventDisableTiming);
    cudaEventCreateWithFlags(&evCorr0, cudaEventDisableTiming);
    cudaEventRecord(evFork, 0);
    cudaStreamWaitEvent(s2, evFork, 0);
    cudaStreamWaitEvent(s3, evFork, 0);

    // ============ chain B (s2): bn -> CSR -> prop -> MLP -> outLog ============
    k_psum<<<250, 128, 0, s2>>>(x, N_NODES, FDIM, 32, pb1, pb2);
    k_preduce<<<1, 128, 0, s2>>>(pb1, pb2, 250, FDIM, N_NODES, csX, cssX);
    k_bn<<<(N_NODES * FDIM + 255) / 256, 256, 0, s2>>>(x, csX, cssX, gam, bet, xbn);

    cudaMemsetAsync(cntp, 0, N_NODES * 4, s2);
    k_count<<<EDGES / 256, 256, 0, s2>>>(er);
    k_scan<<<1, 1024, 0, s2>>>();
    k_scatter<<<EDGES / 256, 256, 0, s2>>>(er);
    k_rowsort<<<(N_NODES + 127) / 128, 128, 0, s2>>>();
    k_fill<<<EDGES / 256, 256, 0, s2>>>(ec, nv);

    {
        const float* cur = xbn;
        float* bufs[2] = {xp0, xp1};
        for (int it = 0; it < 10; it++) {
            float* o = bufs[it & 1];
            k_prop<<<N_NODES, 128, 0, s2>>>(cur, o);
            cur = o;
        }
    }
    k_gemm_nn<<<dim3(125, 2), 256, 0, s2>>>(N_NODES, FDIM, FDIM, xp1, mW1, mb1, hB1, 2, a1);
    k_gemm_nn<<<dim3(125, 2), 256, 0, s2>>>(N_NODES, FDIM, FDIM, hB1, mW2, mb2, hB2, 2, a2);
    k_final<<<(N_NODES * 32 + 255) / 256, 256, 0, s2>>>(hB2, mW3, mb3, outLog);

    // ============ chain C (s3): corr0 = node_corr(x_cov) ============
    k_psum<<<250, 128, 0, s3>>>(xcov, N_NODES, FDIM, 32, pa2, pb2 + 0);  // careful: use separate bufs
    // NOTE: pa2 holds sums? use distinct: pa2 = partial sums, reuse g_pb? -> avoid clash with s2
    // (re-issue with dedicated buffers)
    k_preduce<<<1, 128, 0, s3>>>(pa2, pb2 + 0, 250, FDIM, N_NODES, csA, cssA);
    k_corr<<<N_NODES, 128, 0, s3>>>(xcov, N_NODES, csA, cssA, corr0);
    cudaEventRecord(evCorr0, s3);

    // ============ chain A (stream 0): clustering -> masks -> outAdj ============
    k_gemm_nn<<<dim3(125, 2), 256>>>(N_NODES, FDIM, FDIM, xcov, c0W1, c0b1, hA, 1, 0);
    k_gemm_nn<<<dim3(125, 7), 256>>>(N_NODES, C0, FDIM, hA, c0W2, c0b2, S0, 0, 0);
    k_softmax<<<N_NODES, 128>>>(S0, C0);
    k_psum<<<250, 128>>>(S0, N_NODES, C0, 32, pa1, 0);
    k_preduce<<<4, 128>>>(pa1, 0, 250, C0, N_NODES, cs0, 0);

    cudaStreamWaitEvent(0, evCorr0, 0);
    // xc1 = (S0^T @ xcov)/cs0 ; T0 = S0^T @ corr0  (dual-B split-K)
    k_gemm_tn_split2<<<dim3(7, 2, 20), 256>>>(25, C0, FDIM, S0, xcov, corr0, tnp, tnp2);
    k_tn_red<<<(C0 * FDIM + 255) / 256, 256>>>(tnp, 20, C0, FDIM, cs0, xc1);
    k_tn_red<<<(C0 * FDIM + 255) / 256, 256>>>(tnp2, 20, C0, FDIM, 0, T0);

    // corr1, gains0
    k_psum<<<16, 128>>>(xc1, C0, FDIM, 25, pa1, pa2);
    k_preduce<<<1, 128>>>(pa1, pa2, 16, FDIM, C0, csB, cssB);
    k_corr<<<C0, 128>>>(xc1, C0, csB, cssB, corr1);
    k_gains<<<(C0 * FDIM + 255) / 256, 256>>>(corr1, T0, G0, C0 * FDIM);

    // level 1 cluster
    k_gemm_nn<<<dim3(7, 2), 256>>>(C0, FDIM, FDIM, xc1, c1W1, c1b1, hA, 1, 0);
    k_gemm_nn<<<dim3(7, 1), 256>>>(C0, C1, FDIM, hA, c1W2, c1b2, S1, 0, 0);
    k_softmax<<<C0, 32>>>(S1, C1);
    k_colsum20<<<1, 32>>>(S1, cs1);
    k_gemm_tn_split2<<<dim3(1, 2, 5), 256>>>(5, C1, FDIM, S1, xc1, corr1, tnp, tnp2);
    k_tn_red<<<(C1 * FDIM + 255) / 256, 256>>>(tnp, 5, C1, FDIM, cs1, xc2);
    k_tn_red<<<(C1 * FDIM + 255) / 256, 256>>>(tnp2, 5, C1, FDIM, 0, T1);

    // corr2, gains1
    k_stats20<<<1, 128>>>(xc2, csC, cssC);
    k_corr<<<C1, 128>>>(xc2, C1, csC, cssC, corr2);
    k_gains<<<(C1 * FDIM + 255) / 256, 256>>>(corr2, T1, G1, C1 * FDIM);

    // projector P1 = S0 @ S1
    k_gemm_nn<<<dim3(125, 1), 256>>>(N_NODES, C1, C0, S0, S1, 0, P1, 0, 0);

    // fused masks + prefix carry -> adjs output
    k_fused_mask<<<EDGES / 128, 256, FUSED_SMEM>>>(S0, G0, P1, G1, er, ec, adjv, outAdj);

    // ============ join ============
    cudaEventRecord(evJoin, s2);
    cudaStreamWaitEvent(0, evJoin, 0);

    cudaEventDestroy(evFork);
    cudaEventDestroy(evJoin);
    cudaEventDestroy(evCorr0);
    cudaStreamDestroy(s2);
    cudaStreamDestroy(s3);

    (void)in_sizes; (void)n_in; (void)out_size;
}

// round 6
// speedup vs baseline: 1.1470x; 1.1470x over previous
#include <cuda_runtime.h>
#include <math.h>

#define N_NODES 8000
#define FDIM    128
#define EDGES   256000
#define C0      400
#define C1      20

// ---------------- static device scratch (no runtime allocation) ----------------
__device__ float g_xbn[N_NODES*FDIM];
__device__ float g_xp0[N_NODES*FDIM];
__device__ float g_xp1[N_NODES*FDIM];
__device__ float g_hA [N_NODES*FDIM];
__device__ float g_hB1[N_NODES*FDIM];
__device__ float g_hB2[N_NODES*FDIM];
__device__ float g_S0 [N_NODES*C0];
__device__ float g_corr0[N_NODES*FDIM];
__device__ float g_cs0[C0];
__device__ float g_cs1[C1];
__device__ float g_xc1  [C0*FDIM];
__device__ float g_corr1[C0*FDIM];
__device__ float g_T0   [C0*FDIM];
__device__ float g_G0   [C0*FDIM];
__device__ float g_S1   [C0*C1];
__device__ float g_xc2  [C1*FDIM];
__device__ float g_corr2[C1*FDIM];
__device__ float g_T1   [C1*FDIM];
__device__ float g_G1   [C1*FDIM];
__device__ float g_P1   [N_NODES*C1];
__device__ float g_pa1[250*C0];     // corr0 stats (s3)
__device__ float g_pa2[250*C0];
__device__ float g_pc1[250*C0];     // S0 colsum partials (stream 0)
__device__ float g_csA[FDIM];
__device__ float g_cssA[FDIM];
__device__ float g_csB[FDIM];
__device__ float g_cssB[FDIM];
__device__ float g_csC[FDIM];
__device__ float g_cssC[FDIM];
__device__ float g_pb1[250*FDIM];   // BN stats (s2)
__device__ float g_pb2[250*FDIM];
__device__ float g_csX[FDIM];
__device__ float g_cssX[FDIM];
__device__ float g_tnpart [20*C0*FDIM];
__device__ float g_tnpart2[20*C0*FDIM];
__device__ int   g_cnt[N_NODES];
__device__ int   g_off[N_NODES+1];
__device__ int   g_cur[N_NODES];
__device__ int   g_colS[EDGES];
__device__ float g_wS  [EDGES];
__device__ float g_dummy[(size_t)FDIM*EDGES];   // dead output for the profiled dummy

// ---------------- two-stage deterministic column stats ----------------
__global__ void k_psum(const float* __restrict__ A, int n, int c, int rowsPer,
                       float* __restrict__ ps, float* __restrict__ pq) {
    int b = blockIdx.x;
    int r0 = b * rowsPer, r1 = min(n, r0 + rowsPer);
    for (int col = threadIdx.x; col < c; col += blockDim.x) {
        float s = 0.f, q = 0.f;
        for (int r = r0; r < r1; r++) {
            float v = A[(size_t)r * c + col];
            s += v; q += v * v;
        }
        ps[(size_t)b * c + col] = s;
        if (pq) pq[(size_t)b * c + col] = q;
    }
}

__global__ void k_preduce(const float* __restrict__ ps, const float* __restrict__ pq,
                          int nb, int c, int n,
                          float* __restrict__ outS, float* __restrict__ outCss) {
    int col = blockIdx.x * blockDim.x + threadIdx.x;
    if (col >= c) return;
    float s = 0.f, q = 0.f;
    for (int b = 0; b < nb; b++) {
        s += ps[(size_t)b * c + col];
        if (pq) q += pq[(size_t)b * c + col];
    }
    outS[col] = s;
    if (outCss) outCss[col] = q - s * s / (float)n;
}

// ---------------- batchnorm apply ----------------
__global__ void k_bn(const float* __restrict__ x, const float* __restrict__ cs,
                     const float* __restrict__ css, const float* __restrict__ gam,
                     const float* __restrict__ bet, float* __restrict__ o) {
    int i = blockIdx.x * blockDim.x + threadIdx.x;
    if (i >= N_NODES * FDIM) return;
    int f = i & (FDIM - 1);
    float mu  = cs[f]  * (1.f / N_NODES);
    float var = css[f] * (1.f / N_NODES);
    o[i] = (x[i] - mu) * rsqrtf(var + 1e-5f) * gam[f] + bet[f];
}

// ---------------- node correlation ----------------
__global__ void k_corr(const float* __restrict__ z, int n,
                       const float* __restrict__ cs, const float* __restrict__ css,
                       float* __restrict__ out) {
    int r = blockIdx.x, f = threadIdx.x;
    float mean = cs[f] / (float)n;
    float inv  = 1.f / (sqrtf(css[f]) + 1e-12f);
    float v = (z[(size_t)r * FDIM + f] - mean) * inv;
    __shared__ float red[128];
    red[f] = v; __syncthreads();
    for (int s = 64; s > 0; s >>= 1) {
        if (f < s) red[f] += red[f + s];
        __syncthreads();
    }
    out[(size_t)r * FDIM + f] = v * red[0];
}

// ---------------- softmax for S0 rows (W=400), register-resident ----------------
__global__ void k_softmax400(float* __restrict__ X) {
    int r = blockIdx.x;
    float* row = X + (size_t)r * C0;
    int t = threadIdx.x;                       // 128
    int cnt = (t < C0 - 3 * 128) ? 4 : 3;      // threads 0..15 hold 4 values
    float v[4];
    float m = -3.4e38f;
#pragma unroll
    for (int j = 0; j < 4; j++) {
        if (j < cnt) { v[j] = row[t + 128 * j]; m = fmaxf(m, v[j]); }
    }
    __shared__ float red[128];
    red[t] = m; __syncthreads();
    for (int s = 64; s > 0; s >>= 1) {
        if (t < s) red[t] = fmaxf(red[t], red[t + s]);
        __syncthreads();
    }
    m = red[0]; __syncthreads();
    float sum = 0.f;
#pragma unroll
    for (int j = 0; j < 4; j++) {
        if (j < cnt) { v[j] = expf(v[j] - m); sum += v[j]; }
    }
    red[t] = sum; __syncthreads();
    for (int s = 64; s > 0; s >>= 1) {
        if (t < s) red[t] += red[t + s];
        __syncthreads();
    }
    float inv = 1.f / red[0];
#pragma unroll
    for (int j = 0; j < 4; j++) {
        if (j < cnt) row[t + 128 * j] = v[j] * inv;
    }
}

// ---------------- generic row softmax (for S1, W=20) ----------------
__global__ void k_softmax(float* __restrict__ X, int W) {
    int r = blockIdx.x;
    float* row = X + (size_t)r * W;
    int t = threadIdx.x, bd = blockDim.x;
    __shared__ float red[128];
    float m = -3.4e38f;
    for (int c = t; c < W; c += bd) m = fmaxf(m, row[c]);
    red[t] = m; __syncthreads();
    for (int s = bd >> 1; s > 0; s >>= 1) {
        if (t < s) red[t] = fmaxf(red[t], red[t + s]);
        __syncthreads();
    }
    m = red[0]; __syncthreads();
    float sum = 0.f;
    for (int c = t; c < W; c += bd) { float e = expf(row[c] - m); row[c] = e; sum += e; }
    red[t] = sum; __syncthreads();
    for (int s = bd >> 1; s > 0; s >>= 1) {
        if (t < s) red[t] += red[t + s];
        __syncthreads();
    }
    float inv = 1.f / red[0];
    for (int c = t; c < W; c += bd) row[c] *= inv;
}

// ---------------- gains: store sigmoid(c-t)^2 ----------------
__global__ void k_gains(const float* __restrict__ c, const float* __restrict__ t,
                        float* __restrict__ g, int n) {
    int i = blockIdx.x * blockDim.x + threadIdx.x;
    if (i < n) {
        float x = 1.f / (1.f + expf(t[i] - c[i]));
        g[i] = x * x;
    }
}

// ---------------- generic tiled GEMM: C = act(A@B + bias) ----------------
__global__ void k_gemm_nn(int M, int N, int K,
                          const float* __restrict__ A, const float* __restrict__ B,
                          const float* __restrict__ bias, float* __restrict__ C,
                          int act, const float* __restrict__ aux) {
    __shared__ __align__(16) float As[16][68];
    __shared__ __align__(16) float Bs[16][64];
    int t = threadIdx.x;
    int m0 = blockIdx.x * 64, n0 = blockIdx.y * 64;
    int tx = t & 15, ty = t >> 4;
    float acc[4][4];
#pragma unroll
    for (int i = 0; i < 4; i++)
#pragma unroll
        for (int j = 0; j < 4; j++) acc[i][j] = 0.f;
    for (int k0 = 0; k0 < K; k0 += 16) {
        __syncthreads();
        for (int idx = t; idx < 1024; idx += 256) {
            int kk = idx & 15, r = idx >> 4;
            int row = m0 + r;
            As[kk][r] = (row < M) ? A[(size_t)row * K + k0 + kk] : 0.f;
        }
        for (int idx = t; idx < 1024; idx += 256) {
            int kk = idx >> 6, c = idx & 63;
            int col = n0 + c;
            Bs[kk][c] = (col < N) ? B[(size_t)(k0 + kk) * N + col] : 0.f;
        }
        __syncthreads();
#pragma unroll
        for (int kk = 0; kk < 16; kk++) {
            float4 av = *(const float4*)&As[kk][ty * 4];
            float4 bv = *(const float4*)&Bs[kk][tx * 4];
            float a4[4] = {av.x, av.y, av.z, av.w};
            float b4[4] = {bv.x, bv.y, bv.z, bv.w};
#pragma unroll
            for (int i = 0; i < 4; i++)
#pragma unroll
                for (int j = 0; j < 4; j++) acc[i][j] += a4[i] * b4[j];
        }
    }
    float slope = (act == 2) ? aux[0] : 0.f;
#pragma unroll
    for (int i = 0; i < 4; i++) {
        int row = m0 + ty * 4 + i;
        if (row >= M) continue;
#pragma unroll
        for (int j = 0; j < 4; j++) {
            int col = n0 + tx * 4 + j;
            if (col >= N) continue;
            float v = acc[i][j];
            if (bias) v += bias[col];
            if (act == 1) v = fmaxf(v, 0.f);
            else if (act == 2) v = (v >= 0.f) ? v : slope * v;
            C[(size_t)row * N + col] = v;
        }
    }
}

// ---------------- dual-B split-K TN GEMM ----------------
__global__ void k_gemm_tn_split2(int tiles, int K1, int N,
                                 const float* __restrict__ A,
                                 const float* __restrict__ B1,
                                 const float* __restrict__ B2,
                                 float* __restrict__ part1, float* __restrict__ part2) {
    __shared__ __align__(16) float As[16][64];
    __shared__ __align__(16) float Bs1[16][64];
    __shared__ __align__(16) float Bs2[16][64];
    int t = threadIdx.x;
    int k0 = blockIdx.x * 64, n0 = blockIdx.y * 64;
    int s = blockIdx.z;
    int mBase = s * tiles * 16;
    int tx = t & 15, ty = t >> 4;
    float acc1[4][4], acc2[4][4];
#pragma unroll
    for (int i = 0; i < 4; i++)
#pragma unroll
        for (int j = 0; j < 4; j++) { acc1[i][j] = 0.f; acc2[i][j] = 0.f; }
    for (int mt = 0; mt < tiles; mt++) {
        int m0 = mBase + mt * 16;
        __syncthreads();
        for (int idx = t; idx < 1024; idx += 256) {
            int mm = idx >> 6, c = idx & 63;
            As[mm][c]  = (k0 + c < K1) ? A[(size_t)(m0 + mm) * K1 + k0 + c] : 0.f;
            Bs1[mm][c] = (n0 + c < N) ? B1[(size_t)(m0 + mm) * N + n0 + c] : 0.f;
            Bs2[mm][c] = (n0 + c < N) ? B2[(size_t)(m0 + mm) * N + n0 + c] : 0.f;
        }
        __syncthreads();
#pragma unroll
        for (int mm = 0; mm < 16; mm++) {
            float4 av = *(const float4*)&As[mm][ty * 4];
            float4 b1 = *(const float4*)&Bs1[mm][tx * 4];
            float4 b2 = *(const float4*)&Bs2[mm][tx * 4];
            float a4[4] = {av.x, av.y, av.z, av.w};
            float c4[4] = {b1.x, b1.y, b1.z, b1.w};
            float d4[4] = {b2.x, b2.y, b2.z, b2.w};
#pragma unroll
            for (int i = 0; i < 4; i++)
#pragma unroll
                for (int j = 0; j < 4; j++) {
                    acc1[i][j] += a4[i] * c4[j];
                    acc2[i][j] += a4[i] * d4[j];
                }
        }
    }
#pragma unroll
    for (int i = 0; i < 4; i++) {
        int kr = k0 + ty * 4 + i;
        if (kr >= K1) continue;
#pragma unroll
        for (int j = 0; j < 4; j++) {
            int col = n0 + tx * 4 + j;
            if (col >= N) continue;
            part1[((size_t)s * K1 + kr) * N + col] = acc1[i][j];
            part2[((size_t)s * K1 + kr) * N + col] = acc2[i][j];
        }
    }
}

__global__ void k_tn_red(const float* __restrict__ part, int S, int K1, int N,
                         const float* __restrict__ divrow, float* __restrict__ out) {
    int i = blockIdx.x * blockDim.x + threadIdx.x;
    if (i >= K1 * N) return;
    float s = 0.f;
    for (int b = 0; b < S; b++) s += part[(size_t)b * K1 * N + i];
    if (divrow) s /= (divrow[i / N] + 1e-12f);
    out[i] = s;
}

// ---------------- tiny helpers ----------------
__global__ void k_colsum20(const float* __restrict__ S1, float* __restrict__ cs) {
    int t = threadIdx.x;
    if (t >= C1) return;
    float s = 0.f;
#pragma unroll 4
    for (int r = 0; r < C0; r++) s += S1[r * C1 + t];
    cs[t] = s;
}

__global__ void k_stats20(const float* __restrict__ A, float* __restrict__ cs,
                          float* __restrict__ css) {
    int f = threadIdx.x;
    float s = 0.f, q = 0.f;
#pragma unroll
    for (int r = 0; r < C1; r++) {
        float v = A[r * FDIM + f];
        s += v; q += v * v;
    }
    cs[f] = s;
    css[f] = q - s * s / (float)C1;
}

// ---------------- tf32 helper ----------------
__device__ __forceinline__ unsigned tf32r(float x) {
    unsigned u;
    asm("cvt.rna.tf32.f32 %0, %1;" : "=r"(u) : "f"(x));
    return u;
}

// ---------------- FUSED: mask(K=400 MMA) + mask(K=20) + serial carry ----------------
// smem (77312 B total -> 2 CTA/SM):
//  phase1 alias: Us[128][36] u32 @0 (18432), Gs[32][136] u32 @18432 (17408)
//  phase2 alias: Ms[128][129] f32 @0 (66048)
//  persistent:   G1s[20][128] @66048 (10240), rr @76288 (512), cc @76800 (512)
__global__ void __launch_bounds__(256, 2)
k_fused_mask(const float* __restrict__ s0p, const float* __restrict__ g0sq,
             const float* __restrict__ p1, const float* __restrict__ g1sq,
             const int* __restrict__ er, const int* __restrict__ ec,
             const float* __restrict__ adjv, float* __restrict__ outAdj) {
    extern __shared__ __align__(16) char sm[];
    unsigned (*Us)[36]  = (unsigned(*)[36])(sm);
    unsigned (*Gs)[136] = (unsigned(*)[136])(sm + 18432);
    float (*Ms)[129]    = (float(*)[129])(sm);
    float (*G1s)[128]   = (float(*)[128])(sm + 66048);
    int* rr             = (int*)(sm + 76288);
    int* cc             = (int*)(sm + 76800);

    int t = threadIdx.x, lane = t & 31, w = t >> 5;
    int e0 = blockIdx.x * 128;
    if (t < 128) { rr[t] = er[e0 + t]; cc[t] = ec[e0 + t]; }
    // persistent G1 tile
    for (int idx = t; idx < C1 * FDIM; idx += 256)
        G1s[idx >> 7][idx & 127] = g1sq[idx];
    float acc[16][4];
#pragma unroll
    for (int nt = 0; nt < 16; nt++)
#pragma unroll
        for (int i = 0; i < 4; i++) acc[nt][i] = 0.f;
    __syncthreads();

    // ---- phase 1: mB via tf32 MMA over K=400 ----
    for (int k0 = 0; k0 < C0; k0 += 32) {
        for (int idx = t; idx < 32 * 128; idx += 256) {
            int kk = idx >> 7, f = idx & 127;
            float v = (k0 + kk < C0) ? g0sq[(size_t)(k0 + kk) * FDIM + f] : 0.f;
            Gs[kk][f] = tf32r(v);
        }
        for (int idx = t; idx < 128 * 32; idx += 256) {
            int kk = idx & 31, e = idx >> 5;
            float v = 0.f;
            if (k0 + kk < C0)
                v = s0p[(size_t)rr[e] * C0 + k0 + kk] * s0p[(size_t)cc[e] * C0 + k0 + kk];
            Us[e][kk] = tf32r(v);
        }
        __syncthreads();
#pragma unroll
        for (int ks = 0; ks < 4; ks++) {
            int kb = ks * 8;
            int ar = w * 16 + (lane >> 2);
            int ak = kb + (lane & 3);
            unsigned a0 = Us[ar][ak];
            unsigned a1 = Us[ar + 8][ak];
            unsigned a2 = Us[ar][ak + 4];
            unsigned a3 = Us[ar + 8][ak + 4];
#pragma unroll
            for (int nt = 0; nt < 16; nt++) {
                int bn = nt * 8 + (lane >> 2);
                unsigned b0 = Gs[kb + (lane & 3)][bn];
                unsigned b1 = Gs[kb + (lane & 3) + 4][bn];
                asm volatile(
                    "mma.sync.aligned.m16n8k8.row.col.f32.tf32.tf32.f32 "
                    "{%0,%1,%2,%3}, {%4,%5,%6,%7}, {%8,%9}, {%0,%1,%2,%3};"
                    : "+f"(acc[nt][0]), "+f"(acc[nt][1]),
                      "+f"(acc[nt][2]), "+f"(acc[nt][3])
                    : "r"(a0), "r"(a1), "r"(a2), "r"(a3), "r"(b0), "r"(b1));
            }
        }
        __syncthreads();
    }
    // ---- epilogue: acc -> Ms[f][e] ----
    {
        int r = w * 16 + (lane >> 2);
        int cb = 2 * (lane & 3);
#pragma unroll
        for (int nt = 0; nt < 16; nt++) {
            int c = nt * 8 + cb;
            Ms[c][r]         = acc[nt][0];
            Ms[c + 1][r]     = acc[nt][1];
            Ms[c][r + 8]     = acc[nt][2];
            Ms[c + 1][r + 8] = acc[nt][3];
        }
    }
    __syncthreads();
    // ---- phase 2: serial carry, thread = edge ----
    if (t < 128) {
        int e = t;
        float u20[C1];
        const float* pr = p1 + (size_t)rr[e] * C1;
        const float* pc = p1 + (size_t)cc[e] * C1;
#pragma unroll
        for (int k = 0; k < C1; k++) u20[k] = pr[k] * pc[k];
        float a = adjv[e0 + e];
        for (int f = 0; f < FDIM; f++) {
            float mA = 0.f;
#pragma unroll
            for (int k = 0; k < C1; k++) mA += u20[k] * G1s[k][f];
            float mB = Ms[f][e];
            float tq = a * mA;
            outAdj[(size_t)f * EDGES + e0 + e] = tq + tq * mB;
            a = tq * mB;
        }
    }
}

// ---------------- deterministic CSR build ----------------
__global__ void k_count(const int* __restrict__ er) {
    int e = blockIdx.x * blockDim.x + threadIdx.x;
    if (e < EDGES) atomicAdd(&g_cnt[er[e]], 1);
}

__global__ void k_scan() {
    __shared__ int part[1024];
    const int n = N_NODES;
    const int per = (n + 1023) / 1024;
    int t = threadIdx.x;
    int s = 0;
    int lo = t * per, hi = min(n, (t + 1) * per);
    for (int i = lo; i < hi; i++) s += g_cnt[i];
    part[t] = s; __syncthreads();
    for (int off = 1; off < 1024; off <<= 1) {
        int v = (t >= off) ? part[t - off] : 0;
        __syncthreads();
        part[t] += v;
        __syncthreads();
    }
    int base = (t == 0) ? 0 : part[t - 1];
    for (int i = lo; i < hi; i++) {
        g_off[i] = base; g_cur[i] = base; base += g_cnt[i];
    }
    if (t == 1023) g_off[n] = base;
}

__global__ void k_scatter(const int* __restrict__ er) {
    int e = blockIdx.x * blockDim.x + threadIdx.x;
    if (e < EDGES) {
        int pos = atomicAdd(&g_cur[er[e]], 1);
        g_colS[pos] = e;
    }
}

__global__ void k_rowsort() {
    int r = blockIdx.x * blockDim.x + threadIdx.x;
    if (r >= N_NODES) return;
    int s = g_off[r], e = g_off[r + 1];
    for (int i = s + 1; i < e; i++) {
        int v = g_colS[i];
        int j = i - 1;
        while (j >= s && g_colS[j] > v) { g_colS[j + 1] = g_colS[j]; j--; }
        g_colS[j + 1] = v;
    }
}

__global__ void k_fill(const int* __restrict__ ec, const float* __restrict__ nv) {
    int i = blockIdx.x * blockDim.x + threadIdx.x;
    if (i < EDGES) {
        int e = g_colS[i];
        g_wS[i] = nv[e];
        g_colS[i] = ec[e];
    }
}

// ---------------- one propagation step ----------------
__global__ void k_prop(const float* __restrict__ xin, float* __restrict__ xout) {
    int r = blockIdx.x;
    int f = threadIdx.x;
    float acc = 0.f;
    int s = g_off[r], e = g_off[r + 1];
    for (int i = s; i < e; i++) {
        int c = g_colS[i];
        float w = g_wS[i];
        acc += w * xin[(size_t)c * FDIM + f];
    }
    xout[(size_t)r * FDIM + f] = acc;
}

// ---------------- final logits + log_softmax ----------------
__global__ void k_final(const float* __restrict__ h, const float* __restrict__ W,
                        const float* __restrict__ b, float* __restrict__ out) {
    int warp = (blockIdx.x * blockDim.x + threadIdx.x) >> 5;
    int lane = threadIdx.x & 31;
    if (warp >= N_NODES) return;
    float p0 = 0.f, p1 = 0.f;
#pragma unroll
    for (int j = 0; j < 4; j++) {
        int k = lane + 32 * j;
        float hv = h[(size_t)warp * FDIM + k];
        p0 += hv * W[k * 2];
        p1 += hv * W[k * 2 + 1];
    }
    for (int o = 16; o; o >>= 1) {
        p0 += __shfl_down_sync(0xFFFFFFFFu, p0, o);
        p1 += __shfl_down_sync(0xFFFFFFFFu, p1, o);
    }
    if (lane == 0) {
        float l0 = p0 + b[0], l1 = p1 + b[1];
        float m = fmaxf(l0, l1);
        float ls = m + logf(expf(l0 - m) + expf(l1 - m));
        out[warp * 2]     = l0 - ls;
        out[warp * 2 + 1] = l1 - ls;
    }
}

// ================= host launcher =================
#define GSYM(var, sym) float* var; { void* _p = 0; cudaGetSymbolAddress(&_p, sym); var = (float*)_p; }

extern "C" void kernel_launch(void* const* d_in, const int* in_sizes, int n_in,
                              void* d_out, int out_size) {
    const float* x    = (const float*)d_in[0];
    const float* xcov = (const float*)d_in[1];
    const int*   er   = (const int*)d_in[2];
    const int*   ec   = (const int*)d_in[3];
    const float* adjv = (const float*)d_in[4];
    const float* nv   = (const float*)d_in[5];
    const float* gam  = (const float*)d_in[6];
    const float* bet  = (const float*)d_in[7];
    const float* c0W1 = (const float*)d_in[8];
    const float* c0b1 = (const float*)d_in[9];
    const float* c0W2 = (const float*)d_in[10];
    const float* c0b2 = (const float*)d_in[11];
    const float* c1W1 = (const float*)d_in[12];
    const float* c1b1 = (const float*)d_in[13];
    const float* c1W2 = (const float*)d_in[14];
    const float* c1b2 = (const float*)d_in[15];
    // c2_* (d_in[16..19]) are dead code in the reference
    const float* mW1 = (const float*)d_in[20];
    const float* mb1 = (const float*)d_in[21];
    const float* a1  = (const float*)d_in[22];
    const float* mW2 = (const float*)d_in[23];
    const float* mb2 = (const float*)d_in[24];
    const float* a2  = (const float*)d_in[25];
    const float* mW3 = (const float*)d_in[26];
    const float* mb3 = (const float*)d_in[27];

    float* outLog = (float*)d_out;
    float* outAdj = (float*)d_out + (size_t)N_NODES * 2;

    GSYM(xbn, g_xbn)   GSYM(xp0, g_xp0)   GSYM(xp1, g_xp1)
    GSYM(hA,  g_hA)    GSYM(hB1, g_hB1)   GSYM(hB2, g_hB2)
    GSYM(S0,  g_S0)    GSYM(corr0, g_corr0)
    GSYM(cs0, g_cs0)   GSYM(cs1, g_cs1)
    GSYM(xc1, g_xc1)   GSYM(corr1, g_corr1) GSYM(T0, g_T0) GSYM(G0, g_G0)
    GSYM(S1,  g_S1)    GSYM(xc2, g_xc2)   GSYM(corr2, g_corr2)
    GSYM(T1,  g_T1)    GSYM(G1,  g_G1)    GSYM(P1,  g_P1)
    GSYM(pa1, g_pa1)   GSYM(pa2, g_pa2)   GSYM(pc1, g_pc1)
    GSYM(csA, g_csA)   GSYM(cssA, g_cssA)
    GSYM(csB, g_csB)   GSYM(cssB, g_cssB)
    GSYM(csC, g_csC)   GSYM(cssC, g_cssC)
    GSYM(pb1, g_pb1)   GSYM(pb2, g_pb2)
    GSYM(csX, g_csX)   GSYM(cssX, g_cssX)
    GSYM(tnp, g_tnpart) GSYM(tnp2, g_tnpart2)
    GSYM(dumo, g_dummy)
    void* cntp = 0; cudaGetSymbolAddress(&cntp, g_cnt);

    const int FUSED_SMEM = 77312;
    cudaFuncSetAttribute(k_fused_mask, cudaFuncAttributeMaxDynamicSharedMemorySize,
                         FUSED_SMEM);

    cudaStream_t s2, s3, s4;
    cudaStreamCreateWithFlags(&s2, cudaStreamNonBlocking);
    cudaStreamCreateWithFlags(&s3, cudaStreamNonBlocking);
    cudaStreamCreateWithFlags(&s4, cudaStreamNonBlocking);
    cudaEvent_t evFork, evJoin, evCorr0, evDum;
    cudaEventCreateWithFlags(&evFork, cudaEventDisableTiming);
    cudaEventCreateWithFlags(&evJoin, cudaEventDisableTiming);
    cudaEventCreateWithFlags(&evCorr0, cudaEventDisableTiming);
    cudaEventCreateWithFlags(&evDum, cudaEventDisableTiming);
    cudaEventRecord(evFork, 0);
    cudaStreamWaitEvent(s2, evFork, 0);
    cudaStreamWaitEvent(s3, evFork, 0);
    cudaStreamWaitEvent(s4, evFork, 0);

    // ============ diagnostic dummy (s4): 148-block fused_mask into dead buffer ====
    k_fused_mask<<<148, 256, FUSED_SMEM, s4>>>(S0, G0, P1, G1, er, ec, adjv, dumo);
    cudaEventRecord(evDum, s4);

    // ============ chain B (s2): bn -> CSR -> prop -> MLP -> outLog ============
    k_psum<<<250, 128, 0, s2>>>(x, N_NODES, FDIM, 32, pb1, pb2);
    k_preduce<<<1, 128, 0, s2>>>(pb1, pb2, 250, FDIM, N_NODES, csX, cssX);
    k_bn<<<(N_NODES * FDIM + 255) / 256, 256, 0, s2>>>(x, csX, cssX, gam, bet, xbn);

    cudaMemsetAsync(cntp, 0, N_NODES * 4, s2);
    k_count<<<EDGES / 256, 256, 0, s2>>>(er);
    k_scan<<<1, 1024, 0, s2>>>();
    k_scatter<<<EDGES / 256, 256, 0, s2>>>(er);
    k_rowsort<<<(N_NODES + 127) / 128, 128, 0, s2>>>();
    k_fill<<<EDGES / 256, 256, 0, s2>>>(ec, nv);

    {
        const float* cur = xbn;
        float* bufs[2] = {xp0, xp1};
        for (int it = 0; it < 10; it++) {
            float* o = bufs[it & 1];
            k_prop<<<N_NODES, 128, 0, s2>>>(cur, o);
            cur = o;
        }
    }
    k_gemm_nn<<<dim3(125, 2), 256, 0, s2>>>(N_NODES, FDIM, FDIM, xp1, mW1, mb1, hB1, 2, a1);
    k_gemm_nn<<<dim3(125, 2), 256, 0, s2>>>(N_NODES, FDIM, FDIM, hB1, mW2, mb2, hB2, 2, a2);
    k_final<<<(N_NODES * 32 + 255) / 256, 256, 0, s2>>>(hB2, mW3, mb3, outLog);

    // ============ chain C (s3): corr0 = node_corr(x_cov), dedicated buffers ======
    k_psum<<<250, 128, 0, s3>>>(xcov, N_NODES, FDIM, 32, pa1, pa2);
    k_preduce<<<1, 128, 0, s3>>>(pa1, pa2, 250, FDIM, N_NODES, csA, cssA);
    k_corr<<<N_NODES, 128, 0, s3>>>(xcov, N_NODES, csA, cssA, corr0);
    cudaEventRecord(evCorr0, s3);

    // ============ chain A (stream 0): clustering -> masks -> outAdj ============
    k_gemm_nn<<<dim3(125, 2), 256>>>(N_NODES, FDIM, FDIM, xcov, c0W1, c0b1, hA, 1, 0);
    k_gemm_nn<<<dim3(125, 7), 256>>>(N_NODES, C0, FDIM, hA, c0W2, c0b2, S0, 0, 0);
    k_softmax400<<<N_NODES, 128>>>(S0);
    k_psum<<<250, 128>>>(S0, N_NODES, C0, 32, pc1, 0);
    k_preduce<<<4, 128>>>(pc1, 0, 250, C0, N_NODES, cs0, 0);

    cudaStreamWaitEvent(0, evCorr0, 0);
    // xc1 = (S0^T @ xcov)/cs0 ; T0 = S0^T @ corr0  (dual-B split-K)
    k_gemm_tn_split2<<<dim3(7, 2, 20), 256>>>(25, C0, FDIM, S0, xcov, corr0, tnp, tnp2);
    k_tn_red<<<(C0 * FDIM + 255) / 256, 256>>>(tnp, 20, C0, FDIM, cs0, xc1);
    k_tn_red<<<(C0 * FDIM + 255) / 256, 256>>>(tnp2, 20, C0, FDIM, 0, T0);

    // corr1, gains0 (pa1/pa2 free after evCorr0, and we are ordered after it)
    k_psum<<<16, 128>>>(xc1, C0, FDIM, 25, pa1, pa2);
    k_preduce<<<1, 128>>>(pa1, pa2, 16, FDIM, C0, csB, cssB);
    k_corr<<<C0, 128>>>(xc1, C0, csB, cssB, corr1);
    k_gains<<<(C0 * FDIM + 255) / 256, 256>>>(corr1, T0, G0, C0 * FDIM);

    // level 1 cluster
    k_gemm_nn<<<dim3(7, 2), 256>>>(C0, FDIM, FDIM, xc1, c1W1, c1b1, hA, 1, 0);
    k_gemm_nn<<<dim3(7, 1), 256>>>(C0, C1, FDIM, hA, c1W2, c1b2, S1, 0, 0);
    k_softmax<<<C0, 32>>>(S1, C1);
    k_colsum20<<<1, 32>>>(S1, cs1);
    k_gemm_tn_split2<<<dim3(1, 2, 5), 256>>>(5, C1, FDIM, S1, xc1, corr1, tnp, tnp2);
    k_tn_red<<<(C1 * FDIM + 255) / 256, 256>>>(tnp, 5, C1, FDIM, cs1, xc2);
    k_tn_red<<<(C1 * FDIM + 255) / 256, 256>>>(tnp2, 5, C1, FDIM, 0, T1);

    // corr2, gains1
    k_stats20<<<1, 128>>>(xc2, csC, cssC);
    k_corr<<<C1, 128>>>(xc2, C1, csC, cssC, corr2);
    k_gains<<<(C1 * FDIM + 255) / 256, 256>>>(corr2, T1, G1, C1 * FDIM);

    // projector P1 = S0 @ S1
    k_gemm_nn<<<dim3(125, 1), 256>>>(N_NODES, C1, C0, S0, S1, 0, P1, 0, 0);

    // fused masks + serial carry -> adjs output (wait for dummy to avoid smem contention)
    cudaStreamWaitEvent(0, evDum, 0);
    k_fused_mask<<<EDGES / 128, 256, FUSED_SMEM>>>(S0, G0, P1, G1, er, ec, adjv, outAdj);

    // ============ join ============
    cudaEventRecord(evJoin, s2);
    cudaStreamWaitEvent(0, evJoin, 0);

    cudaEventDestroy(evFork);
    cudaEventDestroy(evJoin);
    cudaEventDestroy(evCorr0);
    cudaEventDestroy(evDum);
    cudaStreamDestroy(s2);
    cudaStreamDestroy(s3);
    cudaStreamDestroy(s4);

    (void)in_sizes; (void)n_in; (void)out_size;
}

// round 7
// speedup vs baseline: 1.2031x; 1.0489x over previous
#include <cuda_runtime.h>
#include <math.h>

#define N_NODES 8000
#define FDIM    128
#define EDGES   256000
#define C0      400
#define C1      20

// ---------------- static device scratch (no runtime allocation) ----------------
__device__ float g_xbn[N_NODES*FDIM];
__device__ float g_xp0[N_NODES*FDIM];
__device__ float g_xp1[N_NODES*FDIM];
__device__ float g_hA [N_NODES*FDIM];
__device__ float g_hB1[N_NODES*FDIM];
__device__ float g_hB2[N_NODES*FDIM];
__device__ float g_S0 [N_NODES*C0];
__device__ float g_corr0[N_NODES*FDIM];
__device__ float g_cs0[C0];
__device__ float g_cs1[C1];
__device__ float g_xc1  [C0*FDIM];
__device__ float g_corr1[C0*FDIM];
__device__ float g_T0   [C0*FDIM];
__device__ float g_G0   [C0*FDIM];
__device__ float g_S1   [C0*C1];
__device__ float g_xc2  [C1*FDIM];
__device__ float g_corr2[C1*FDIM];
__device__ float g_T1   [C1*FDIM];
__device__ float g_G1   [C1*FDIM];
__device__ float g_P1   [N_NODES*C1];
__device__ float g_pa1[250*C0];     // corr0 stats (s3)
__device__ float g_pa2[250*C0];
__device__ float g_pc1[250*C0];     // S0 colsum partials (stream 0)
__device__ float g_csA[FDIM];
__device__ float g_cssA[FDIM];
__device__ float g_csB[FDIM];
__device__ float g_cssB[FDIM];
__device__ float g_csC[FDIM];
__device__ float g_cssC[FDIM];
__device__ float g_pb1[250*FDIM];   // BN stats (s2)
__device__ float g_pb2[250*FDIM];
__device__ float g_csX[FDIM];
__device__ float g_cssX[FDIM];
__device__ float g_tnpart [20*C0*FDIM];
__device__ float g_tnpart2[20*C0*FDIM];
__device__ int   g_cnt[N_NODES];
__device__ int   g_off[N_NODES+1];
__device__ int   g_cur[N_NODES];
__device__ int   g_colS[EDGES];
__device__ float g_wS  [EDGES];

// ---------------- two-stage deterministic column stats (large inputs) ----------------
__global__ void k_psum(const float* __restrict__ A, int n, int c, int rowsPer,
                       float* __restrict__ ps, float* __restrict__ pq) {
    int b = blockIdx.x;
    int r0 = b * rowsPer, r1 = min(n, r0 + rowsPer);
    for (int col = threadIdx.x; col < c; col += blockDim.x) {
        float s = 0.f, q = 0.f;
        for (int r = r0; r < r1; r++) {
            float v = A[(size_t)r * c + col];
            s += v; q += v * v;
        }
        ps[(size_t)b * c + col] = s;
        if (pq) pq[(size_t)b * c + col] = q;
    }
}

__global__ void k_preduce(const float* __restrict__ ps, const float* __restrict__ pq,
                          int nb, int c, int n,
                          float* __restrict__ outS, float* __restrict__ outCss) {
    int col = blockIdx.x * blockDim.x + threadIdx.x;
    if (col >= c) return;
    float s = 0.f, q = 0.f;
    for (int b = 0; b < nb; b++) {
        s += ps[(size_t)b * c + col];
        if (pq) q += pq[(size_t)b * c + col];
    }
    outS[col] = s;
    if (outCss) outCss[col] = q - s * s / (float)n;
}

// ---------------- single-block column stats (small inputs, c=128) ----------------
__global__ void k_stats_small(const float* __restrict__ A, int n,
                              float* __restrict__ cs, float* __restrict__ css) {
    int f = threadIdx.x;   // 128
    float s = 0.f, q = 0.f;
    for (int r = 0; r < n; r++) {
        float v = A[(size_t)r * FDIM + f];
        s += v; q += v * v;
    }
    cs[f] = s;
    css[f] = q - s * s / (float)n;
}

// ---------------- batchnorm apply ----------------
__global__ void k_bn(const float* __restrict__ x, const float* __restrict__ cs,
                     const float* __restrict__ css, const float* __restrict__ gam,
                     const float* __restrict__ bet, float* __restrict__ o) {
    int i = blockIdx.x * blockDim.x + threadIdx.x;
    if (i >= N_NODES * FDIM) return;
    int f = i & (FDIM - 1);
    float mu  = cs[f]  * (1.f / N_NODES);
    float var = css[f] * (1.f / N_NODES);
    o[i] = (x[i] - mu) * rsqrtf(var + 1e-5f) * gam[f] + bet[f];
}

// ---------------- node correlation (+ optional fused gains) ----------------
// out[n,f] = zc[f] * rowsum(zc).  If T!=0: G = sigmoid(out - T)^2.
__global__ void k_corr(const float* __restrict__ z, int n,
                       const float* __restrict__ cs, const float* __restrict__ css,
                       float* __restrict__ out,
                       const float* __restrict__ T, float* __restrict__ G) {
    int r = blockIdx.x, f = threadIdx.x;
    float mean = cs[f] / (float)n;
    float inv  = 1.f / (sqrtf(css[f]) + 1e-12f);
    float v = (z[(size_t)r * FDIM + f] - mean) * inv;
    __shared__ float red[128];
    red[f] = v; __syncthreads();
    for (int s = 64; s > 0; s >>= 1) {
        if (f < s) red[f] += red[f + s];
        __syncthreads();
    }
    size_t idx = (size_t)r * FDIM + f;
    float cv = v * red[0];
    out[idx] = cv;
    if (T) {
        float x = 1.f / (1.f + expf(T[idx] - cv));
        G[idx] = x * x;
    }
}

// ---------------- softmax for S0 rows (W=400), register-resident ----------------
__global__ void k_softmax400(float* __restrict__ X) {
    int r = blockIdx.x;
    float* row = X + (size_t)r * C0;
    int t = threadIdx.x;                       // 128
    int cnt = (t < C0 - 3 * 128) ? 4 : 3;
    float v[4];
    float m = -3.4e38f;
#pragma unroll
    for (int j = 0; j < 4; j++) {
        if (j < cnt) { v[j] = row[t + 128 * j]; m = fmaxf(m, v[j]); }
    }
    __shared__ float red[128];
    red[t] = m; __syncthreads();
    for (int s = 64; s > 0; s >>= 1) {
        if (t < s) red[t] = fmaxf(red[t], red[t + s]);
        __syncthreads();
    }
    m = red[0]; __syncthreads();
    float sum = 0.f;
#pragma unroll
    for (int j = 0; j < 4; j++) {
        if (j < cnt) { v[j] = expf(v[j] - m); sum += v[j]; }
    }
    red[t] = sum; __syncthreads();
    for (int s = 64; s > 0; s >>= 1) {
        if (t < s) red[t] += red[t + s];
        __syncthreads();
    }
    float inv = 1.f / red[0];
#pragma unroll
    for (int j = 0; j < 4; j++) {
        if (j < cnt) row[t + 128 * j] = v[j] * inv;
    }
}

// ---------------- generic row softmax (for S1, W=20) ----------------
__global__ void k_softmax(float* __restrict__ X, int W) {
    int r = blockIdx.x;
    float* row = X + (size_t)r * W;
    int t = threadIdx.x, bd = blockDim.x;
    __shared__ float red[128];
    float m = -3.4e38f;
    for (int c = t; c < W; c += bd) m = fmaxf(m, row[c]);
    red[t] = m; __syncthreads();
    for (int s = bd >> 1; s > 0; s >>= 1) {
        if (t < s) red[t] = fmaxf(red[t], red[t + s]);
        __syncthreads();
    }
    m = red[0]; __syncthreads();
    float sum = 0.f;
    for (int c = t; c < W; c += bd) { float e = expf(row[c] - m); row[c] = e; sum += e; }
    red[t] = sum; __syncthreads();
    for (int s = bd >> 1; s > 0; s >>= 1) {
        if (t < s) red[t] += red[t + s];
        __syncthreads();
    }
    float inv = 1.f / red[0];
    for (int c = t; c < W; c += bd) row[c] *= inv;
}

// ---------------- generic tiled GEMM: C = act(A@B + bias) ----------------
__global__ void k_gemm_nn(int M, int N, int K,
                          const float* __restrict__ A, const float* __restrict__ B,
                          const float* __restrict__ bias, float* __restrict__ C,
                          int act, const float* __restrict__ aux) {
    __shared__ __align__(16) float As[16][68];
    __shared__ __align__(16) float Bs[16][64];
    int t = threadIdx.x;
    int m0 = blockIdx.x * 64, n0 = blockIdx.y * 64;
    int tx = t & 15, ty = t >> 4;
    float acc[4][4];
#pragma unroll
    for (int i = 0; i < 4; i++)
#pragma unroll
        for (int j = 0; j < 4; j++) acc[i][j] = 0.f;
    for (int k0 = 0; k0 < K; k0 += 16) {
        __syncthreads();
        for (int idx = t; idx < 1024; idx += 256) {
            int kk = idx & 15, r = idx >> 4;
            int row = m0 + r;
            As[kk][r] = (row < M) ? A[(size_t)row * K + k0 + kk] : 0.f;
        }
        for (int idx = t; idx < 1024; idx += 256) {
            int kk = idx >> 6, c = idx & 63;
            int col = n0 + c;
            Bs[kk][c] = (col < N) ? B[(size_t)(k0 + kk) * N + col] : 0.f;
        }
        __syncthreads();
#pragma unroll
        for (int kk = 0; kk < 16; kk++) {
            float4 av = *(const float4*)&As[kk][ty * 4];
            float4 bv = *(const float4*)&Bs[kk][tx * 4];
            float a4[4] = {av.x, av.y, av.z, av.w};
            float b4[4] = {bv.x, bv.y, bv.z, bv.w};
#pragma unroll
            for (int i = 0; i < 4; i++)
#pragma unroll
                for (int j = 0; j < 4; j++) acc[i][j] += a4[i] * b4[j];
        }
    }
    float slope = (act == 2) ? aux[0] : 0.f;
#pragma unroll
    for (int i = 0; i < 4; i++) {
        int row = m0 + ty * 4 + i;
        if (row >= M) continue;
#pragma unroll
        for (int j = 0; j < 4; j++) {
            int col = n0 + tx * 4 + j;
            if (col >= N) continue;
            float v = acc[i][j];
            if (bias) v += bias[col];
            if (act == 1) v = fmaxf(v, 0.f);
            else if (act == 2) v = (v >= 0.f) ? v : slope * v;
            C[(size_t)row * N + col] = v;
        }
    }
}

// ---------------- dual-B split-K TN GEMM ----------------
__global__ void k_gemm_tn_split2(int tiles, int K1, int N,
                                 const float* __restrict__ A,
                                 const float* __restrict__ B1,
                                 const float* __restrict__ B2,
                                 float* __restrict__ part1, float* __restrict__ part2) {
    __shared__ __align__(16) float As[16][64];
    __shared__ __align__(16) float Bs1[16][64];
    __shared__ __align__(16) float Bs2[16][64];
    int t = threadIdx.x;
    int k0 = blockIdx.x * 64, n0 = blockIdx.y * 64;
    int s = blockIdx.z;
    int mBase = s * tiles * 16;
    int tx = t & 15, ty = t >> 4;
    float acc1[4][4], acc2[4][4];
#pragma unroll
    for (int i = 0; i < 4; i++)
#pragma unroll
        for (int j = 0; j < 4; j++) { acc1[i][j] = 0.f; acc2[i][j] = 0.f; }
    for (int mt = 0; mt < tiles; mt++) {
        int m0 = mBase + mt * 16;
        __syncthreads();
        for (int idx = t; idx < 1024; idx += 256) {
            int mm = idx >> 6, c = idx & 63;
            As[mm][c]  = (k0 + c < K1) ? A[(size_t)(m0 + mm) * K1 + k0 + c] : 0.f;
            Bs1[mm][c] = (n0 + c < N) ? B1[(size_t)(m0 + mm) * N + n0 + c] : 0.f;
            Bs2[mm][c] = (n0 + c < N) ? B2[(size_t)(m0 + mm) * N + n0 + c] : 0.f;
        }
        __syncthreads();
#pragma unroll
        for (int mm = 0; mm < 16; mm++) {
            float4 av = *(const float4*)&As[mm][ty * 4];
            float4 b1 = *(const float4*)&Bs1[mm][tx * 4];
            float4 b2 = *(const float4*)&Bs2[mm][tx * 4];
            float a4[4] = {av.x, av.y, av.z, av.w};
            float c4[4] = {b1.x, b1.y, b1.z, b1.w};
            float d4[4] = {b2.x, b2.y, b2.z, b2.w};
#pragma unroll
            for (int i = 0; i < 4; i++)
#pragma unroll
                for (int j = 0; j < 4; j++) {
                    acc1[i][j] += a4[i] * c4[j];
                    acc2[i][j] += a4[i] * d4[j];
                }
        }
    }
#pragma unroll
    for (int i = 0; i < 4; i++) {
        int kr = k0 + ty * 4 + i;
        if (kr >= K1) continue;
#pragma unroll
        for (int j = 0; j < 4; j++) {
            int col = n0 + tx * 4 + j;
            if (col >= N) continue;
            part1[((size_t)s * K1 + kr) * N + col] = acc1[i][j];
            part2[((size_t)s * K1 + kr) * N + col] = acc2[i][j];
        }
    }
}

// dual reduce: out1 = sum(part1)/div, out2 = sum(part2)
__global__ void k_tn_red2(const float* __restrict__ part1, const float* __restrict__ part2,
                          int S, int K1, int N,
                          const float* __restrict__ divrow,
                          float* __restrict__ out1, float* __restrict__ out2) {
    int i = blockIdx.x * blockDim.x + threadIdx.x;
    if (i >= K1 * N) return;
    float s1 = 0.f, s2 = 0.f;
    for (int b = 0; b < S; b++) {
        s1 += part1[(size_t)b * K1 * N + i];
        s2 += part2[(size_t)b * K1 * N + i];
    }
    if (divrow) s1 /= (divrow[i / N] + 1e-12f);
    out1[i] = s1;
    out2[i] = s2;
}

// ---------------- tiny colsum for S1 [400 x 20] ----------------
__global__ void k_colsum20(const float* __restrict__ S1, float* __restrict__ cs) {
    int t = threadIdx.x;
    if (t >= C1) return;
    float s = 0.f;
#pragma unroll 4
    for (int r = 0; r < C0; r++) s += S1[r * C1 + t];
    cs[t] = s;
}

// ---------------- tf32 helper ----------------
__device__ __forceinline__ unsigned tf32r(float x) {
    unsigned u;
    asm("cvt.rna.tf32.f32 %0, %1;" : "=r"(u) : "f"(x));
    return u;
}

// ---------------- FUSED: mask(K=400 MMA) + mask(K=20) + serial carry ----------------
// smem (77312 B total -> 2 CTA/SM):
//  phase1 alias: Us[128][36] u32 @0 (18432), Gs[32][136] u32 @18432 (17408)
//  phase2 alias: Ms[128][129] f32 @0 (66048)
//  persistent:   G1s[20][128] @66048 (10240), rr @76288 (512), cc @76800 (512)
__global__ void __launch_bounds__(256, 2)
k_fused_mask(const float* __restrict__ s0p, const float* __restrict__ g0sq,
             const float* __restrict__ p1, const float* __restrict__ g1sq,
             const int* __restrict__ er, const int* __restrict__ ec,
             const float* __restrict__ adjv, float* __restrict__ outAdj) {
    extern __shared__ __align__(16) char sm[];
    unsigned (*Us)[36]  = (unsigned(*)[36])(sm);
    unsigned (*Gs)[136] = (unsigned(*)[136])(sm + 18432);
    float (*Ms)[129]    = (float(*)[129])(sm);
    float (*G1s)[128]   = (float(*)[128])(sm + 66048);
    int* rr             = (int*)(sm + 76288);
    int* cc             = (int*)(sm + 76800);

    int t = threadIdx.x, lane = t & 31, w = t >> 5;
    int e0 = blockIdx.x * 128;
    if (t < 128) { rr[t] = er[e0 + t]; cc[t] = ec[e0 + t]; }
    for (int idx = t; idx < C1 * FDIM; idx += 256)
        G1s[idx >> 7][idx & 127] = g1sq[idx];
    float acc[16][4];
#pragma unroll
    for (int nt = 0; nt < 16; nt++)
#pragma unroll
        for (int i = 0; i < 4; i++) acc[nt][i] = 0.f;
    __syncthreads();

    for (int k0 = 0; k0 < C0; k0 += 32) {
        for (int idx = t; idx < 32 * 128; idx += 256) {
            int kk = idx >> 7, f = idx & 127;
            float v = (k0 + kk < C0) ? g0sq[(size_t)(k0 + kk) * FDIM + f] : 0.f;
            Gs[kk][f] = tf32r(v);
        }
        for (int idx = t; idx < 128 * 32; idx += 256) {
            int kk = idx & 31, e = idx >> 5;
            float v = 0.f;
            if (k0 + kk < C0)
                v = s0p[(size_t)rr[e] * C0 + k0 + kk] * s0p[(size_t)cc[e] * C0 + k0 + kk];
            Us[e][kk] = tf32r(v);
        }
        __syncthreads();
#pragma unroll
        for (int ks = 0; ks < 4; ks++) {
            int kb = ks * 8;
            int ar = w * 16 + (lane >> 2);
            int ak = kb + (lane & 3);
            unsigned a0 = Us[ar][ak];
            unsigned a1 = Us[ar + 8][ak];
            unsigned a2 = Us[ar][ak + 4];
            unsigned a3 = Us[ar + 8][ak + 4];
#pragma unroll
            for (int nt = 0; nt < 16; nt++) {
                int bn = nt * 8 + (lane >> 2);
                unsigned b0 = Gs[kb + (lane & 3)][bn];
                unsigned b1 = Gs[kb + (lane & 3) + 4][bn];
                asm volatile(
                    "mma.sync.aligned.m16n8k8.row.col.f32.tf32.tf32.f32 "
                    "{%0,%1,%2,%3}, {%4,%5,%6,%7}, {%8,%9}, {%0,%1,%2,%3};"
                    : "+f"(acc[nt][0]), "+f"(acc[nt][1]),
                      "+f"(acc[nt][2]), "+f"(acc[nt][3])
                    : "r"(a0), "r"(a1), "r"(a2), "r"(a3), "r"(b0), "r"(b1));
            }
        }
        __syncthreads();
    }
    {
        int r = w * 16 + (lane >> 2);
        int cb = 2 * (lane & 3);
#pragma unroll
        for (int nt = 0; nt < 16; nt++) {
            int c = nt * 8 + cb;
            Ms[c][r]         = acc[nt][0];
            Ms[c + 1][r]     = acc[nt][1];
            Ms[c][r + 8]     = acc[nt][2];
            Ms[c + 1][r + 8] = acc[nt][3];
        }
    }
    __syncthreads();
    if (t < 128) {
        int e = t;
        float u20[C1];
        const float* pr = p1 + (size_t)rr[e] * C1;
        const float* pc = p1 + (size_t)cc[e] * C1;
#pragma unroll
        for (int k = 0; k < C1; k++) u20[k] = pr[k] * pc[k];
        float a = adjv[e0 + e];
        for (int f = 0; f < FDIM; f++) {
            float mA = 0.f;
#pragma unroll
            for (int k = 0; k < C1; k++) mA += u20[k] * G1s[k][f];
            float mB = Ms[f][e];
            float tq = a * mA;
            outAdj[(size_t)f * EDGES + e0 + e] = tq + tq * mB;
            a = tq * mB;
        }
    }
}

// ---------------- CSR build (atomic order within row; fp-tolerance safe) ----------
__global__ void k_count(const int* __restrict__ er) {
    int e = blockIdx.x * blockDim.x + threadIdx.x;
    if (e < EDGES) atomicAdd(&g_cnt[er[e]], 1);
}

__global__ void k_scan() {
    __shared__ int part[1024];
    const int n = N_NODES;
    const int per = (n + 1023) / 1024;
    int t = threadIdx.x;
    int s = 0;
    int lo = t * per, hi = min(n, (t + 1) * per);
    for (int i = lo; i < hi; i++) s += g_cnt[i];
    part[t] = s; __syncthreads();
    for (int off = 1; off < 1024; off <<= 1) {
        int v = (t >= off) ? part[t - off] : 0;
        __syncthreads();
        part[t] += v;
        __syncthreads();
    }
    int base = (t == 0) ? 0 : part[t - 1];
    for (int i = lo; i < hi; i++) {
        g_off[i] = base; g_cur[i] = base; base += g_cnt[i];
    }
    if (t == 1023) g_off[n] = base;
}

__global__ void k_scatter(const int* __restrict__ er, const int* __restrict__ ec,
                          const float* __restrict__ nv) {
    int e = blockIdx.x * blockDim.x + threadIdx.x;
    if (e < EDGES) {
        int pos = atomicAdd(&g_cur[er[e]], 1);
        g_colS[pos] = ec[e];
        g_wS[pos]   = nv[e];
    }
}

// ---------------- one propagation step (2 nodes per block) ----------------
__global__ void k_prop(const float* __restrict__ xin, float* __restrict__ xout) {
    int r = blockIdx.x * 2 + (threadIdx.x >> 7);
    int f = threadIdx.x & 127;
    float acc = 0.f;
    int s = g_off[r], e = g_off[r + 1];
    for (int i = s; i < e; i++) {
        int c = g_colS[i];
        float w = g_wS[i];
        acc += w * xin[(size_t)c * FDIM + f];
    }
    xout[(size_t)r * FDIM + f] = acc;
}

// ---------------- final logits + log_softmax ----------------
__global__ void k_final(const float* __restrict__ h, const float* __restrict__ W,
                        const float* __restrict__ b, float* __restrict__ out) {
    int warp = (blockIdx.x * blockDim.x + threadIdx.x) >> 5;
    int lane = threadIdx.x & 31;
    if (warp >= N_NODES) return;
    float p0 = 0.f, p1 = 0.f;
#pragma unroll
    for (int j = 0; j < 4; j++) {
        int k = lane + 32 * j;
        float hv = h[(size_t)warp * FDIM + k];
        p0 += hv * W[k * 2];
        p1 += hv * W[k * 2 + 1];
    }
    for (int o = 16; o; o >>= 1) {
        p0 += __shfl_down_sync(0xFFFFFFFFu, p0, o);
        p1 += __shfl_down_sync(0xFFFFFFFFu, p1, o);
    }
    if (lane == 0) {
        float l0 = p0 + b[0], l1 = p1 + b[1];
        float m = fmaxf(l0, l1);
        float ls = m + logf(expf(l0 - m) + expf(l1 - m));
        out[warp * 2]     = l0 - ls;
        out[warp * 2 + 1] = l1 - ls;
    }
}

// ================= host launcher =================
#define GSYM(var, sym) float* var; { void* _p = 0; cudaGetSymbolAddress(&_p, sym); var = (float*)_p; }

extern "C" void kernel_launch(void* const* d_in, const int* in_sizes, int n_in,
                              void* d_out, int out_size) {
    const float* x    = (const float*)d_in[0];
    const float* xcov = (const float*)d_in[1];
    const int*   er   = (const int*)d_in[2];
    const int*   ec   = (const int*)d_in[3];
    const float* adjv = (const float*)d_in[4];
    const float* nv   = (const float*)d_in[5];
    const float* gam  = (const float*)d_in[6];
    const float* bet  = (const float*)d_in[7];
    const float* c0W1 = (const float*)d_in[8];
    const float* c0b1 = (const float*)d_in[9];
    const float* c0W2 = (const float*)d_in[10];
    const float* c0b2 = (const float*)d_in[11];
    const float* c1W1 = (const float*)d_in[12];
    const float* c1b1 = (const float*)d_in[13];
    const float* c1W2 = (const float*)d_in[14];
    const float* c1b2 = (const float*)d_in[15];
    // c2_* (d_in[16..19]) are dead code in the reference
    const float* mW1 = (const float*)d_in[20];
    const float* mb1 = (const float*)d_in[21];
    const float* a1  = (const float*)d_in[22];
    const float* mW2 = (const float*)d_in[23];
    const float* mb2 = (const float*)d_in[24];
    const float* a2  = (const float*)d_in[25];
    const float* mW3 = (const float*)d_in[26];
    const float* mb3 = (const float*)d_in[27];

    float* outLog = (float*)d_out;
    float* outAdj = (float*)d_out + (size_t)N_NODES * 2;

    GSYM(xbn, g_xbn)   GSYM(xp0, g_xp0)   GSYM(xp1, g_xp1)
    GSYM(hA,  g_hA)    GSYM(hB1, g_hB1)   GSYM(hB2, g_hB2)
    GSYM(S0,  g_S0)    GSYM(corr0, g_corr0)
    GSYM(cs0, g_cs0)   GSYM(cs1, g_cs1)
    GSYM(xc1, g_xc1)   GSYM(corr1, g_corr1) GSYM(T0, g_T0) GSYM(G0, g_G0)
    GSYM(S1,  g_S1)    GSYM(xc2, g_xc2)   GSYM(corr2, g_corr2)
    GSYM(T1,  g_T1)    GSYM(G1,  g_G1)    GSYM(P1,  g_P1)
    GSYM(pa1, g_pa1)   GSYM(pa2, g_pa2)   GSYM(pc1, g_pc1)
    GSYM(csA, g_csA)   GSYM(cssA, g_cssA)
    GSYM(csB, g_csB)   GSYM(cssB, g_cssB)
    GSYM(csC, g_csC)   GSYM(cssC, g_cssC)
    GSYM(pb1, g_pb1)   GSYM(pb2, g_pb2)
    GSYM(csX, g_csX)   GSYM(cssX, g_cssX)
    GSYM(tnp, g_tnpart) GSYM(tnp2, g_tnpart2)
    void* cntp = 0; cudaGetSymbolAddress(&cntp, g_cnt);

    const int FUSED_SMEM = 77312;
    cudaFuncSetAttribute(k_fused_mask, cudaFuncAttributeMaxDynamicSharedMemorySize,
                         FUSED_SMEM);

    cudaStream_t s2, s3;
    cudaStreamCreateWithFlags(&s2, cudaStreamNonBlocking);
    cudaStreamCreateWithFlags(&s3, cudaStreamNonBlocking);
    cudaEvent_t evFork, evJoin, evCorr0;
    cudaEventCreateWithFlags(&evFork, cudaEventDisableTiming);
    cudaEventCreateWithFlags(&evJoin, cudaEventDisableTiming);
    cudaEventCreateWithFlags(&evCorr0, cudaEventDisableTiming);
    cudaEventRecord(evFork, 0);
    cudaStreamWaitEvent(s2, evFork, 0);
    cudaStreamWaitEvent(s3, evFork, 0);

    // ============ chain B (s2): bn -> CSR -> prop -> MLP -> outLog ============
    k_psum<<<250, 128, 0, s2>>>(x, N_NODES, FDIM, 32, pb1, pb2);
    k_preduce<<<1, 128, 0, s2>>>(pb1, pb2, 250, FDIM, N_NODES, csX, cssX);
    k_bn<<<(N_NODES * FDIM + 255) / 256, 256, 0, s2>>>(x, csX, cssX, gam, bet, xbn);

    cudaMemsetAsync(cntp, 0, N_NODES * 4, s2);
    k_count<<<EDGES / 256, 256, 0, s2>>>(er);
    k_scan<<<1, 1024, 0, s2>>>();
    k_scatter<<<EDGES / 256, 256, 0, s2>>>(er, ec, nv);

    {
        const float* cur = xbn;
        float* bufs[2] = {xp0, xp1};
        for (int it = 0; it < 10; it++) {
            float* o = bufs[it & 1];
            k_prop<<<N_NODES / 2, 256, 0, s2>>>(cur, o);
            cur = o;
        }
    }
    k_gemm_nn<<<dim3(125, 2), 256, 0, s2>>>(N_NODES, FDIM, FDIM, xp1, mW1, mb1, hB1, 2, a1);
    k_gemm_nn<<<dim3(125, 2), 256, 0, s2>>>(N_NODES, FDIM, FDIM, hB1, mW2, mb2, hB2, 2, a2);
    k_final<<<(N_NODES * 32 + 255) / 256, 256, 0, s2>>>(hB2, mW3, mb3, outLog);

    // ============ chain C (s3): corr0 = node_corr(x_cov) ============
    k_psum<<<250, 128, 0, s3>>>(xcov, N_NODES, FDIM, 32, pa1, pa2);
    k_preduce<<<1, 128, 0, s3>>>(pa1, pa2, 250, FDIM, N_NODES, csA, cssA);
    k_corr<<<N_NODES, 128, 0, s3>>>(xcov, N_NODES, csA, cssA, corr0, 0, 0);
    cudaEventRecord(evCorr0, s3);

    // ============ chain A (stream 0): clustering -> masks -> outAdj ============
    k_gemm_nn<<<dim3(125, 2), 256>>>(N_NODES, FDIM, FDIM, xcov, c0W1, c0b1, hA, 1, 0);
    k_gemm_nn<<<dim3(125, 7), 256>>>(N_NODES, C0, FDIM, hA, c0W2, c0b2, S0, 0, 0);
    k_softmax400<<<N_NODES, 128>>>(S0);
    k_psum<<<250, 128>>>(S0, N_NODES, C0, 32, pc1, 0);
    k_preduce<<<4, 128>>>(pc1, 0, 250, C0, N_NODES, cs0, 0);

    cudaStreamWaitEvent(0, evCorr0, 0);
    // xc1 = (S0^T @ xcov)/cs0 ; T0 = S0^T @ corr0  (dual-B split-K)
    k_gemm_tn_split2<<<dim3(7, 2, 20), 256>>>(25, C0, FDIM, S0, xcov, corr0, tnp, tnp2);
    k_tn_red2<<<(C0 * FDIM + 255) / 256, 256>>>(tnp, tnp2, 20, C0, FDIM, cs0, xc1, T0);

    // corr1 + gains0 (fused)
    k_stats_small<<<1, 128>>>(xc1, C0, csB, cssB);
    k_corr<<<C0, 128>>>(xc1, C0, csB, cssB, corr1, T0, G0);

    // level 1 cluster
    k_gemm_nn<<<dim3(7, 2), 256>>>(C0, FDIM, FDIM, xc1, c1W1, c1b1, hA, 1, 0);
    k_gemm_nn<<<dim3(7, 1), 256>>>(C0, C1, FDIM, hA, c1W2, c1b2, S1, 0, 0);
    k_softmax<<<C0, 32>>>(S1, C1);
    k_colsum20<<<1, 32>>>(S1, cs1);
    k_gemm_tn_split2<<<dim3(1, 2, 5), 256>>>(5, C1, FDIM, S1, xc1, corr1, tnp, tnp2);
    k_tn_red2<<<(C1 * FDIM + 255) / 256, 256>>>(tnp, tnp2, 5, C1, FDIM, cs1, xc2, T1);

    // corr2 + gains1 (fused)
    k_stats_small<<<1, 128>>>(xc2, C1, csC, cssC);
    k_corr<<<C1, 128>>>(xc2, C1, csC, cssC, corr2, T1, G1);

    // projector P1 = S0 @ S1
    k_gemm_nn<<<dim3(125, 1), 256>>>(N_NODES, C1, C0, S0, S1, 0, P1, 0, 0);

    // fused masks + serial carry -> adjs output
    k_fused_mask<<<EDGES / 128, 256, FUSED_SMEM>>>(S0, G0, P1, G1, er, ec, adjv, outAdj);

    // ============ join ============
    cudaEventRecord(evJoin, s2);
    cudaStreamWaitEvent(0, evJoin, 0);

    cudaEventDestroy(evFork);
    cudaEventDestroy(evJoin);
    cudaEventDestroy(evCorr0);
    cudaStreamDestroy(s2);
    cudaStreamDestroy(s3);

    (void)in_sizes; (void)n_in; (void)out_size;
}

// round 9
// speedup vs baseline: 1.2783x; 1.0625x over previous
#include <cuda_runtime.h>
#include <math.h>

#define N_NODES 8000
#define FDIM    128
#define EDGES   256000
#define C0      400
#define C1      20

// ---------------- static device scratch (no runtime allocation) ----------------
__device__ float g_xp0[N_NODES*FDIM];
__device__ float g_xp1[N_NODES*FDIM];
__device__ float g_hA [N_NODES*FDIM];
__device__ float g_hB1[N_NODES*FDIM];
__device__ float g_hB2[N_NODES*FDIM];
__device__ float g_S0 [N_NODES*C0];
__device__ float g_corr0[N_NODES*FDIM];
__device__ float g_cs0[C0];
__device__ float g_cs1[C1];
__device__ float g_xc1  [C0*FDIM];
__device__ float g_corr1[C0*FDIM];
__device__ float g_T0   [C0*FDIM];
__device__ float g_G0   [C0*FDIM];
__device__ float g_S1   [C0*C1];
__device__ float g_xc2  [C1*FDIM];
__device__ float g_corr2[C1*FDIM];
__device__ float g_T1   [C1*FDIM];
__device__ float g_G1   [C1*FDIM];
__device__ float g_P1   [N_NODES*C1];
__device__ float g_pa1[250*C0];     // corr0 stats partials (s3)
__device__ float g_pa2[250*C0];
__device__ float g_pc1[250*C0];     // S0 colsum partials (s3)
__device__ float g_csA[FDIM];
__device__ float g_cssA[FDIM];
__device__ float g_csB[FDIM];       // xc1 stats (raw sums via atomics)
__device__ float g_qB [FDIM];
__device__ float g_csC[FDIM];       // xc2 stats (raw sums via atomics)
__device__ float g_qC [FDIM];
__device__ float g_pb1[250*FDIM];   // BN stats partials (s2)
__device__ float g_pb2[250*FDIM];
__device__ float g_csX[FDIM];
__device__ float g_cssX[FDIM];
__device__ float g_tnpart [20*C0*FDIM];
__device__ float g_tnpart2[20*C0*FDIM];
__device__ int   g_cnt[N_NODES];
__device__ int   g_off[N_NODES+1];
__device__ int   g_cur[N_NODES];
__device__ int   g_colS[EDGES];
__device__ float g_wS  [EDGES];

// ---------------- zero all atomic-accumulated buffers + cnt (one launch) --------
__global__ void k_zero() {
    int i = blockIdx.x * blockDim.x + threadIdx.x;
    if (i < N_NODES) g_cnt[i] = 0;
    if (i < FDIM) { g_csB[i] = 0.f; g_qB[i] = 0.f; g_csC[i] = 0.f; g_qC[i] = 0.f; }
    if (i < C1) g_cs1[i] = 0.f;
}

// ---------------- two-stage deterministic column stats (large inputs) ----------
__global__ void k_psum(const float* __restrict__ A, int n, int c, int rowsPer,
                       float* __restrict__ ps, float* __restrict__ pq) {
    int b = blockIdx.x;
    int r0 = b * rowsPer, r1 = min(n, r0 + rowsPer);
    for (int col = threadIdx.x; col < c; col += blockDim.x) {
        float s = 0.f, q = 0.f;
        for (int r = r0; r < r1; r++) {
            float v = A[(size_t)r * c + col];
            s += v; q += v * v;
        }
        ps[(size_t)b * c + col] = s;
        if (pq) pq[(size_t)b * c + col] = q;
    }
}

__global__ void k_preduce(const float* __restrict__ ps, const float* __restrict__ pq,
                          int nb, int c, int n,
                          float* __restrict__ outS, float* __restrict__ outCss) {
    int col = blockIdx.x * blockDim.x + threadIdx.x;
    if (col >= c) return;
    float s = 0.f, q = 0.f;
    for (int b = 0; b < nb; b++) {
        s += ps[(size_t)b * c + col];
        if (pq) q += pq[(size_t)b * c + col];
    }
    outS[col] = s;
    if (outCss) outCss[col] = q - s * s / (float)n;
}

// ---------------- node correlation (+ optional fused gains) ----------------
__global__ void k_corr(const float* __restrict__ z, int n,
                       const float* __restrict__ cs, const float* __restrict__ cssOrQ,
                       float* __restrict__ out,
                       const float* __restrict__ T, float* __restrict__ G, int rawq) {
    int r = blockIdx.x, f = threadIdx.x;
    float s = cs[f];
    float mean = s / (float)n;
    float css = rawq ? (cssOrQ[f] - s * s / (float)n) : cssOrQ[f];
    float inv = 1.f / (sqrtf(css) + 1e-12f);
    float v = (z[(size_t)r * FDIM + f] - mean) * inv;
    __shared__ float red[128];
    red[f] = v; __syncthreads();
    for (int st = 64; st > 0; st >>= 1) {
        if (f < st) red[f] += red[f + st];
        __syncthreads();
    }
    size_t idx = (size_t)r * FDIM + f;
    float cv = v * red[0];
    out[idx] = cv;
    if (T) {
        float x = 1.f / (1.f + expf(T[idx] - cv));
        G[idx] = x * x;
    }
}

// ---------------- softmax for S0 rows (W=400), register-resident ----------------
__global__ void k_softmax400(float* __restrict__ X) {
    int r = blockIdx.x;
    float* row = X + (size_t)r * C0;
    int t = threadIdx.x;                       // 128
    int cnt = (t < C0 - 3 * 128) ? 4 : 3;
    float v[4];
    float m = -3.4e38f;
#pragma unroll
    for (int j = 0; j < 4; j++) {
        if (j < cnt) { v[j] = row[t + 128 * j]; m = fmaxf(m, v[j]); }
    }
    __shared__ float red[128];
    red[t] = m; __syncthreads();
    for (int s = 64; s > 0; s >>= 1) {
        if (t < s) red[t] = fmaxf(red[t], red[t + s]);
        __syncthreads();
    }
    m = red[0]; __syncthreads();
    float sum = 0.f;
#pragma unroll
    for (int j = 0; j < 4; j++) {
        if (j < cnt) { v[j] = expf(v[j] - m); sum += v[j]; }
    }
    red[t] = sum; __syncthreads();
    for (int s = 64; s > 0; s >>= 1) {
        if (t < s) red[t] += red[t + s];
        __syncthreads();
    }
    float inv = 1.f / red[0];
#pragma unroll
    for (int j = 0; j < 4; j++) {
        if (j < cnt) row[t + 128 * j] = v[j] * inv;
    }
}

// ---------------- softmax for S1 rows (W=20), warp/row + fused colsum ----------
__global__ void k_softmax20(float* __restrict__ X, float* __restrict__ cs) {
    int warp = (blockIdx.x * blockDim.x + threadIdx.x) >> 5;
    int lane = threadIdx.x & 31;
    if (warp >= C0) return;
    float* row = X + (size_t)warp * C1;
    float v = (lane < C1) ? row[lane] : -3.4e38f;
    float m = v;
#pragma unroll
    for (int o = 16; o; o >>= 1) m = fmaxf(m, __shfl_xor_sync(0xFFFFFFFFu, m, o));
    float e = (lane < C1) ? expf(v - m) : 0.f;
    float s = e;
#pragma unroll
    for (int o = 16; o; o >>= 1) s += __shfl_xor_sync(0xFFFFFFFFu, s, o);
    if (lane < C1) {
        float val = e / s;
        row[lane] = val;
        atomicAdd(&cs[lane], val);
    }
}

// ---------------- generic tiled GEMM: C = act(A@B + bias) ----------------
__global__ void k_gemm_nn(int M, int N, int K,
                          const float* __restrict__ A, const float* __restrict__ B,
                          const float* __restrict__ bias, float* __restrict__ C,
                          int act, const float* __restrict__ aux) {
    __shared__ __align__(16) float As[16][68];
    __shared__ __align__(16) float Bs[16][64];
    int t = threadIdx.x;
    int m0 = blockIdx.x * 64, n0 = blockIdx.y * 64;
    int tx = t & 15, ty = t >> 4;
    float acc[4][4];
#pragma unroll
    for (int i = 0; i < 4; i++)
#pragma unroll
        for (int j = 0; j < 4; j++) acc[i][j] = 0.f;
    for (int k0 = 0; k0 < K; k0 += 16) {
        __syncthreads();
        for (int idx = t; idx < 1024; idx += 256) {
            int kk = idx & 15, r = idx >> 4;
            int row = m0 + r;
            As[kk][r] = (row < M) ? A[(size_t)row * K + k0 + kk] : 0.f;
        }
        for (int idx = t; idx < 1024; idx += 256) {
            int kk = idx >> 6, c = idx & 63;
            int col = n0 + c;
            Bs[kk][c] = (col < N) ? B[(size_t)(k0 + kk) * N + col] : 0.f;
        }
        __syncthreads();
#pragma unroll
        for (int kk = 0; kk < 16; kk++) {
            float4 av = *(const float4*)&As[kk][ty * 4];
            float4 bv = *(const float4*)&Bs[kk][tx * 4];
            float a4[4] = {av.x, av.y, av.z, av.w};
            float b4[4] = {bv.x, bv.y, bv.z, bv.w};
#pragma unroll
            for (int i = 0; i < 4; i++)
#pragma unroll
                for (int j = 0; j < 4; j++) acc[i][j] += a4[i] * b4[j];
        }
    }
    float slope = (act == 2) ? aux[0] : 0.f;
#pragma unroll
    for (int i = 0; i < 4; i++) {
        int row = m0 + ty * 4 + i;
        if (row >= M) continue;
#pragma unroll
        for (int j = 0; j < 4; j++) {
            int col = n0 + tx * 4 + j;
            if (col >= N) continue;
            float v = acc[i][j];
            if (bias) v += bias[col];
            if (act == 1) v = fmaxf(v, 0.f);
            else if (act == 2) v = (v >= 0.f) ? v : slope * v;
            C[(size_t)row * N + col] = v;
        }
    }
}

// ---------------- dual-B split-K TN GEMM ----------------
__global__ void k_gemm_tn_split2(int tiles, int K1, int N,
                                 const float* __restrict__ A,
                                 const float* __restrict__ B1,
                                 const float* __restrict__ B2,
                                 float* __restrict__ part1, float* __restrict__ part2) {
    __shared__ __align__(16) float As[16][64];
    __shared__ __align__(16) float Bs1[16][64];
    __shared__ __align__(16) float Bs2[16][64];
    int t = threadIdx.x;
    int k0 = blockIdx.x * 64, n0 = blockIdx.y * 64;
    int s = blockIdx.z;
    int mBase = s * tiles * 16;
    int tx = t & 15, ty = t >> 4;
    float acc1[4][4], acc2[4][4];
#pragma unroll
    for (int i = 0; i < 4; i++)
#pragma unroll
        for (int j = 0; j < 4; j++) { acc1[i][j] = 0.f; acc2[i][j] = 0.f; }
    for (int mt = 0; mt < tiles; mt++) {
        int m0 = mBase + mt * 16;
        __syncthreads();
        for (int idx = t; idx < 1024; idx += 256) {
            int mm = idx >> 6, c = idx & 63;
            As[mm][c]  = (k0 + c < K1) ? A[(size_t)(m0 + mm) * K1 + k0 + c] : 0.f;
            Bs1[mm][c] = (n0 + c < N) ? B1[(size_t)(m0 + mm) * N + n0 + c] : 0.f;
            Bs2[mm][c] = (n0 + c < N) ? B2[(size_t)(m0 + mm) * N + n0 + c] : 0.f;
        }
        __syncthreads();
#pragma unroll
        for (int mm = 0; mm < 16; mm++) {
            float4 av = *(const float4*)&As[mm][ty * 4];
            float4 b1 = *(const float4*)&Bs1[mm][tx * 4];
            float4 b2 = *(const float4*)&Bs2[mm][tx * 4];
            float a4[4] = {av.x, av.y, av.z, av.w};
            float c4[4] = {b1.x, b1.y, b1.z, b1.w};
            float d4[4] = {b2.x, b2.y, b2.z, b2.w};
#pragma unroll
            for (int i = 0; i < 4; i++)
#pragma unroll
                for (int j = 0; j < 4; j++) {
                    acc1[i][j] += a4[i] * c4[j];
                    acc2[i][j] += a4[i] * d4[j];
                }
        }
    }
#pragma unroll
    for (int i = 0; i < 4; i++) {
        int kr = k0 + ty * 4 + i;
        if (kr >= K1) continue;
#pragma unroll
        for (int j = 0; j < 4; j++) {
            int col = n0 + tx * 4 + j;
            if (col >= N) continue;
            part1[((size_t)s * K1 + kr) * N + col] = acc1[i][j];
            part2[((size_t)s * K1 + kr) * N + col] = acc2[i][j];
        }
    }
}

// dual reduce + fused atomic column-stats of out1 (if csS!=0)
__global__ void k_tn_red2(const float* __restrict__ part1, const float* __restrict__ part2,
                          int S, int K1, int N,
                          const float* __restrict__ divrow,
                          float* __restrict__ out1, float* __restrict__ out2,
                          float* __restrict__ csS, float* __restrict__ qS) {
    int i = blockIdx.x * blockDim.x + threadIdx.x;
    if (i >= K1 * N) return;
    float s1 = 0.f, s2 = 0.f;
    for (int b = 0; b < S; b++) {
        s1 += part1[(size_t)b * K1 * N + i];
        s2 += part2[(size_t)b * K1 * N + i];
    }
    if (divrow) s1 /= (divrow[i / N] + 1e-12f);
    out1[i] = s1;
    out2[i] = s2;
    if (csS) {
        int f = i % N;   // N == FDIM in both uses
        atomicAdd(&csS[f], s1);
        atomicAdd(&qS[f], s1 * s1);
    }
}

// ---------------- tf32 helper ----------------
__device__ __forceinline__ unsigned tf32r(float x) {
    unsigned u;
    asm("cvt.rna.tf32.f32 %0, %1;" : "=r"(u) : "f"(x));
    return u;
}

// ---------------- FUSED: mask(K=400 MMA) + mask(K=20) + serial carry ----------------
__global__ void __launch_bounds__(256, 2)
k_fused_mask(const float* __restrict__ s0p, const float* __restrict__ g0sq,
             const float* __restrict__ p1, const float* __restrict__ g1sq,
             const int* __restrict__ er, const int* __restrict__ ec,
             const float* __restrict__ adjv, float* __restrict__ outAdj) {
    extern __shared__ __align__(16) char sm[];
    unsigned (*Us)[36]  = (unsigned(*)[36])(sm);
    unsigned (*Gs)[136] = (unsigned(*)[136])(sm + 18432);
    float (*Ms)[129]    = (float(*)[129])(sm);
    float (*G1s)[128]   = (float(*)[128])(sm + 66048);
    int* rr             = (int*)(sm + 76288);
    int* cc             = (int*)(sm + 76800);

    int t = threadIdx.x, lane = t & 31, w = t >> 5;
    int e0 = blockIdx.x * 128;
    if (t < 128) { rr[t] = er[e0 + t]; cc[t] = ec[e0 + t]; }
    for (int idx = t; idx < C1 * FDIM; idx += 256)
        G1s[idx >> 7][idx & 127] = g1sq[idx];
    float acc[16][4];
#pragma unroll
    for (int nt = 0; nt < 16; nt++)
#pragma unroll
        for (int i = 0; i < 4; i++) acc[nt][i] = 0.f;
    __syncthreads();

    for (int k0 = 0; k0 < C0; k0 += 32) {
        for (int idx = t; idx < 32 * 128; idx += 256) {
            int kk = idx >> 7, f = idx & 127;
            float v = (k0 + kk < C0) ? g0sq[(size_t)(k0 + kk) * FDIM + f] : 0.f;
            Gs[kk][f] = tf32r(v);
        }
        for (int idx = t; idx < 128 * 32; idx += 256) {
            int kk = idx & 31, e = idx >> 5;
            float v = 0.f;
            if (k0 + kk < C0)
                v = s0p[(size_t)rr[e] * C0 + k0 + kk] * s0p[(size_t)cc[e] * C0 + k0 + kk];
            Us[e][kk] = tf32r(v);
        }
        __syncthreads();
#pragma unroll
        for (int ks = 0; ks < 4; ks++) {
            int kb = ks * 8;
            int ar = w * 16 + (lane >> 2);
            int ak = kb + (lane & 3);
            unsigned a0 = Us[ar][ak];
            unsigned a1 = Us[ar + 8][ak];
            unsigned a2 = Us[ar][ak + 4];
            unsigned a3 = Us[ar + 8][ak + 4];
#pragma unroll
            for (int nt = 0; nt < 16; nt++) {
                int bn = nt * 8 + (lane >> 2);
                unsigned b0 = Gs[kb + (lane & 3)][bn];
                unsigned b1 = Gs[kb + (lane & 3) + 4][bn];
                asm volatile(
                    "mma.sync.aligned.m16n8k8.row.col.f32.tf32.tf32.f32 "
                    "{%0,%1,%2,%3}, {%4,%5,%6,%7}, {%8,%9}, {%0,%1,%2,%3};"
                    : "+f"(acc[nt][0]), "+f"(acc[nt][1]),
                      "+f"(acc[nt][2]), "+f"(acc[nt][3])
                    : "r"(a0), "r"(a1), "r"(a2), "r"(a3), "r"(b0), "r"(b1));
            }
        }
        __syncthreads();
    }
    {
        int r = w * 16 + (lane >> 2);
        int cb = 2 * (lane & 3);
#pragma unroll
        for (int nt = 0; nt < 16; nt++) {
            int c = nt * 8 + cb;
            Ms[c][r]         = acc[nt][0];
            Ms[c + 1][r]     = acc[nt][1];
            Ms[c][r + 8]     = acc[nt][2];
            Ms[c + 1][r + 8] = acc[nt][3];
        }
    }
    __syncthreads();
    if (t < 128) {
        int e = t;
        float u20[C1];
        const float* pr = p1 + (size_t)rr[e] * C1;
        const float* pc = p1 + (size_t)cc[e] * C1;
#pragma unroll
        for (int k = 0; k < C1; k++) u20[k] = pr[k] * pc[k];
        float a = adjv[e0 + e];
        for (int f = 0; f < FDIM; f++) {
            float mA = 0.f;
#pragma unroll
            for (int k = 0; k < C1; k++) mA += u20[k] * G1s[k][f];
            float mB = Ms[f][e];
            float tq = a * mA;
            outAdj[(size_t)f * EDGES + e0 + e] = tq + tq * mB;
            a = tq * mB;
        }
    }
}

// ---------------- CSR build ----------------
__global__ void k_count(const int* __restrict__ er) {
    int e = blockIdx.x * blockDim.x + threadIdx.x;
    if (e < EDGES) atomicAdd(&g_cnt[er[e]], 1);
}

__global__ void k_scan() {
    __shared__ int part[1024];
    const int n = N_NODES;
    const int per = (n + 1023) / 1024;
    int t = threadIdx.x;
    int s = 0;
    int lo = t * per, hi = min(n, (t + 1) * per);
    for (int i = lo; i < hi; i++) s += g_cnt[i];
    part[t] = s; __syncthreads();
    for (int off = 1; off < 1024; off <<= 1) {
        int v = (t >= off) ? part[t - off] : 0;
        __syncthreads();
        part[t] += v;
        __syncthreads();
    }
    int base = (t == 0) ? 0 : part[t - 1];
    for (int i = lo; i < hi; i++) {
        g_off[i] = base; g_cur[i] = base; base += g_cnt[i];
    }
    if (t == 1023) g_off[n] = base;
}

__global__ void k_scatter(const int* __restrict__ er, const int* __restrict__ ec,
                          const float* __restrict__ nv) {
    int e = blockIdx.x * blockDim.x + threadIdx.x;
    if (e < EDGES) {
        int pos = atomicAdd(&g_cur[er[e]], 1);
        g_colS[pos] = ec[e];
        g_wS[pos]   = nv[e];
    }
}

// ---------------- propagation step with fused BN on gathered input ----------------
__global__ void k_prop_bn(const float* __restrict__ x,
                          const float* __restrict__ cs, const float* __restrict__ css,
                          const float* __restrict__ gam, const float* __restrict__ bet,
                          float* __restrict__ xout) {
    int r = blockIdx.x * 2 + (threadIdx.x >> 7);
    int f = threadIdx.x & 127;
    float mu   = cs[f]  * (1.f / N_NODES);
    float var  = css[f] * (1.f / N_NODES);
    float rstd = rsqrtf(var + 1e-5f);
    float scale = gam[f] * rstd;
    float shift = bet[f] - mu * scale;
    float acc = 0.f;
    int s = g_off[r], e = g_off[r + 1];
    for (int i = s; i < e; i++) {
        int c = g_colS[i];
        float w = g_wS[i];
        acc += w * (x[(size_t)c * FDIM + f] * scale + shift);
    }
    xout[(size_t)r * FDIM + f] = acc;
}

// ---------------- plain propagation step (2 nodes per block) ----------------
__global__ void k_prop(const float* __restrict__ xin, float* __restrict__ xout) {
    int r = blockIdx.x * 2 + (threadIdx.x >> 7);
    int f = threadIdx.x & 127;
    float acc = 0.f;
    int s = g_off[r], e = g_off[r + 1];
    for (int i = s; i < e; i++) {
        int c = g_colS[i];
        float w = g_wS[i];
        acc += w * xin[(size_t)c * FDIM + f];
    }
    xout[(size_t)r * FDIM + f] = acc;
}

// ---------------- final logits + log_softmax ----------------
__global__ void k_final(const float* __restrict__ h, const float* __restrict__ W,
                        const float* __restrict__ b, float* __restrict__ out) {
    int warp = (blockIdx.x * blockDim.x + threadIdx.x) >> 5;
    int lane = threadIdx.x & 31;
    if (warp >= N_NODES) return;
    float p0 = 0.f, p1 = 0.f;
#pragma unroll
    for (int j = 0; j < 4; j++) {
        int k = lane + 32 * j;
        float hv = h[(size_t)warp * FDIM + k];
        p0 += hv * W[k * 2];
        p1 += hv * W[k * 2 + 1];
    }
    for (int o = 16; o; o >>= 1) {
        p0 += __shfl_down_sync(0xFFFFFFFFu, p0, o);
        p1 += __shfl_down_sync(0xFFFFFFFFu, p1, o);
    }
    if (lane == 0) {
        float l0 = p0 + b[0], l1 = p1 + b[1];
        float m = fmaxf(l0, l1);
        float ls = m + logf(expf(l0 - m) + expf(l1 - m));
        out[warp * 2]     = l0 - ls;
        out[warp * 2 + 1] = l1 - ls;
    }
}

// ================= host launcher =================
#define GSYM(var, sym) float* var; { void* _p = 0; cudaGetSymbolAddress(&_p, sym); var = (float*)_p; }

extern "C" void kernel_launch(void* const* d_in, const int* in_sizes, int n_in,
                              void* d_out, int out_size) {
    const float* x    = (const float*)d_in[0];
    const float* xcov = (const float*)d_in[1];
    const int*   er   = (const int*)d_in[2];
    const int*   ec   = (const int*)d_in[3];
    const float* adjv = (const float*)d_in[4];
    const float* nv   = (const float*)d_in[5];
    const float* gam  = (const float*)d_in[6];
    const float* bet  = (const float*)d_in[7];
    const float* c0W1 = (const float*)d_in[8];
    const float* c0b1 = (const float*)d_in[9];
    const float* c0W2 = (const float*)d_in[10];
    const float* c0b2 = (const float*)d_in[11];
    const float* c1W1 = (const float*)d_in[12];
    const float* c1b1 = (const float*)d_in[13];
    const float* c1W2 = (const float*)d_in[14];
    const float* c1b2 = (const float*)d_in[15];
    // c2_* (d_in[16..19]) are dead code in the reference
    const float* mW1 = (const float*)d_in[20];
    const float* mb1 = (const float*)d_in[21];
    const float* a1  = (const float*)d_in[22];
    const float* mW2 = (const float*)d_in[23];
    const float* mb2 = (const float*)d_in[24];
    const float* a2  = (const float*)d_in[25];
    const float* mW3 = (const float*)d_in[26];
    const float* mb3 = (const float*)d_in[27];

    float* outLog = (float*)d_out;
    float* outAdj = (float*)d_out + (size_t)N_NODES * 2;

    GSYM(xp0, g_xp0)   GSYM(xp1, g_xp1)
    GSYM(hA,  g_hA)    GSYM(hB1, g_hB1)   GSYM(hB2, g_hB2)
    GSYM(S0,  g_S0)    GSYM(corr0, g_corr0)
    GSYM(cs0, g_cs0)   GSYM(cs1, g_cs1)
    GSYM(xc1, g_xc1)   GSYM(corr1, g_corr1) GSYM(T0, g_T0) GSYM(G0, g_G0)
    GSYM(S1,  g_S1)    GSYM(xc2, g_xc2)   GSYM(corr2, g_corr2)
    GSYM(T1,  g_T1)    GSYM(G1,  g_G1)    GSYM(P1,  g_P1)
    GSYM(pa1, g_pa1)   GSYM(pa2, g_pa2)   GSYM(pc1, g_pc1)
    GSYM(csA, g_csA)   GSYM(cssA, g_cssA)
    GSYM(csB, g_csB)   GSYM(qB, g_qB)
    GSYM(csC, g_csC)   GSYM(qC, g_qC)
    GSYM(pb1, g_pb1)   GSYM(pb2, g_pb2)
    GSYM(csX, g_csX)   GSYM(cssX, g_cssX)
    GSYM(tnp, g_tnpart) GSYM(tnp2, g_tnpart2)

    const int FUSED_SMEM = 77312;
    cudaFuncSetAttribute(k_fused_mask, cudaFuncAttributeMaxDynamicSharedMemorySize,
                         FUSED_SMEM);

    cudaStream_t s2, s3;
    cudaStreamCreateWithFlags(&s2, cudaStreamNonBlocking);
    cudaStreamCreateWithFlags(&s3, cudaStreamNonBlocking);
    cudaEvent_t evFork, evJoin, evCorr0, evS0, evCs0;
    cudaEventCreateWithFlags(&evFork, cudaEventDisableTiming);
    cudaEventCreateWithFlags(&evJoin, cudaEventDisableTiming);
    cudaEventCreateWithFlags(&evCorr0, cudaEventDisableTiming);
    cudaEventCreateWithFlags(&evS0, cudaEventDisableTiming);
    cudaEventCreateWithFlags(&evCs0, cudaEventDisableTiming);

    // zero all atomic buffers + cnt, then fork
    k_zero<<<(N_NODES + 1023) / 1024, 1024>>>();
    cudaEventRecord(evFork, 0);
    cudaStreamWaitEvent(s2, evFork, 0);
    cudaStreamWaitEvent(s3, evFork, 0);

    // ============ chain B (s2): stats -> CSR -> prop(BN-fused) -> MLP -> outLog ===
    k_psum<<<250, 128, 0, s2>>>(x, N_NODES, FDIM, 32, pb1, pb2);
    k_preduce<<<1, 128, 0, s2>>>(pb1, pb2, 250, FDIM, N_NODES, csX, cssX);
    k_count<<<EDGES / 256, 256, 0, s2>>>(er);
    k_scan<<<1, 1024, 0, s2>>>();
    k_scatter<<<EDGES / 256, 256, 0, s2>>>(er, ec, nv);

    k_prop_bn<<<N_NODES / 2, 256, 0, s2>>>(x, csX, cssX, gam, bet, xp0);
    {
        const float* cur = xp0;
        float* bufs[2] = {xp1, xp0};
        for (int it = 0; it < 9; it++) {
            float* o = bufs[it & 1];
            k_prop<<<N_NODES / 2, 256, 0, s2>>>(cur, o);
            cur = o;
        }
        // ends in xp1
    }
    k_gemm_nn<<<dim3(125, 2), 256, 0, s2>>>(N_NODES, FDIM, FDIM, xp1, mW1, mb1, hB1, 2, a1);
    k_gemm_nn<<<dim3(125, 2), 256, 0, s2>>>(N_NODES, FDIM, FDIM, hB1, mW2, mb2, hB2, 2, a2);
    k_final<<<(N_NODES * 32 + 255) / 256, 256, 0, s2>>>(hB2, mW3, mb3, outLog);

    // ============ chain C part 1 (s3): corr0 ============
    k_psum<<<250, 128, 0, s3>>>(xcov, N_NODES, FDIM, 32, pa1, pa2);
    k_preduce<<<1, 128, 0, s3>>>(pa1, pa2, 250, FDIM, N_NODES, csA, cssA);
    k_corr<<<N_NODES, 128, 0, s3>>>(xcov, N_NODES, csA, cssA, corr0, 0, 0, 0);
    cudaEventRecord(evCorr0, s3);

    // ============ chain A (stream 0): cluster MLP -> softmax, record evS0 ========
    k_gemm_nn<<<dim3(125, 2), 256>>>(N_NODES, FDIM, FDIM, xcov, c0W1, c0b1, hA, 1, 0);
    k_gemm_nn<<<dim3(125, 7), 256>>>(N_NODES, C0, FDIM, hA, c0W2, c0b2, S0, 0, 0);
    k_softmax400<<<N_NODES, 128>>>(S0);
    cudaEventRecord(evS0, 0);   // recorded BEFORE any wait on it (capture-safe)

    // ============ chain C part 2 (s3): S0 colsum, after evS0 ============
    cudaStreamWaitEvent(s3, evS0, 0);
    k_psum<<<250, 128, 0, s3>>>(S0, N_NODES, C0, 32, pc1, 0);
    k_preduce<<<4, 128, 0, s3>>>(pc1, 0, 250, C0, N_NODES, cs0, 0);
    cudaEventRecord(evCs0, s3);

    // ============ chain A continues (stream 0) ============
    cudaStreamWaitEvent(0, evCorr0, 0);
    k_gemm_tn_split2<<<dim3(7, 2, 20), 256>>>(25, C0, FDIM, S0, xcov, corr0, tnp, tnp2);
    cudaStreamWaitEvent(0, evCs0, 0);
    k_tn_red2<<<(C0 * FDIM + 255) / 256, 256>>>(tnp, tnp2, 20, C0, FDIM, cs0, xc1, T0,
                                                csB, qB);

    // corr1 + gains0 (stats from red2 atomics)
    k_corr<<<C0, 128>>>(xc1, C0, csB, qB, corr1, T0, G0, 1);

    // level 1 cluster
    k_gemm_nn<<<dim3(7, 2), 256>>>(C0, FDIM, FDIM, xc1, c1W1, c1b1, hA, 1, 0);
    k_gemm_nn<<<dim3(7, 1), 256>>>(C0, C1, FDIM, hA, c1W2, c1b2, S1, 0, 0);
    k_softmax20<<<50, 256>>>(S1, cs1);
    k_gemm_tn_split2<<<dim3(1, 2, 5), 256>>>(5, C1, FDIM, S1, xc1, corr1, tnp, tnp2);
    k_tn_red2<<<(C1 * FDIM + 255) / 256, 256>>>(tnp, tnp2, 5, C1, FDIM, cs1, xc2, T1,
                                                csC, qC);

    // corr2 + gains1
    k_corr<<<C1, 128>>>(xc2, C1, csC, qC, corr2, T1, G1, 1);

    // projector P1 = S0 @ S1
    k_gemm_nn<<<dim3(125, 1), 256>>>(N_NODES, C1, C0, S0, S1, 0, P1, 0, 0);

    // fused masks + serial carry -> adjs output
    k_fused_mask<<<EDGES / 128, 256, FUSED_SMEM>>>(S0, G0, P1, G1, er, ec, adjv, outAdj);

    // ============ join ============
    cudaEventRecord(evJoin, s2);
    cudaStreamWaitEvent(0, evJoin, 0);

    cudaEventDestroy(evFork);
    cudaEventDestroy(evJoin);
    cudaEventDestroy(evCorr0);
    cudaEventDestroy(evS0);
    cudaEventDestroy(evCs0);
    cudaStreamDestroy(s2);
    cudaStreamDestroy(s3);

    (void)in_sizes; (void)n_in; (void)out_size;
}

// round 10
// speedup vs baseline: 1.3670x; 1.0694x over previous
#include <cuda_runtime.h>
#include <math.h>

#define N_NODES 8000
#define FDIM    128
#define EDGES   256000
#define C0      400
#define C1      20
#define ZSPLIT  25

// ---------------- static device scratch (no runtime allocation) ----------------
__device__ float g_xp0[N_NODES*FDIM];
__device__ float g_xp1[N_NODES*FDIM];
__device__ float g_hA [N_NODES*FDIM];
__device__ float g_hB1[N_NODES*FDIM];
__device__ float g_hB2[N_NODES*FDIM];
__device__ float g_S0 [N_NODES*C0];
__device__ float g_corr0[N_NODES*FDIM];
__device__ float g_cs0[C0];
__device__ float g_cs1[C1];
__device__ float g_xc1  [C0*FDIM];
__device__ float g_corr1[C0*FDIM];
__device__ float g_T0   [C0*FDIM];
__device__ float g_G0   [C0*FDIM];
__device__ float g_S1   [C0*C1];
__device__ float g_xc2  [C1*FDIM];
__device__ float g_corr2[C1*FDIM];
__device__ float g_T1   [C1*FDIM];
__device__ float g_G1   [C1*FDIM];
__device__ float g_P1   [N_NODES*C1];
__device__ float g_pa1[250*C0];     // corr0 stats partials (s3)
__device__ float g_pa2[250*C0];
__device__ float g_pc1[250*C0];     // S0 colsum partials (s3)
__device__ float g_csA[FDIM];
__device__ float g_cssA[FDIM];
__device__ float g_csB[FDIM];       // xc1 stats (raw sums via atomics)
__device__ float g_qB [FDIM];
__device__ float g_csC[FDIM];       // xc2 stats (raw sums via atomics)
__device__ float g_qC [FDIM];
__device__ float g_pb1[250*FDIM];   // BN stats partials (s2)
__device__ float g_pb2[250*FDIM];
__device__ float g_csX[FDIM];
__device__ float g_cssX[FDIM];
__device__ float g_tnpart [ZSPLIT*C0*FDIM];
__device__ float g_tnpart2[ZSPLIT*C0*FDIM];
__device__ int   g_cnt[N_NODES];
__device__ int   g_off[N_NODES+1];
__device__ int   g_cur[N_NODES];
__device__ int   g_colS[EDGES];
__device__ float g_wS  [EDGES];

// ---------------- zero all atomic-accumulated buffers + cnt (one launch) --------
__global__ void k_zero() {
    int i = blockIdx.x * blockDim.x + threadIdx.x;
    if (i < N_NODES) g_cnt[i] = 0;
    if (i < FDIM) { g_csB[i] = 0.f; g_qB[i] = 0.f; g_csC[i] = 0.f; g_qC[i] = 0.f; }
    if (i < C1) g_cs1[i] = 0.f;
}

// ---------------- two-stage deterministic column stats (large inputs) ----------
__global__ void k_psum(const float* __restrict__ A, int n, int c, int rowsPer,
                       float* __restrict__ ps, float* __restrict__ pq) {
    int b = blockIdx.x;
    int r0 = b * rowsPer, r1 = min(n, r0 + rowsPer);
    for (int col = threadIdx.x; col < c; col += blockDim.x) {
        float s = 0.f, q = 0.f;
        for (int r = r0; r < r1; r++) {
            float v = A[(size_t)r * c + col];
            s += v; q += v * v;
        }
        ps[(size_t)b * c + col] = s;
        if (pq) pq[(size_t)b * c + col] = q;
    }
}

__global__ void k_preduce(const float* __restrict__ ps, const float* __restrict__ pq,
                          int nb, int c, int n,
                          float* __restrict__ outS, float* __restrict__ outCss) {
    int col = blockIdx.x * blockDim.x + threadIdx.x;
    if (col >= c) return;
    float s = 0.f, q = 0.f;
    for (int b = 0; b < nb; b++) {
        s += ps[(size_t)b * c + col];
        if (pq) q += pq[(size_t)b * c + col];
    }
    outS[col] = s;
    if (outCss) outCss[col] = q - s * s / (float)n;
}

// ---------------- node correlation (+ optional fused gains) ----------------
__global__ void k_corr(const float* __restrict__ z, int n,
                       const float* __restrict__ cs, const float* __restrict__ cssOrQ,
                       float* __restrict__ out,
                       const float* __restrict__ T, float* __restrict__ G, int rawq) {
    int r = blockIdx.x, f = threadIdx.x;
    float s = cs[f];
    float mean = s / (float)n;
    float css = rawq ? (cssOrQ[f] - s * s / (float)n) : cssOrQ[f];
    float inv = 1.f / (sqrtf(css) + 1e-12f);
    float v = (z[(size_t)r * FDIM + f] - mean) * inv;
    __shared__ float red[128];
    red[f] = v; __syncthreads();
    for (int st = 64; st > 0; st >>= 1) {
        if (f < st) red[f] += red[f + st];
        __syncthreads();
    }
    size_t idx = (size_t)r * FDIM + f;
    float cv = v * red[0];
    out[idx] = cv;
    if (T) {
        float x = 1.f / (1.f + expf(T[idx] - cv));
        G[idx] = x * x;
    }
}

// ---------------- softmax for S0 rows (W=400), register-resident ----------------
__global__ void k_softmax400(float* __restrict__ X) {
    int r = blockIdx.x;
    float* row = X + (size_t)r * C0;
    int t = threadIdx.x;                       // 128
    int cnt = (t < C0 - 3 * 128) ? 4 : 3;
    float v[4];
    float m = -3.4e38f;
#pragma unroll
    for (int j = 0; j < 4; j++) {
        if (j < cnt) { v[j] = row[t + 128 * j]; m = fmaxf(m, v[j]); }
    }
    __shared__ float red[128];
    red[t] = m; __syncthreads();
    for (int s = 64; s > 0; s >>= 1) {
        if (t < s) red[t] = fmaxf(red[t], red[t + s]);
        __syncthreads();
    }
    m = red[0]; __syncthreads();
    float sum = 0.f;
#pragma unroll
    for (int j = 0; j < 4; j++) {
        if (j < cnt) { v[j] = expf(v[j] - m); sum += v[j]; }
    }
    red[t] = sum; __syncthreads();
    for (int s = 64; s > 0; s >>= 1) {
        if (t < s) red[t] += red[t + s];
        __syncthreads();
    }
    float inv = 1.f / red[0];
#pragma unroll
    for (int j = 0; j < 4; j++) {
        if (j < cnt) row[t + 128 * j] = v[j] * inv;
    }
}

// ---------------- softmax for S1 rows (W=20), warp/row + fused colsum ----------
__global__ void k_softmax20(float* __restrict__ X, float* __restrict__ cs) {
    int warp = (blockIdx.x * blockDim.x + threadIdx.x) >> 5;
    int lane = threadIdx.x & 31;
    if (warp >= C0) return;
    float* row = X + (size_t)warp * C1;
    float v = (lane < C1) ? row[lane] : -3.4e38f;
    float m = v;
#pragma unroll
    for (int o = 16; o; o >>= 1) m = fmaxf(m, __shfl_xor_sync(0xFFFFFFFFu, m, o));
    float e = (lane < C1) ? expf(v - m) : 0.f;
    float s = e;
#pragma unroll
    for (int o = 16; o; o >>= 1) s += __shfl_xor_sync(0xFFFFFFFFu, s, o);
    if (lane < C1) {
        float val = e / s;
        row[lane] = val;
        atomicAdd(&cs[lane], val);
    }
}

// ---------------- generic tiled GEMM: C = act(A@B + bias) ----------------
__global__ void k_gemm_nn(int M, int N, int K,
                          const float* __restrict__ A, const float* __restrict__ B,
                          const float* __restrict__ bias, float* __restrict__ C,
                          int act, const float* __restrict__ aux) {
    __shared__ __align__(16) float As[16][68];
    __shared__ __align__(16) float Bs[16][64];
    int t = threadIdx.x;
    int m0 = blockIdx.x * 64, n0 = blockIdx.y * 64;
    int tx = t & 15, ty = t >> 4;
    float acc[4][4];
#pragma unroll
    for (int i = 0; i < 4; i++)
#pragma unroll
        for (int j = 0; j < 4; j++) acc[i][j] = 0.f;
    for (int k0 = 0; k0 < K; k0 += 16) {
        __syncthreads();
        for (int idx = t; idx < 1024; idx += 256) {
            int kk = idx & 15, r = idx >> 4;
            int row = m0 + r;
            As[kk][r] = (row < M) ? A[(size_t)row * K + k0 + kk] : 0.f;
        }
        for (int idx = t; idx < 1024; idx += 256) {
            int kk = idx >> 6, c = idx & 63;
            int col = n0 + c;
            Bs[kk][c] = (col < N) ? B[(size_t)(k0 + kk) * N + col] : 0.f;
        }
        __syncthreads();
#pragma unroll
        for (int kk = 0; kk < 16; kk++) {
            float4 av = *(const float4*)&As[kk][ty * 4];
            float4 bv = *(const float4*)&Bs[kk][tx * 4];
            float a4[4] = {av.x, av.y, av.z, av.w};
            float b4[4] = {bv.x, bv.y, bv.z, bv.w};
#pragma unroll
            for (int i = 0; i < 4; i++)
#pragma unroll
                for (int j = 0; j < 4; j++) acc[i][j] += a4[i] * b4[j];
        }
    }
    float slope = (act == 2) ? aux[0] : 0.f;
#pragma unroll
    for (int i = 0; i < 4; i++) {
        int row = m0 + ty * 4 + i;
        if (row >= M) continue;
#pragma unroll
        for (int j = 0; j < 4; j++) {
            int col = n0 + tx * 4 + j;
            if (col >= N) continue;
            float v = acc[i][j];
            if (bias) v += bias[col];
            if (act == 1) v = fmaxf(v, 0.f);
            else if (act == 2) v = (v >= 0.f) ? v : slope * v;
            C[(size_t)row * N + col] = v;
        }
    }
}

// ---------------- tf32 helper ----------------
__device__ __forceinline__ unsigned tf32r(float x) {
    unsigned u;
    asm("cvt.rna.tf32.f32 %0, %1;" : "=r"(u) : "f"(x));
    return u;
}

// ---------------- tf32 MMA TN GEMM: part{1,2}[z, k1, n] = A_chunkT @ B{1,2}_chunk --
// A = S0 [N_NODES][C0]; B1,B2 [N_NODES][FDIM]. M(mma)=k1, K(mma)=m, N=n.
// CTA: 64 k1 x 128 n, 8 warps (wr = k1 subtile, wc = n half). z-chunk = 320 rows.
__global__ void __launch_bounds__(256)
k_tn_mma(const float* __restrict__ A,
         const float* __restrict__ B1, const float* __restrict__ B2,
         float* __restrict__ part1, float* __restrict__ part2) {
    __shared__ unsigned As[64][33];
    __shared__ unsigned Bs1[32][136];
    __shared__ unsigned Bs2[32][136];
    int t = threadIdx.x, lane = t & 31, w = t >> 5;
    int wr = w & 3, wc = w >> 2;
    int k10 = blockIdx.x * 64;
    int mBase = blockIdx.y * 320;
    float acc1[8][4], acc2[8][4];
#pragma unroll
    for (int nt = 0; nt < 8; nt++)
#pragma unroll
        for (int i = 0; i < 4; i++) { acc1[nt][i] = 0.f; acc2[nt][i] = 0.f; }

    for (int mc = 0; mc < 320; mc += 32) {
        // stage A transposed: As[k1_local][m]
        for (int idx = t; idx < 2048; idx += 256) {
            int m = idx >> 6, kl = idx & 63;
            int k1 = k10 + kl;
            float v = (k1 < C0) ? A[(size_t)(mBase + mc + m) * C0 + k1] : 0.f;
            As[kl][m] = tf32r(v);
        }
        // stage B1/B2: Bs[m][n]
        for (int idx = t; idx < 4096; idx += 256) {
            int m = idx >> 7, n = idx & 127;
            size_t g = (size_t)(mBase + mc + m) * FDIM + n;
            Bs1[m][n] = tf32r(B1[g]);
            Bs2[m][n] = tf32r(B2[g]);
        }
        __syncthreads();
#pragma unroll
        for (int ks = 0; ks < 4; ks++) {
            int ar = wr * 16 + (lane >> 2);
            int ak = ks * 8 + (lane & 3);
            unsigned a0 = As[ar][ak];
            unsigned a1 = As[ar + 8][ak];
            unsigned a2 = As[ar][ak + 4];
            unsigned a3 = As[ar + 8][ak + 4];
            int kb = ks * 8 + (lane & 3);
#pragma unroll
            for (int nt = 0; nt < 8; nt++) {
                int bn = wc * 64 + nt * 8 + (lane >> 2);
                unsigned b0 = Bs1[kb][bn];
                unsigned b1 = Bs1[kb + 4 - (lane & 3) + (lane & 3)][bn]; // placeholder fix below
                b1 = Bs1[ks * 8 + (lane & 3) + 4][bn];
                asm volatile(
                    "mma.sync.aligned.m16n8k8.row.col.f32.tf32.tf32.f32 "
                    "{%0,%1,%2,%3}, {%4,%5,%6,%7}, {%8,%9}, {%0,%1,%2,%3};"
                    : "+f"(acc1[nt][0]), "+f"(acc1[nt][1]),
                      "+f"(acc1[nt][2]), "+f"(acc1[nt][3])
                    : "r"(a0), "r"(a1), "r"(a2), "r"(a3), "r"(b0), "r"(b1));
                unsigned c0 = Bs2[ks * 8 + (lane & 3)][bn];
                unsigned c1 = Bs2[ks * 8 + (lane & 3) + 4][bn];
                asm volatile(
                    "mma.sync.aligned.m16n8k8.row.col.f32.tf32.tf32.f32 "
                    "{%0,%1,%2,%3}, {%4,%5,%6,%7}, {%8,%9}, {%0,%1,%2,%3};"
                    : "+f"(acc2[nt][0]), "+f"(acc2[nt][1]),
                      "+f"(acc2[nt][2]), "+f"(acc2[nt][3])
                    : "r"(a0), "r"(a1), "r"(a2), "r"(a3), "r"(c0), "r"(c1));
            }
        }
        __syncthreads();
    }
    int z = blockIdx.y;
    int k1r = k10 + wr * 16 + (lane >> 2);
    int cb = 2 * (lane & 3);
#pragma unroll
    for (int nt = 0; nt < 8; nt++) {
        int n = wc * 64 + nt * 8 + cb;
        if (k1r < C0) {
            size_t b = ((size_t)z * C0 + k1r) * FDIM + n;
            part1[b] = acc1[nt][0]; part1[b + 1] = acc1[nt][1];
            part2[b] = acc2[nt][0]; part2[b + 1] = acc2[nt][1];
        }
        if (k1r + 8 < C0) {
            size_t b = ((size_t)z * C0 + k1r + 8) * FDIM + n;
            part1[b] = acc1[nt][2]; part1[b + 1] = acc1[nt][3];
            part2[b] = acc2[nt][2]; part2[b + 1] = acc2[nt][3];
        }
    }
}

// ---------------- SIMT dual-B split-K TN GEMM (small level-1 use) ----------------
__global__ void k_gemm_tn_split2(int tiles, int K1, int N,
                                 const float* __restrict__ A,
                                 const float* __restrict__ B1,
                                 const float* __restrict__ B2,
                                 float* __restrict__ part1, float* __restrict__ part2) {
    __shared__ __align__(16) float As[16][64];
    __shared__ __align__(16) float Bs1[16][64];
    __shared__ __align__(16) float Bs2[16][64];
    int t = threadIdx.x;
    int k0 = blockIdx.x * 64, n0 = blockIdx.y * 64;
    int s = blockIdx.z;
    int mBase = s * tiles * 16;
    int tx = t & 15, ty = t >> 4;
    float acc1[4][4], acc2[4][4];
#pragma unroll
    for (int i = 0; i < 4; i++)
#pragma unroll
        for (int j = 0; j < 4; j++) { acc1[i][j] = 0.f; acc2[i][j] = 0.f; }
    for (int mt = 0; mt < tiles; mt++) {
        int m0 = mBase + mt * 16;
        __syncthreads();
        for (int idx = t; idx < 1024; idx += 256) {
            int mm = idx >> 6, c = idx & 63;
            As[mm][c]  = (k0 + c < K1) ? A[(size_t)(m0 + mm) * K1 + k0 + c] : 0.f;
            Bs1[mm][c] = (n0 + c < N) ? B1[(size_t)(m0 + mm) * N + n0 + c] : 0.f;
            Bs2[mm][c] = (n0 + c < N) ? B2[(size_t)(m0 + mm) * N + n0 + c] : 0.f;
        }
        __syncthreads();
#pragma unroll
        for (int mm = 0; mm < 16; mm++) {
            float4 av = *(const float4*)&As[mm][ty * 4];
            float4 b1 = *(const float4*)&Bs1[mm][tx * 4];
            float4 b2 = *(const float4*)&Bs2[mm][tx * 4];
            float a4[4] = {av.x, av.y, av.z, av.w};
            float c4[4] = {b1.x, b1.y, b1.z, b1.w};
            float d4[4] = {b2.x, b2.y, b2.z, b2.w};
#pragma unroll
            for (int i = 0; i < 4; i++)
#pragma unroll
                for (int j = 0; j < 4; j++) {
                    acc1[i][j] += a4[i] * c4[j];
                    acc2[i][j] += a4[i] * d4[j];
                }
        }
    }
#pragma unroll
    for (int i = 0; i < 4; i++) {
        int kr = k0 + ty * 4 + i;
        if (kr >= K1) continue;
#pragma unroll
        for (int j = 0; j < 4; j++) {
            int col = n0 + tx * 4 + j;
            if (col >= N) continue;
            part1[((size_t)s * K1 + kr) * N + col] = acc1[i][j];
            part2[((size_t)s * K1 + kr) * N + col] = acc2[i][j];
        }
    }
}

// dual reduce + fused atomic column-stats of out1 (if csS!=0)
__global__ void k_tn_red2(const float* __restrict__ part1, const float* __restrict__ part2,
                          int S, int K1, int N,
                          const float* __restrict__ divrow,
                          float* __restrict__ out1, float* __restrict__ out2,
                          float* __restrict__ csS, float* __restrict__ qS) {
    int i = blockIdx.x * blockDim.x + threadIdx.x;
    if (i >= K1 * N) return;
    float s1 = 0.f, s2 = 0.f;
    for (int b = 0; b < S; b++) {
        s1 += part1[(size_t)b * K1 * N + i];
        s2 += part2[(size_t)b * K1 * N + i];
    }
    if (divrow) s1 /= (divrow[i / N] + 1e-12f);
    out1[i] = s1;
    out2[i] = s2;
    if (csS) {
        int f = i % N;
        atomicAdd(&csS[f], s1);
        atomicAdd(&qS[f], s1 * s1);
    }
}

// ---------------- FUSED: mask(K=400 MMA) + mask(K=20) + serial carry ----------------
__global__ void __launch_bounds__(256, 2)
k_fused_mask(const float* __restrict__ s0p, const float* __restrict__ g0sq,
             const float* __restrict__ p1, const float* __restrict__ g1sq,
             const int* __restrict__ er, const int* __restrict__ ec,
             const float* __restrict__ adjv, float* __restrict__ outAdj) {
    extern __shared__ __align__(16) char sm[];
    unsigned (*Us)[36]  = (unsigned(*)[36])(sm);
    unsigned (*Gs)[136] = (unsigned(*)[136])(sm + 18432);
    float (*Ms)[129]    = (float(*)[129])(sm);
    float (*G1s)[128]   = (float(*)[128])(sm + 66048);
    int* rr             = (int*)(sm + 76288);
    int* cc             = (int*)(sm + 76800);

    int t = threadIdx.x, lane = t & 31, w = t >> 5;
    int e0 = blockIdx.x * 128;
    if (t < 128) { rr[t] = er[e0 + t]; cc[t] = ec[e0 + t]; }
    for (int idx = t; idx < C1 * FDIM; idx += 256)
        G1s[idx >> 7][idx & 127] = g1sq[idx];
    float acc[16][4];
#pragma unroll
    for (int nt = 0; nt < 16; nt++)
#pragma unroll
        for (int i = 0; i < 4; i++) acc[nt][i] = 0.f;
    __syncthreads();

    for (int k0 = 0; k0 < C0; k0 += 32) {
        for (int idx = t; idx < 32 * 128; idx += 256) {
            int kk = idx >> 7, f = idx & 127;
            float v = (k0 + kk < C0) ? g0sq[(size_t)(k0 + kk) * FDIM + f] : 0.f;
            Gs[kk][f] = tf32r(v);
        }
        for (int idx = t; idx < 128 * 32; idx += 256) {
            int kk = idx & 31, e = idx >> 5;
            float v = 0.f;
            if (k0 + kk < C0)
                v = s0p[(size_t)rr[e] * C0 + k0 + kk] * s0p[(size_t)cc[e] * C0 + k0 + kk];
            Us[e][kk] = tf32r(v);
        }
        __syncthreads();
#pragma unroll
        for (int ks = 0; ks < 4; ks++) {
            int kb = ks * 8;
            int ar = w * 16 + (lane >> 2);
            int ak = kb + (lane & 3);
            unsigned a0 = Us[ar][ak];
            unsigned a1 = Us[ar + 8][ak];
            unsigned a2 = Us[ar][ak + 4];
            unsigned a3 = Us[ar + 8][ak + 4];
#pragma unroll
            for (int nt = 0; nt < 16; nt++) {
                int bn = nt * 8 + (lane >> 2);
                unsigned b0 = Gs[kb + (lane & 3)][bn];
                unsigned b1 = Gs[kb + (lane & 3) + 4][bn];
                asm volatile(
                    "mma.sync.aligned.m16n8k8.row.col.f32.tf32.tf32.f32 "
                    "{%0,%1,%2,%3}, {%4,%5,%6,%7}, {%8,%9}, {%0,%1,%2,%3};"
                    : "+f"(acc[nt][0]), "+f"(acc[nt][1]),
                      "+f"(acc[nt][2]), "+f"(acc[nt][3])
                    : "r"(a0), "r"(a1), "r"(a2), "r"(a3), "r"(b0), "r"(b1));
            }
        }
        __syncthreads();
    }
    {
        int r = w * 16 + (lane >> 2);
        int cb = 2 * (lane & 3);
#pragma unroll
        for (int nt = 0; nt < 16; nt++) {
            int c = nt * 8 + cb;
            Ms[c][r]         = acc[nt][0];
            Ms[c + 1][r]     = acc[nt][1];
            Ms[c][r + 8]     = acc[nt][2];
            Ms[c + 1][r + 8] = acc[nt][3];
        }
    }
    __syncthreads();
    if (t < 128) {
        int e = t;
        float u20[C1];
        const float* pr = p1 + (size_t)rr[e] * C1;
        const float* pc = p1 + (size_t)cc[e] * C1;
#pragma unroll
        for (int k = 0; k < C1; k++) u20[k] = pr[k] * pc[k];
        float a = adjv[e0 + e];
        for (int f = 0; f < FDIM; f++) {
            float mA = 0.f;
#pragma unroll
            for (int k = 0; k < C1; k++) mA += u20[k] * G1s[k][f];
            float mB = Ms[f][e];
            float tq = a * mA;
            outAdj[(size_t)f * EDGES + e0 + e] = tq + tq * mB;
            a = tq * mB;
        }
    }
}

// ---------------- CSR build ----------------
__global__ void k_count(const int* __restrict__ er) {
    int e = blockIdx.x * blockDim.x + threadIdx.x;
    if (e < EDGES) atomicAdd(&g_cnt[er[e]], 1);
}

__global__ void k_scan() {
    __shared__ int part[1024];
    const int n = N_NODES;
    const int per = (n + 1023) / 1024;
    int t = threadIdx.x;
    int s = 0;
    int lo = t * per, hi = min(n, (t + 1) * per);
    for (int i = lo; i < hi; i++) s += g_cnt[i];
    part[t] = s; __syncthreads();
    for (int off = 1; off < 1024; off <<= 1) {
        int v = (t >= off) ? part[t - off] : 0;
        __syncthreads();
        part[t] += v;
        __syncthreads();
    }
    int base = (t == 0) ? 0 : part[t - 1];
    for (int i = lo; i < hi; i++) {
        g_off[i] = base; g_cur[i] = base; base += g_cnt[i];
    }
    if (t == 1023) g_off[n] = base;
}

__global__ void k_scatter(const int* __restrict__ er, const int* __restrict__ ec,
                          const float* __restrict__ nv) {
    int e = blockIdx.x * blockDim.x + threadIdx.x;
    if (e < EDGES) {
        int pos = atomicAdd(&g_cur[er[e]], 1);
        g_colS[pos] = ec[e];
        g_wS[pos]   = nv[e];
    }
}

// ---------------- propagation step with fused BN on gathered input ----------------
__global__ void k_prop_bn(const float* __restrict__ x,
                          const float* __restrict__ cs, const float* __restrict__ css,
                          const float* __restrict__ gam, const float* __restrict__ bet,
                          float* __restrict__ xout) {
    int r = blockIdx.x * 2 + (threadIdx.x >> 7);
    int f = threadIdx.x & 127;
    float mu   = cs[f]  * (1.f / N_NODES);
    float var  = css[f] * (1.f / N_NODES);
    float rstd = rsqrtf(var + 1e-5f);
    float scale = gam[f] * rstd;
    float shift = bet[f] - mu * scale;
    float acc = 0.f;
    int s = g_off[r], e = g_off[r + 1];
    for (int i = s; i < e; i++) {
        int c = g_colS[i];
        float w = g_wS[i];
        acc += w * (x[(size_t)c * FDIM + f] * scale + shift);
    }
    xout[(size_t)r * FDIM + f] = acc;
}

// ---------------- plain propagation step (2 nodes per block) ----------------
__global__ void k_prop(const float* __restrict__ xin, float* __restrict__ xout) {
    int r = blockIdx.x * 2 + (threadIdx.x >> 7);
    int f = threadIdx.x & 127;
    float acc = 0.f;
    int s = g_off[r], e = g_off[r + 1];
    for (int i = s; i < e; i++) {
        int c = g_colS[i];
        float w = g_wS[i];
        acc += w * xin[(size_t)c * FDIM + f];
    }
    xout[(size_t)r * FDIM + f] = acc;
}

// ---------------- final logits + log_softmax ----------------
__global__ void k_final(const float* __restrict__ h, const float* __restrict__ W,
                        const float* __restrict__ b, float* __restrict__ out) {
    int warp = (blockIdx.x * blockDim.x + threadIdx.x) >> 5;
    int lane = threadIdx.x & 31;
    if (warp >= N_NODES) return;
    float p0 = 0.f, p1 = 0.f;
#pragma unroll
    for (int j = 0; j < 4; j++) {
        int k = lane + 32 * j;
        float hv = h[(size_t)warp * FDIM + k];
        p0 += hv * W[k * 2];
        p1 += hv * W[k * 2 + 1];
    }
    for (int o = 16; o; o >>= 1) {
        p0 += __shfl_down_sync(0xFFFFFFFFu, p0, o);
        p1 += __shfl_down_sync(0xFFFFFFFFu, p1, o);
    }
    if (lane == 0) {
        float l0 = p0 + b[0], l1 = p1 + b[1];
        float m = fmaxf(l0, l1);
        float ls = m + logf(expf(l0 - m) + expf(l1 - m));
        out[warp * 2]     = l0 - ls;
        out[warp * 2 + 1] = l1 - ls;
    }
}

// ================= host launcher =================
#define GSYM(var, sym) float* var; { void* _p = 0; cudaGetSymbolAddress(&_p, sym); var = (float*)_p; }

extern "C" void kernel_launch(void* const* d_in, const int* in_sizes, int n_in,
                              void* d_out, int out_size) {
    const float* x    = (const float*)d_in[0];
    const float* xcov = (const float*)d_in[1];
    const int*   er   = (const int*)d_in[2];
    const int*   ec   = (const int*)d_in[3];
    const float* adjv = (const float*)d_in[4];
    const float* nv   = (const float*)d_in[5];
    const float* gam  = (const float*)d_in[6];
    const float* bet  = (const float*)d_in[7];
    const float* c0W1 = (const float*)d_in[8];
    const float* c0b1 = (const float*)d_in[9];
    const float* c0W2 = (const float*)d_in[10];
    const float* c0b2 = (const float*)d_in[11];
    const float* c1W1 = (const float*)d_in[12];
    const float* c1b1 = (const float*)d_in[13];
    const float* c1W2 = (const float*)d_in[14];
    const float* c1b2 = (const float*)d_in[15];
    // c2_* (d_in[16..19]) are dead code in the reference
    const float* mW1 = (const float*)d_in[20];
    const float* mb1 = (const float*)d_in[21];
    const float* a1  = (const float*)d_in[22];
    const float* mW2 = (const float*)d_in[23];
    const float* mb2 = (const float*)d_in[24];
    const float* a2  = (const float*)d_in[25];
    const float* mW3 = (const float*)d_in[26];
    const float* mb3 = (const float*)d_in[27];

    float* outLog = (float*)d_out;
    float* outAdj = (float*)d_out + (size_t)N_NODES * 2;

    GSYM(xp0, g_xp0)   GSYM(xp1, g_xp1)
    GSYM(hA,  g_hA)    GSYM(hB1, g_hB1)   GSYM(hB2, g_hB2)
    GSYM(S0,  g_S0)    GSYM(corr0, g_corr0)
    GSYM(cs0, g_cs0)   GSYM(cs1, g_cs1)
    GSYM(xc1, g_xc1)   GSYM(corr1, g_corr1) GSYM(T0, g_T0) GSYM(G0, g_G0)
    GSYM(S1,  g_S1)    GSYM(xc2, g_xc2)   GSYM(corr2, g_corr2)
    GSYM(T1,  g_T1)    GSYM(G1,  g_G1)    GSYM(P1,  g_P1)
    GSYM(pa1, g_pa1)   GSYM(pa2, g_pa2)   GSYM(pc1, g_pc1)
    GSYM(csA, g_csA)   GSYM(cssA, g_cssA)
    GSYM(csB, g_csB)   GSYM(qB, g_qB)
    GSYM(csC, g_csC)   GSYM(qC, g_qC)
    GSYM(pb1, g_pb1)   GSYM(pb2, g_pb2)
    GSYM(csX, g_csX)   GSYM(cssX, g_cssX)
    GSYM(tnp, g_tnpart) GSYM(tnp2, g_tnpart2)

    const int FUSED_SMEM = 77312;
    cudaFuncSetAttribute(k_fused_mask, cudaFuncAttributeMaxDynamicSharedMemorySize,
                         FUSED_SMEM);

    cudaStream_t s2, s3;
    cudaStreamCreateWithFlags(&s2, cudaStreamNonBlocking);
    cudaStreamCreateWithFlags(&s3, cudaStreamNonBlocking);
    cudaEvent_t evFork, evJoin, evCorr0, evS0, evCs0, evS1, evP1;
    cudaEventCreateWithFlags(&evFork, cudaEventDisableTiming);
    cudaEventCreateWithFlags(&evJoin, cudaEventDisableTiming);
    cudaEventCreateWithFlags(&evCorr0, cudaEventDisableTiming);
    cudaEventCreateWithFlags(&evS0, cudaEventDisableTiming);
    cudaEventCreateWithFlags(&evCs0, cudaEventDisableTiming);
    cudaEventCreateWithFlags(&evS1, cudaEventDisableTiming);
    cudaEventCreateWithFlags(&evP1, cudaEventDisableTiming);

    // zero all atomic buffers + cnt, then fork
    k_zero<<<(N_NODES + 1023) / 1024, 1024>>>();
    cudaEventRecord(evFork, 0);
    cudaStreamWaitEvent(s2, evFork, 0);
    cudaStreamWaitEvent(s3, evFork, 0);

    // ============ chain B (s2): stats -> CSR -> prop(BN-fused) -> MLP -> outLog ===
    k_psum<<<250, 128, 0, s2>>>(x, N_NODES, FDIM, 32, pb1, pb2);
    k_preduce<<<1, 128, 0, s2>>>(pb1, pb2, 250, FDIM, N_NODES, csX, cssX);
    k_count<<<EDGES / 256, 256, 0, s2>>>(er);
    k_scan<<<1, 1024, 0, s2>>>();
    k_scatter<<<EDGES / 256, 256, 0, s2>>>(er, ec, nv);

    k_prop_bn<<<N_NODES / 2, 256, 0, s2>>>(x, csX, cssX, gam, bet, xp0);
    {
        const float* cur = xp0;
        float* bufs[2] = {xp1, xp0};
        for (int it = 0; it < 9; it++) {
            float* o = bufs[it & 1];
            k_prop<<<N_NODES / 2, 256, 0, s2>>>(cur, o);
            cur = o;
        }
        // ends in xp1
    }
    k_gemm_nn<<<dim3(125, 2), 256, 0, s2>>>(N_NODES, FDIM, FDIM, xp1, mW1, mb1, hB1, 2, a1);
    k_gemm_nn<<<dim3(125, 2), 256, 0, s2>>>(N_NODES, FDIM, FDIM, hB1, mW2, mb2, hB2, 2, a2);
    k_final<<<(N_NODES * 32 + 255) / 256, 256, 0, s2>>>(hB2, mW3, mb3, outLog);

    // ============ chain C part 1 (s3): corr0 ============
    k_psum<<<250, 128, 0, s3>>>(xcov, N_NODES, FDIM, 32, pa1, pa2);
    k_preduce<<<1, 128, 0, s3>>>(pa1, pa2, 250, FDIM, N_NODES, csA, cssA);
    k_corr<<<N_NODES, 128, 0, s3>>>(xcov, N_NODES, csA, cssA, corr0, 0, 0, 0);
    cudaEventRecord(evCorr0, s3);

    // ============ chain A (stream 0): cluster MLP -> softmax, record evS0 ========
    k_gemm_nn<<<dim3(125, 2), 256>>>(N_NODES, FDIM, FDIM, xcov, c0W1, c0b1, hA, 1, 0);
    k_gemm_nn<<<dim3(125, 7), 256>>>(N_NODES, C0, FDIM, hA, c0W2, c0b2, S0, 0, 0);
    k_softmax400<<<N_NODES, 128>>>(S0);
    cudaEventRecord(evS0, 0);

    // ============ chain C part 2 (s3): S0 colsum, after evS0 ============
    cudaStreamWaitEvent(s3, evS0, 0);
    k_psum<<<250, 128, 0, s3>>>(S0, N_NODES, C0, 32, pc1, 0);
    k_preduce<<<4, 128, 0, s3>>>(pc1, 0, 250, C0, N_NODES, cs0, 0);
    cudaEventRecord(evCs0, s3);

    // ============ chain A continues (stream 0) ============
    cudaStreamWaitEvent(0, evCorr0, 0);
    // xc1 = (S0^T @ xcov)/cs0 ; T0 = S0^T @ corr0 -- tf32 MMA, split over m (Z=25)
    k_tn_mma<<<dim3(7, ZSPLIT), 256>>>(S0, xcov, corr0, tnp, tnp2);
    cudaStreamWaitEvent(0, evCs0, 0);
    k_tn_red2<<<(C0 * FDIM + 255) / 256, 256>>>(tnp, tnp2, ZSPLIT, C0, FDIM, cs0,
                                                xc1, T0, csB, qB);

    // corr1 + gains0 (stats from red2 atomics)
    k_corr<<<C0, 128>>>(xc1, C0, csB, qB, corr1, T0, G0, 1);

    // level 1 cluster
    k_gemm_nn<<<dim3(7, 2), 256>>>(C0, FDIM, FDIM, xc1, c1W1, c1b1, hA, 1, 0);
    k_gemm_nn<<<dim3(7, 1), 256>>>(C0, C1, FDIM, hA, c1W2, c1b2, S1, 0, 0);
    k_softmax20<<<50, 256>>>(S1, cs1);
    cudaEventRecord(evS1, 0);

    // ============ chain C part 3 (s3): P1 = S0 @ S1, after evS1 ============
    cudaStreamWaitEvent(s3, evS1, 0);
    k_gemm_nn<<<dim3(125, 1), 256, 0, s3>>>(N_NODES, C1, C0, S0, S1, 0, P1, 0, 0);
    cudaEventRecord(evP1, s3);

    // ============ chain A tail (stream 0) ============
    k_gemm_tn_split2<<<dim3(1, 2, 5), 256>>>(5, C1, FDIM, S1, xc1, corr1, tnp, tnp2);
    k_tn_red2<<<(C1 * FDIM + 255) / 256, 256>>>(tnp, tnp2, 5, C1, FDIM, cs1, xc2, T1,
                                                csC, qC);
    k_corr<<<C1, 128>>>(xc2, C1, csC, qC, corr2, T1, G1, 1);

    // fused masks + serial carry -> adjs output
    cudaStreamWaitEvent(0, evP1, 0);
    k_fused_mask<<<EDGES / 128, 256, FUSED_SMEM>>>(S0, G0, P1, G1, er, ec, adjv, outAdj);

    // ============ join ============
    cudaEventRecord(evJoin, s2);
    cudaStreamWaitEvent(0, evJoin, 0);

    cudaEventDestroy(evFork);
    cudaEventDestroy(evJoin);
    cudaEventDestroy(evCorr0);
    cudaEventDestroy(evS0);
    cudaEventDestroy(evCs0);
    cudaEventDestroy(evS1);
    cudaEventDestroy(evP1);
    cudaStreamDestroy(s2);
    cudaStreamDestroy(s3);

    (void)in_sizes; (void)n_in; (void)out_size;
}

// round 11
// speedup vs baseline: 1.3884x; 1.0157x over previous
#include <cuda_runtime.h>
#include <math.h>

#define N_NODES 8000
#define FDIM    128
#define EDGES   256000
#define C0      400
#define C1      20
#define ZSPLIT  25

// ---------------- static device scratch (no runtime allocation) ----------------
__device__ float g_xp0[N_NODES*FDIM];
__device__ float g_xp1[N_NODES*FDIM];
__device__ float g_hA [N_NODES*FDIM];
__device__ float g_hB1[N_NODES*FDIM];
__device__ float g_hB2[N_NODES*FDIM];
__device__ float g_S0 [N_NODES*C0];
__device__ float g_corr0[N_NODES*FDIM];
__device__ float g_cs0[C0];
__device__ float g_cs1[C1];
__device__ float g_xc1  [C0*FDIM];
__device__ float g_corr1[C0*FDIM];
__device__ float g_T0   [C0*FDIM];
__device__ float g_G0   [C0*FDIM];
__device__ float g_S1   [C0*C1];
__device__ float g_xc2  [C1*FDIM];
__device__ float g_corr2[C1*FDIM];
__device__ float g_T1   [C1*FDIM];
__device__ float g_G1   [C1*FDIM];
__device__ float g_P1   [N_NODES*C1];
__device__ float g_pa1[250*C0];
__device__ float g_pa2[250*C0];
__device__ float g_pc1[250*C0];
__device__ float g_csA[FDIM];
__device__ float g_cssA[FDIM];
__device__ float g_csB[FDIM];
__device__ float g_qB [FDIM];
__device__ float g_csC[FDIM];
__device__ float g_qC [FDIM];
__device__ float g_pb1[250*FDIM];
__device__ float g_pb2[250*FDIM];
__device__ float g_csX[FDIM];
__device__ float g_cssX[FDIM];
__device__ float g_tnpart [ZSPLIT*C0*FDIM];
__device__ float g_tnpart2[ZSPLIT*C0*FDIM];
__device__ int   g_cnt[N_NODES];
__device__ int   g_off[N_NODES+1];
__device__ int   g_cur[N_NODES];
__device__ int   g_colS[EDGES];
__device__ float g_wS  [EDGES];

// ---------------- zero all atomic-accumulated buffers + cnt (one launch) --------
__global__ void k_zero() {
    int i = blockIdx.x * blockDim.x + threadIdx.x;
    if (i < N_NODES) g_cnt[i] = 0;
    if (i < FDIM) { g_csB[i] = 0.f; g_qB[i] = 0.f; g_csC[i] = 0.f; g_qC[i] = 0.f; }
    if (i < C1) g_cs1[i] = 0.f;
}

// ---------------- two-stage deterministic column stats ----------------
__global__ void k_psum(const float* __restrict__ A, int n, int c, int rowsPer,
                       float* __restrict__ ps, float* __restrict__ pq) {
    int b = blockIdx.x;
    int r0 = b * rowsPer, r1 = min(n, r0 + rowsPer);
    for (int col = threadIdx.x; col < c; col += blockDim.x) {
        float s = 0.f, q = 0.f;
        for (int r = r0; r < r1; r++) {
            float v = A[(size_t)r * c + col];
            s += v; q += v * v;
        }
        ps[(size_t)b * c + col] = s;
        if (pq) pq[(size_t)b * c + col] = q;
    }
}

__global__ void k_preduce(const float* __restrict__ ps, const float* __restrict__ pq,
                          int nb, int c, int n,
                          float* __restrict__ outS, float* __restrict__ outCss) {
    int col = blockIdx.x * blockDim.x + threadIdx.x;
    if (col >= c) return;
    float s = 0.f, q = 0.f;
    for (int b = 0; b < nb; b++) {
        s += ps[(size_t)b * c + col];
        if (pq) q += pq[(size_t)b * c + col];
    }
    outS[col] = s;
    if (outCss) outCss[col] = q - s * s / (float)n;
}

// ---------------- node correlation (+ optional fused gains) ----------------
__global__ void k_corr(const float* __restrict__ z, int n,
                       const float* __restrict__ cs, const float* __restrict__ cssOrQ,
                       float* __restrict__ out,
                       const float* __restrict__ T, float* __restrict__ G, int rawq) {
    int r = blockIdx.x, f = threadIdx.x;
    float s = cs[f];
    float mean = s / (float)n;
    float css = rawq ? (cssOrQ[f] - s * s / (float)n) : cssOrQ[f];
    float inv = 1.f / (sqrtf(css) + 1e-12f);
    float v = (z[(size_t)r * FDIM + f] - mean) * inv;
    __shared__ float red[128];
    red[f] = v; __syncthreads();
    for (int st = 64; st > 0; st >>= 1) {
        if (f < st) red[f] += red[f + st];
        __syncthreads();
    }
    size_t idx = (size_t)r * FDIM + f;
    float cv = v * red[0];
    out[idx] = cv;
    if (T) {
        float x = 1.f / (1.f + expf(T[idx] - cv));
        G[idx] = x * x;
    }
}

// ---------------- softmax for S0 rows (W=400), register-resident ----------------
__global__ void k_softmax400(float* __restrict__ X) {
    int r = blockIdx.x;
    float* row = X + (size_t)r * C0;
    int t = threadIdx.x;
    int cnt = (t < C0 - 3 * 128) ? 4 : 3;
    float v[4];
    float m = -3.4e38f;
#pragma unroll
    for (int j = 0; j < 4; j++) {
        if (j < cnt) { v[j] = row[t + 128 * j]; m = fmaxf(m, v[j]); }
    }
    __shared__ float red[128];
    red[t] = m; __syncthreads();
    for (int s = 64; s > 0; s >>= 1) {
        if (t < s) red[t] = fmaxf(red[t], red[t + s]);
        __syncthreads();
    }
    m = red[0]; __syncthreads();
    float sum = 0.f;
#pragma unroll
    for (int j = 0; j < 4; j++) {
        if (j < cnt) { v[j] = expf(v[j] - m); sum += v[j]; }
    }
    red[t] = sum; __syncthreads();
    for (int s = 64; s > 0; s >>= 1) {
        if (t < s) red[t] += red[t + s];
        __syncthreads();
    }
    float inv = 1.f / red[0];
#pragma unroll
    for (int j = 0; j < 4; j++) {
        if (j < cnt) row[t + 128 * j] = v[j] * inv;
    }
}

// ---------------- softmax for S1 rows (W=20), warp/row + fused colsum ----------
__global__ void k_softmax20(float* __restrict__ X, float* __restrict__ cs) {
    int warp = (blockIdx.x * blockDim.x + threadIdx.x) >> 5;
    int lane = threadIdx.x & 31;
    if (warp >= C0) return;
    float* row = X + (size_t)warp * C1;
    float v = (lane < C1) ? row[lane] : -3.4e38f;
    float m = v;
#pragma unroll
    for (int o = 16; o; o >>= 1) m = fmaxf(m, __shfl_xor_sync(0xFFFFFFFFu, m, o));
    float e = (lane < C1) ? expf(v - m) : 0.f;
    float s = e;
#pragma unroll
    for (int o = 16; o; o >>= 1) s += __shfl_xor_sync(0xFFFFFFFFu, s, o);
    if (lane < C1) {
        float val = e / s;
        row[lane] = val;
        atomicAdd(&cs[lane], val);
    }
}

// ---------------- tf32 helper ----------------
__device__ __forceinline__ unsigned tf32r(float x) {
    unsigned u;
    asm("cvt.rna.tf32.f32 %0, %1;" : "=r"(u) : "f"(x));
    return u;
}

#define MMA_TF32(ACC, A0, A1, A2, A3, B0, B1)                                  \
    asm volatile(                                                              \
        "mma.sync.aligned.m16n8k8.row.col.f32.tf32.tf32.f32 "                  \
        "{%0,%1,%2,%3}, {%4,%5,%6,%7}, {%8,%9}, {%0,%1,%2,%3};"                \
        : "+f"(ACC[0]), "+f"(ACC[1]), "+f"(ACC[2]), "+f"(ACC[3])               \
        : "r"(A0), "r"(A1), "r"(A2), "r"(A3), "r"(B0), "r"(B1))

// ---------------- split-3 tf32 NN GEMM (fp32-accurate): C = act(A@B + bias) -----
// A [M,128] rm, B [128,N] rm. CTA 128m x 64n, 256 thr. dyn smem 55296 B.
__global__ void __launch_bounds__(256)
k_nn_mma3(int M, int N,
          const float* __restrict__ A, const float* __restrict__ B,
          const float* __restrict__ bias, float* __restrict__ C,
          int act, const float* __restrict__ aux) {
    extern __shared__ __align__(16) char sm3[];
    unsigned (*Ah)[36] = (unsigned(*)[36])(sm3);               // 18432
    unsigned (*Al)[36] = (unsigned(*)[36])(sm3 + 18432);       // 18432
    unsigned (*Bh)[72] = (unsigned(*)[72])(sm3 + 36864);       // 9216
    unsigned (*Bl)[72] = (unsigned(*)[72])(sm3 + 46080);       // 9216 -> 55296
    int t = threadIdx.x, lane = t & 31, w = t >> 5;
    int m0 = blockIdx.x * 128, n0 = blockIdx.y * 64;
    float acc[8][4];
#pragma unroll
    for (int nt = 0; nt < 8; nt++)
#pragma unroll
        for (int i = 0; i < 4; i++) acc[nt][i] = 0.f;

    for (int k0 = 0; k0 < 128; k0 += 32) {
        for (int idx = t; idx < 128 * 32; idx += 256) {
            int r = idx >> 5, kk = idx & 31;
            int row = m0 + r;
            float v = (row < M) ? A[(size_t)row * 128 + k0 + kk] : 0.f;
            unsigned h = tf32r(v);
            Ah[r][kk] = h;
            Al[r][kk] = tf32r(v - __uint_as_float(h));
        }
        for (int idx = t; idx < 32 * 64; idx += 256) {
            int kk = idx >> 6, n = idx & 63;
            int col = n0 + n;
            float v = (col < N) ? B[(size_t)(k0 + kk) * N + col] : 0.f;
            unsigned h = tf32r(v);
            Bh[kk][n] = h;
            Bl[kk][n] = tf32r(v - __uint_as_float(h));
        }
        __syncthreads();
#pragma unroll
        for (int ks = 0; ks < 4; ks++) {
            int kb = ks * 8;
            int ar = w * 16 + (lane >> 2);
            int ak = kb + (lane & 3);
            unsigned ah0 = Ah[ar][ak],     ah1 = Ah[ar + 8][ak];
            unsigned ah2 = Ah[ar][ak + 4], ah3 = Ah[ar + 8][ak + 4];
            unsigned al0 = Al[ar][ak],     al1 = Al[ar + 8][ak];
            unsigned al2 = Al[ar][ak + 4], al3 = Al[ar + 8][ak + 4];
#pragma unroll
            for (int nt = 0; nt < 8; nt++) {
                int bn = nt * 8 + (lane >> 2);
                unsigned bh0 = Bh[kb + (lane & 3)][bn];
                unsigned bh1 = Bh[kb + (lane & 3) + 4][bn];
                unsigned bl0 = Bl[kb + (lane & 3)][bn];
                unsigned bl1 = Bl[kb + (lane & 3) + 4][bn];
                MMA_TF32(acc[nt], ah0, ah1, ah2, ah3, bh0, bh1);
                MMA_TF32(acc[nt], ah0, ah1, ah2, ah3, bl0, bl1);
                MMA_TF32(acc[nt], al0, al1, al2, al3, bh0, bh1);
            }
        }
        __syncthreads();
    }
    float slope = (act == 2) ? aux[0] : 0.f;
    int rbase = m0 + w * 16 + (lane >> 2);
#pragma unroll
    for (int nt = 0; nt < 8; nt++) {
        int cb = n0 + nt * 8 + 2 * (lane & 3);
#pragma unroll
        for (int q = 0; q < 4; q++) {
            int r = rbase + ((q >= 2) ? 8 : 0);
            int c = cb + (q & 1);
            if (r < M && c < N) {
                float v = acc[nt][q];
                if (bias) v += bias[c];
                if (act == 1) v = fmaxf(v, 0.f);
                else if (act == 2) v = (v >= 0.f) ? v : slope * v;
                C[(size_t)r * N + c] = v;
            }
        }
    }
}

// ---------------- generic tiled SIMT GEMM (small uses: P1, level-1 logits) ------
__global__ void k_gemm_nn(int M, int N, int K,
                          const float* __restrict__ A, const float* __restrict__ B,
                          const float* __restrict__ bias, float* __restrict__ C,
                          int act, const float* __restrict__ aux) {
    __shared__ __align__(16) float As[16][68];
    __shared__ __align__(16) float Bs[16][64];
    int t = threadIdx.x;
    int m0 = blockIdx.x * 64, n0 = blockIdx.y * 64;
    int tx = t & 15, ty = t >> 4;
    float acc[4][4];
#pragma unroll
    for (int i = 0; i < 4; i++)
#pragma unroll
        for (int j = 0; j < 4; j++) acc[i][j] = 0.f;
    for (int k0 = 0; k0 < K; k0 += 16) {
        __syncthreads();
        for (int idx = t; idx < 1024; idx += 256) {
            int kk = idx & 15, r = idx >> 4;
            int row = m0 + r;
            As[kk][r] = (row < M) ? A[(size_t)row * K + k0 + kk] : 0.f;
        }
        for (int idx = t; idx < 1024; idx += 256) {
            int kk = idx >> 6, c = idx & 63;
            int col = n0 + c;
            Bs[kk][c] = (col < N) ? B[(size_t)(k0 + kk) * N + col] : 0.f;
        }
        __syncthreads();
#pragma unroll
        for (int kk = 0; kk < 16; kk++) {
            float4 av = *(const float4*)&As[kk][ty * 4];
            float4 bv = *(const float4*)&Bs[kk][tx * 4];
            float a4[4] = {av.x, av.y, av.z, av.w};
            float b4[4] = {bv.x, bv.y, bv.z, bv.w};
#pragma unroll
            for (int i = 0; i < 4; i++)
#pragma unroll
                for (int j = 0; j < 4; j++) acc[i][j] += a4[i] * b4[j];
        }
    }
    float slope = (act == 2) ? aux[0] : 0.f;
#pragma unroll
    for (int i = 0; i < 4; i++) {
        int row = m0 + ty * 4 + i;
        if (row >= M) continue;
#pragma unroll
        for (int j = 0; j < 4; j++) {
            int col = n0 + tx * 4 + j;
            if (col >= N) continue;
            float v = acc[i][j];
            if (bias) v += bias[col];
            if (act == 1) v = fmaxf(v, 0.f);
            else if (act == 2) v = (v >= 0.f) ? v : slope * v;
            C[(size_t)row * N + col] = v;
        }
    }
}

// ---------------- tf32 MMA TN GEMM (split-m): part{1,2}[z] = A_chunkT @ B{1,2} --
__global__ void __launch_bounds__(256)
k_tn_mma(const float* __restrict__ A,
         const float* __restrict__ B1, const float* __restrict__ B2,
         float* __restrict__ part1, float* __restrict__ part2) {
    __shared__ unsigned As[64][33];
    __shared__ unsigned Bs1[32][136];
    __shared__ unsigned Bs2[32][136];
    int t = threadIdx.x, lane = t & 31, w = t >> 5;
    int wr = w & 3, wc = w >> 2;
    int k10 = blockIdx.x * 64;
    int mBase = blockIdx.y * 320;
    float acc1[8][4], acc2[8][4];
#pragma unroll
    for (int nt = 0; nt < 8; nt++)
#pragma unroll
        for (int i = 0; i < 4; i++) { acc1[nt][i] = 0.f; acc2[nt][i] = 0.f; }

    for (int mc = 0; mc < 320; mc += 32) {
        for (int idx = t; idx < 2048; idx += 256) {
            int m = idx >> 6, kl = idx & 63;
            int k1 = k10 + kl;
            float v = (k1 < C0) ? A[(size_t)(mBase + mc + m) * C0 + k1] : 0.f;
            As[kl][m] = tf32r(v);
        }
        for (int idx = t; idx < 4096; idx += 256) {
            int m = idx >> 7, n = idx & 127;
            size_t g = (size_t)(mBase + mc + m) * FDIM + n;
            Bs1[m][n] = tf32r(B1[g]);
            Bs2[m][n] = tf32r(B2[g]);
        }
        __syncthreads();
#pragma unroll
        for (int ks = 0; ks < 4; ks++) {
            int ar = wr * 16 + (lane >> 2);
            int ak = ks * 8 + (lane & 3);
            unsigned a0 = As[ar][ak];
            unsigned a1 = As[ar + 8][ak];
            unsigned a2 = As[ar][ak + 4];
            unsigned a3 = As[ar + 8][ak + 4];
#pragma unroll
            for (int nt = 0; nt < 8; nt++) {
                int bn = wc * 64 + nt * 8 + (lane >> 2);
                unsigned b0 = Bs1[ks * 8 + (lane & 3)][bn];
                unsigned b1 = Bs1[ks * 8 + (lane & 3) + 4][bn];
                MMA_TF32(acc1[nt], a0, a1, a2, a3, b0, b1);
                unsigned c0 = Bs2[ks * 8 + (lane & 3)][bn];
                unsigned c1 = Bs2[ks * 8 + (lane & 3) + 4][bn];
                MMA_TF32(acc2[nt], a0, a1, a2, a3, c0, c1);
            }
        }
        __syncthreads();
    }
    int z = blockIdx.y;
    int k1r = k10 + wr * 16 + (lane >> 2);
    int cb = 2 * (lane & 3);
#pragma unroll
    for (int nt = 0; nt < 8; nt++) {
        int n = wc * 64 + nt * 8 + cb;
        if (k1r < C0) {
            size_t b = ((size_t)z * C0 + k1r) * FDIM + n;
            part1[b] = acc1[nt][0]; part1[b + 1] = acc1[nt][1];
            part2[b] = acc2[nt][0]; part2[b + 1] = acc2[nt][1];
        }
        if (k1r + 8 < C0) {
            size_t b = ((size_t)z * C0 + k1r + 8) * FDIM + n;
            part1[b] = acc1[nt][2]; part1[b + 1] = acc1[nt][3];
            part2[b] = acc2[nt][2]; part2[b + 1] = acc2[nt][3];
        }
    }
}

// ---------------- SIMT dual-B split-K TN GEMM (level-1) ----------------
__global__ void k_gemm_tn_split2(int tiles, int K1, int N,
                                 const float* __restrict__ A,
                                 const float* __restrict__ B1,
                                 const float* __restrict__ B2,
                                 float* __restrict__ part1, float* __restrict__ part2) {
    __shared__ __align__(16) float As[16][64];
    __shared__ __align__(16) float Bs1[16][64];
    __shared__ __align__(16) float Bs2[16][64];
    int t = threadIdx.x;
    int k0 = blockIdx.x * 64, n0 = blockIdx.y * 64;
    int s = blockIdx.z;
    int mBase = s * tiles * 16;
    int tx = t & 15, ty = t >> 4;
    float acc1[4][4], acc2[4][4];
#pragma unroll
    for (int i = 0; i < 4; i++)
#pragma unroll
        for (int j = 0; j < 4; j++) { acc1[i][j] = 0.f; acc2[i][j] = 0.f; }
    for (int mt = 0; mt < tiles; mt++) {
        int m0 = mBase + mt * 16;
        __syncthreads();
        for (int idx = t; idx < 1024; idx += 256) {
            int mm = idx >> 6, c = idx & 63;
            As[mm][c]  = (k0 + c < K1) ? A[(size_t)(m0 + mm) * K1 + k0 + c] : 0.f;
            Bs1[mm][c] = (n0 + c < N) ? B1[(size_t)(m0 + mm) * N + n0 + c] : 0.f;
            Bs2[mm][c] = (n0 + c < N) ? B2[(size_t)(m0 + mm) * N + n0 + c] : 0.f;
        }
        __syncthreads();
#pragma unroll
        for (int mm = 0; mm < 16; mm++) {
            float4 av = *(const float4*)&As[mm][ty * 4];
            float4 b1 = *(const float4*)&Bs1[mm][tx * 4];
            float4 b2 = *(const float4*)&Bs2[mm][tx * 4];
            float a4[4] = {av.x, av.y, av.z, av.w};
            float c4[4] = {b1.x, b1.y, b1.z, b1.w};
            float d4[4] = {b2.x, b2.y, b2.z, b2.w};
#pragma unroll
            for (int i = 0; i < 4; i++)
#pragma unroll
                for (int j = 0; j < 4; j++) {
                    acc1[i][j] += a4[i] * c4[j];
                    acc2[i][j] += a4[i] * d4[j];
                }
        }
    }
#pragma unroll
    for (int i = 0; i < 4; i++) {
        int kr = k0 + ty * 4 + i;
        if (kr >= K1) continue;
#pragma unroll
        for (int j = 0; j < 4; j++) {
            int col = n0 + tx * 4 + j;
            if (col >= N) continue;
            part1[((size_t)s * K1 + kr) * N + col] = acc1[i][j];
            part2[((size_t)s * K1 + kr) * N + col] = acc2[i][j];
        }
    }
}

// dual reduce + fused atomic column-stats of out1 (if csS!=0)
__global__ void k_tn_red2(const float* __restrict__ part1, const float* __restrict__ part2,
                          int S, int K1, int N,
                          const float* __restrict__ divrow,
                          float* __restrict__ out1, float* __restrict__ out2,
                          float* __restrict__ csS, float* __restrict__ qS) {
    int i = blockIdx.x * blockDim.x + threadIdx.x;
    if (i >= K1 * N) return;
    float s1 = 0.f, s2 = 0.f;
    for (int b = 0; b < S; b++) {
        s1 += part1[(size_t)b * K1 * N + i];
        s2 += part2[(size_t)b * K1 * N + i];
    }
    if (divrow) s1 /= (divrow[i / N] + 1e-12f);
    out1[i] = s1;
    out2[i] = s2;
    if (csS) {
        int f = i % N;
        atomicAdd(&csS[f], s1);
        atomicAdd(&qS[f], s1 * s1);
    }
}

// ---------------- FUSED: mask(K=400 MMA) + mask(K=20) + serial carry ----------------
__global__ void __launch_bounds__(256, 2)
k_fused_mask(const float* __restrict__ s0p, const float* __restrict__ g0sq,
             const float* __restrict__ p1, const float* __restrict__ g1sq,
             const int* __restrict__ er, const int* __restrict__ ec,
             const float* __restrict__ adjv, float* __restrict__ outAdj) {
    extern __shared__ __align__(16) char sm[];
    unsigned (*Us)[36]  = (unsigned(*)[36])(sm);
    unsigned (*Gs)[136] = (unsigned(*)[136])(sm + 18432);
    float (*Ms)[129]    = (float(*)[129])(sm);
    float (*G1s)[128]   = (float(*)[128])(sm + 66048);
    int* rr             = (int*)(sm + 76288);
    int* cc             = (int*)(sm + 76800);

    int t = threadIdx.x, lane = t & 31, w = t >> 5;
    int e0 = blockIdx.x * 128;
    if (t < 128) { rr[t] = er[e0 + t]; cc[t] = ec[e0 + t]; }
    for (int idx = t; idx < C1 * FDIM; idx += 256)
        G1s[idx >> 7][idx & 127] = g1sq[idx];
    float acc[16][4];
#pragma unroll
    for (int nt = 0; nt < 16; nt++)
#pragma unroll
        for (int i = 0; i < 4; i++) acc[nt][i] = 0.f;
    __syncthreads();

    for (int k0 = 0; k0 < C0; k0 += 32) {
        for (int idx = t; idx < 32 * 128; idx += 256) {
            int kk = idx >> 7, f = idx & 127;
            float v = (k0 + kk < C0) ? g0sq[(size_t)(k0 + kk) * FDIM + f] : 0.f;
            Gs[kk][f] = tf32r(v);
        }
        for (int idx = t; idx < 128 * 32; idx += 256) {
            int kk = idx & 31, e = idx >> 5;
            float v = 0.f;
            if (k0 + kk < C0)
                v = s0p[(size_t)rr[e] * C0 + k0 + kk] * s0p[(size_t)cc[e] * C0 + k0 + kk];
            Us[e][kk] = tf32r(v);
        }
        __syncthreads();
#pragma unroll
        for (int ks = 0; ks < 4; ks++) {
            int kb = ks * 8;
            int ar = w * 16 + (lane >> 2);
            int ak = kb + (lane & 3);
            unsigned a0 = Us[ar][ak];
            unsigned a1 = Us[ar + 8][ak];
            unsigned a2 = Us[ar][ak + 4];
            unsigned a3 = Us[ar + 8][ak + 4];
#pragma unroll
            for (int nt = 0; nt < 16; nt++) {
                int bn = nt * 8 + (lane >> 2);
                unsigned b0 = Gs[kb + (lane & 3)][bn];
                unsigned b1 = Gs[kb + (lane & 3) + 4][bn];
                MMA_TF32(acc[nt], a0, a1, a2, a3, b0, b1);
            }
        }
        __syncthreads();
    }
    {
        int r = w * 16 + (lane >> 2);
        int cb = 2 * (lane & 3);
#pragma unroll
        for (int nt = 0; nt < 16; nt++) {
            int c = nt * 8 + cb;
            Ms[c][r]         = acc[nt][0];
            Ms[c + 1][r]     = acc[nt][1];
            Ms[c][r + 8]     = acc[nt][2];
            Ms[c + 1][r + 8] = acc[nt][3];
        }
    }
    __syncthreads();
    if (t < 128) {
        int e = t;
        float u20[C1];
        const float* pr = p1 + (size_t)rr[e] * C1;
        const float* pc = p1 + (size_t)cc[e] * C1;
#pragma unroll
        for (int k = 0; k < C1; k++) u20[k] = pr[k] * pc[k];
        float a = adjv[e0 + e];
        for (int f = 0; f < FDIM; f++) {
            float mA = 0.f;
#pragma unroll
            for (int k = 0; k < C1; k++) mA += u20[k] * G1s[k][f];
            float mB = Ms[f][e];
            float tq = a * mA;
            outAdj[(size_t)f * EDGES + e0 + e] = tq + tq * mB;
            a = tq * mB;
        }
    }
}

// ---------------- CSR build ----------------
__global__ void k_count(const int* __restrict__ er) {
    int e = blockIdx.x * blockDim.x + threadIdx.x;
    if (e < EDGES) atomicAdd(&g_cnt[er[e]], 1);
}

__global__ void k_scan() {
    __shared__ int part[1024];
    const int n = N_NODES;
    const int per = (n + 1023) / 1024;
    int t = threadIdx.x;
    int s = 0;
    int lo = t * per, hi = min(n, (t + 1) * per);
    for (int i = lo; i < hi; i++) s += g_cnt[i];
    part[t] = s; __syncthreads();
    for (int off = 1; off < 1024; off <<= 1) {
        int v = (t >= off) ? part[t - off] : 0;
        __syncthreads();
        part[t] += v;
        __syncthreads();
    }
    int base = (t == 0) ? 0 : part[t - 1];
    for (int i = lo; i < hi; i++) {
        g_off[i] = base; g_cur[i] = base; base += g_cnt[i];
    }
    if (t == 1023) g_off[n] = base;
}

__global__ void k_scatter(const int* __restrict__ er, const int* __restrict__ ec,
                          const float* __restrict__ nv) {
    int e = blockIdx.x * blockDim.x + threadIdx.x;
    if (e < EDGES) {
        int pos = atomicAdd(&g_cur[er[e]], 1);
        g_colS[pos] = ec[e];
        g_wS[pos]   = nv[e];
    }
}

// ---------------- propagation step with fused BN on gathered input ----------------
__global__ void k_prop_bn(const float* __restrict__ x,
                          const float* __restrict__ cs, const float* __restrict__ css,
                          const float* __restrict__ gam, const float* __restrict__ bet,
                          float* __restrict__ xout) {
    int r = blockIdx.x * 2 + (threadIdx.x >> 7);
    int f = threadIdx.x & 127;
    float mu   = cs[f]  * (1.f / N_NODES);
    float var  = css[f] * (1.f / N_NODES);
    float rstd = rsqrtf(var + 1e-5f);
    float scale = gam[f] * rstd;
    float shift = bet[f] - mu * scale;
    float acc = 0.f;
    int s = g_off[r], e = g_off[r + 1];
    for (int i = s; i < e; i++) {
        int c = g_colS[i];
        float w = g_wS[i];
        acc += w * (x[(size_t)c * FDIM + f] * scale + shift);
    }
    xout[(size_t)r * FDIM + f] = acc;
}

// ---------------- plain propagation step (2 nodes per block) ----------------
__global__ void k_prop(const float* __restrict__ xin, float* __restrict__ xout) {
    int r = blockIdx.x * 2 + (threadIdx.x >> 7);
    int f = threadIdx.x & 127;
    float acc = 0.f;
    int s = g_off[r], e = g_off[r + 1];
    for (int i = s; i < e; i++) {
        int c = g_colS[i];
        float w = g_wS[i];
        acc += w * xin[(size_t)c * FDIM + f];
    }
    xout[(size_t)r * FDIM + f] = acc;
}

// ---------------- final logits + log_softmax ----------------
__global__ void k_final(const float* __restrict__ h, const float* __restrict__ W,
                        const float* __restrict__ b, float* __restrict__ out) {
    int warp = (blockIdx.x * blockDim.x + threadIdx.x) >> 5;
    int lane = threadIdx.x & 31;
    if (warp >= N_NODES) return;
    float p0 = 0.f, p1 = 0.f;
#pragma unroll
    for (int j = 0; j < 4; j++) {
        int k = lane + 32 * j;
        float hv = h[(size_t)warp * FDIM + k];
        p0 += hv * W[k * 2];
        p1 += hv * W[k * 2 + 1];
    }
    for (int o = 16; o; o >>= 1) {
        p0 += __shfl_down_sync(0xFFFFFFFFu, p0, o);
        p1 += __shfl_down_sync(0xFFFFFFFFu, p1, o);
    }
    if (lane == 0) {
        float l0 = p0 + b[0], l1 = p1 + b[1];
        float m = fmaxf(l0, l1);
        float ls = m + logf(expf(l0 - m) + expf(l1 - m));
        out[warp * 2]     = l0 - ls;
        out[warp * 2 + 1] = l1 - ls;
    }
}

// ================= host launcher =================
#define GSYM(var, sym) float* var; { void* _p = 0; cudaGetSymbolAddress(&_p, sym); var = (float*)_p; }

extern "C" void kernel_launch(void* const* d_in, const int* in_sizes, int n_in,
                              void* d_out, int out_size) {
    const float* x    = (const float*)d_in[0];
    const float* xcov = (const float*)d_in[1];
    const int*   er   = (const int*)d_in[2];
    const int*   ec   = (const int*)d_in[3];
    const float* adjv = (const float*)d_in[4];
    const float* nv   = (const float*)d_in[5];
    const float* gam  = (const float*)d_in[6];
    const float* bet  = (const float*)d_in[7];
    const float* c0W1 = (const float*)d_in[8];
    const float* c0b1 = (const float*)d_in[9];
    const float* c0W2 = (const float*)d_in[10];
    const float* c0b2 = (const float*)d_in[11];
    const float* c1W1 = (const float*)d_in[12];
    const float* c1b1 = (const float*)d_in[13];
    const float* c1W2 = (const float*)d_in[14];
    const float* c1b2 = (const float*)d_in[15];
    // c2_* (d_in[16..19]) are dead code in the reference
    const float* mW1 = (const float*)d_in[20];
    const float* mb1 = (const float*)d_in[21];
    const float* a1  = (const float*)d_in[22];
    const float* mW2 = (const float*)d_in[23];
    const float* mb2 = (const float*)d_in[24];
    const float* a2  = (const float*)d_in[25];
    const float* mW3 = (const float*)d_in[26];
    const float* mb3 = (const float*)d_in[27];

    float* outLog = (float*)d_out;
    float* outAdj = (float*)d_out + (size_t)N_NODES * 2;

    GSYM(xp0, g_xp0)   GSYM(xp1, g_xp1)
    GSYM(hA,  g_hA)    GSYM(hB1, g_hB1)   GSYM(hB2, g_hB2)
    GSYM(S0,  g_S0)    GSYM(corr0, g_corr0)
    GSYM(cs0, g_cs0)   GSYM(cs1, g_cs1)
    GSYM(xc1, g_xc1)   GSYM(corr1, g_corr1) GSYM(T0, g_T0) GSYM(G0, g_G0)
    GSYM(S1,  g_S1)    GSYM(xc2, g_xc2)   GSYM(corr2, g_corr2)
    GSYM(T1,  g_T1)    GSYM(G1,  g_G1)    GSYM(P1,  g_P1)
    GSYM(pa1, g_pa1)   GSYM(pa2, g_pa2)   GSYM(pc1, g_pc1)
    GSYM(csA, g_csA)   GSYM(cssA, g_cssA)
    GSYM(csB, g_csB)   GSYM(qB, g_qB)
    GSYM(csC, g_csC)   GSYM(qC, g_qC)
    GSYM(pb1, g_pb1)   GSYM(pb2, g_pb2)
    GSYM(csX, g_csX)   GSYM(cssX, g_cssX)
    GSYM(tnp, g_tnpart) GSYM(tnp2, g_tnpart2)

    const int FUSED_SMEM = 77312;
    const int NN3_SMEM = 55296;
    cudaFuncSetAttribute(k_fused_mask, cudaFuncAttributeMaxDynamicSharedMemorySize,
                         FUSED_SMEM);
    cudaFuncSetAttribute(k_nn_mma3, cudaFuncAttributeMaxDynamicSharedMemorySize,
                         NN3_SMEM);

    cudaStream_t s2, s3;
    cudaStreamCreateWithFlags(&s2, cudaStreamNonBlocking);
    cudaStreamCreateWithFlags(&s3, cudaStreamNonBlocking);
    cudaEvent_t evFork, evJoin, evCorr0, evS0, evCs0, evS1, evP1;
    cudaEventCreateWithFlags(&evFork, cudaEventDisableTiming);
    cudaEventCreateWithFlags(&evJoin, cudaEventDisableTiming);
    cudaEventCreateWithFlags(&evCorr0, cudaEventDisableTiming);
    cudaEventCreateWithFlags(&evS0, cudaEventDisableTiming);
    cudaEventCreateWithFlags(&evCs0, cudaEventDisableTiming);
    cudaEventCreateWithFlags(&evS1, cudaEventDisableTiming);
    cudaEventCreateWithFlags(&evP1, cudaEventDisableTiming);

    k_zero<<<(N_NODES + 1023) / 1024, 1024>>>();
    cudaEventRecord(evFork, 0);
    cudaStreamWaitEvent(s2, evFork, 0);
    cudaStreamWaitEvent(s3, evFork, 0);

    // ============ chain B (s2): stats -> CSR -> prop(BN-fused) -> MLP -> outLog ===
    k_psum<<<250, 128, 0, s2>>>(x, N_NODES, FDIM, 32, pb1, pb2);
    k_preduce<<<1, 128, 0, s2>>>(pb1, pb2, 250, FDIM, N_NODES, csX, cssX);
    k_count<<<EDGES / 256, 256, 0, s2>>>(er);
    k_scan<<<1, 1024, 0, s2>>>();
    k_scatter<<<EDGES / 256, 256, 0, s2>>>(er, ec, nv);

    k_prop_bn<<<N_NODES / 2, 256, 0, s2>>>(x, csX, cssX, gam, bet, xp0);
    {
        const float* cur = xp0;
        float* bufs[2] = {xp1, xp0};
        for (int it = 0; it < 9; it++) {
            float* o = bufs[it & 1];
            k_prop<<<N_NODES / 2, 256, 0, s2>>>(cur, o);
            cur = o;
        }
        // ends in xp1
    }
    k_nn_mma3<<<dim3(63, 2), 256, NN3_SMEM, s2>>>(N_NODES, FDIM, xp1, mW1, mb1, hB1, 2, a1);
    k_nn_mma3<<<dim3(63, 2), 256, NN3_SMEM, s2>>>(N_NODES, FDIM, hB1, mW2, mb2, hB2, 2, a2);
    k_final<<<(N_NODES * 32 + 255) / 256, 256, 0, s2>>>(hB2, mW3, mb3, outLog);

    // ============ chain C part 1 (s3): corr0 ============
    k_psum<<<250, 128, 0, s3>>>(xcov, N_NODES, FDIM, 32, pa1, pa2);
    k_preduce<<<1, 128, 0, s3>>>(pa1, pa2, 250, FDIM, N_NODES, csA, cssA);
    k_corr<<<N_NODES, 128, 0, s3>>>(xcov, N_NODES, csA, cssA, corr0, 0, 0, 0);
    cudaEventRecord(evCorr0, s3);

    // ============ chain A (stream 0): cluster MLP -> softmax ============
    k_nn_mma3<<<dim3(63, 2), 256, NN3_SMEM>>>(N_NODES, FDIM, xcov, c0W1, c0b1, hA, 1, 0);
    k_nn_mma3<<<dim3(63, 7), 256, NN3_SMEM>>>(N_NODES, C0, hA, c0W2, c0b2, S0, 0, 0);
    k_softmax400<<<N_NODES, 128>>>(S0);
    cudaEventRecord(evS0, 0);

    // ============ chain C part 2 (s3): S0 colsum ============
    cudaStreamWaitEvent(s3, evS0, 0);
    k_psum<<<250, 128, 0, s3>>>(S0, N_NODES, C0, 32, pc1, 0);
    k_preduce<<<4, 128, 0, s3>>>(pc1, 0, 250, C0, N_NODES, cs0, 0);
    cudaEventRecord(evCs0, s3);

    // ============ chain A continues (stream 0) ============
    cudaStreamWaitEvent(0, evCorr0, 0);
    k_tn_mma<<<dim3(7, ZSPLIT), 256>>>(S0, xcov, corr0, tnp, tnp2);
    cudaStreamWaitEvent(0, evCs0, 0);
    k_tn_red2<<<(C0 * FDIM + 255) / 256, 256>>>(tnp, tnp2, ZSPLIT, C0, FDIM, cs0,
                                                xc1, T0, csB, qB);

    k_corr<<<C0, 128>>>(xc1, C0, csB, qB, corr1, T0, G0, 1);

    // level 1 cluster
    k_nn_mma3<<<dim3(4, 2), 256, NN3_SMEM>>>(C0, FDIM, xc1, c1W1, c1b1, hA, 1, 0);
    k_nn_mma3<<<dim3(4, 1), 256, NN3_SMEM>>>(C0, C1, hA, c1W2, c1b2, S1, 0, 0);
    k_softmax20<<<50, 256>>>(S1, cs1);
    cudaEventRecord(evS1, 0);

    // ============ chain C part 3 (s3): P1 = S0 @ S1 ============
    cudaStreamWaitEvent(s3, evS1, 0);
    k_gemm_nn<<<dim3(125, 1), 256, 0, s3>>>(N_NODES, C1, C0, S0, S1, 0, P1, 0, 0);
    cudaEventRecord(evP1, s3);

    // ============ chain A tail (stream 0) ============
    k_gemm_tn_split2<<<dim3(1, 2, 5), 256>>>(5, C1, FDIM, S1, xc1, corr1, tnp, tnp2);
    k_tn_red2<<<(C1 * FDIM + 255) / 256, 256>>>(tnp, tnp2, 5, C1, FDIM, cs1, xc2, T1,
                                                csC, qC);
    k_corr<<<C1, 128>>>(xc2, C1, csC, qC, corr2, T1, G1, 1);

    cudaStreamWaitEvent(0, evP1, 0);
    k_fused_mask<<<EDGES / 128, 256, FUSED_SMEM>>>(S0, G0, P1, G1, er, ec, adjv, outAdj);

    // ============ join ============
    cudaEventRecord(evJoin, s2);
    cudaStreamWaitEvent(0, evJoin, 0);

    cudaEventDestroy(evFork);
    cudaEventDestroy(evJoin);
    cudaEventDestroy(evCorr0);
    cudaEventDestroy(evS0);
    cudaEventDestroy(evCs0);
    cudaEventDestroy(evS1);
    cudaEventDestroy(evP1);
    cudaStreamDestroy(s2);
    cudaStreamDestroy(s3);

    (void)in_sizes; (void)n_in; (void)out_size;
}